// round 9
// baseline (speedup 1.0000x reference)
#include <cuda_runtime.h>
#include <cuda_bf16.h>
#include <cstdint>
#include <math.h>

// Problem constants
constexpr int B  = 2;
constexpr int S  = 2048;
constexpr int DM = 1024;   // d_model
constexpr int H  = 16;
constexpr int DK = 64;
constexpr int MR = B * S;  // 4096 rows

// ---------------------------------------------------------------------------
// Scratch (allocation-free: __device__ globals)
// ---------------------------------------------------------------------------
__device__ __nv_bfloat16 g_xh[MR * DM];
__device__ __nv_bfloat16 g_xl[MR * DM];
__device__ __nv_bfloat16 g_qh[MR * DM];
__device__ __nv_bfloat16 g_ql[MR * DM];
__device__ __nv_bfloat16 g_kh[MR * DM];
__device__ __nv_bfloat16 g_kl[MR * DM];
__device__ __nv_bfloat16 g_vh[MR * DM];
__device__ __nv_bfloat16 g_vl[MR * DM];
__device__ __nv_bfloat16 g_ah[MR * DM];
__device__ __nv_bfloat16 g_al[MR * DM];
__device__ __nv_bfloat16 g_wth[4 * DM * DM];  // transposed weights, hi part
__device__ __nv_bfloat16 g_wtl[4 * DM * DM];  // transposed weights, lo part

// ---------------------------------------------------------------------------
// mma.sync / ldmatrix / cp.async helpers (non-'a' PTX surface)
// ---------------------------------------------------------------------------
__device__ __forceinline__ uint32_t smem_u32(const void* p) {
    uint32_t a;
    asm("{ .reg .u64 t; cvta.to.shared.u64 t, %1; cvt.u32.u64 %0, t; }"
        : "=r"(a) : "l"(p));
    return a;
}

__device__ __forceinline__ void ldmx4(uint32_t* r, uint32_t addr) {
    asm volatile("ldmatrix.sync.aligned.m8n8.x4.shared.b16 {%0,%1,%2,%3}, [%4];"
                 : "=r"(r[0]), "=r"(r[1]), "=r"(r[2]), "=r"(r[3]) : "r"(addr));
}
__device__ __forceinline__ void ldmx2(uint32_t* r, uint32_t addr) {
    asm volatile("ldmatrix.sync.aligned.m8n8.x2.shared.b16 {%0,%1}, [%2];"
                 : "=r"(r[0]), "=r"(r[1]) : "r"(addr));
}
__device__ __forceinline__ void ldmx2t(uint32_t* r, uint32_t addr) {
    asm volatile("ldmatrix.sync.aligned.m8n8.x2.trans.shared.b16 {%0,%1}, [%2];"
                 : "=r"(r[0]), "=r"(r[1]) : "r"(addr));
}
__device__ __forceinline__ void mma16816(float* c, const uint32_t* a, const uint32_t* b) {
    asm volatile(
        "mma.sync.aligned.m16n8k16.row.col.f32.bf16.bf16.f32 "
        "{%0,%1,%2,%3}, {%4,%5,%6,%7}, {%8,%9}, {%0,%1,%2,%3};"
        : "+f"(c[0]), "+f"(c[1]), "+f"(c[2]), "+f"(c[3])
        : "r"(a[0]), "r"(a[1]), "r"(a[2]), "r"(a[3]), "r"(b[0]), "r"(b[1]));
}
__device__ __forceinline__ void cp16(uint32_t saddr, const void* g) {
    asm volatile("cp.async.cg.shared.global [%0], [%1], 16;"
                 :: "r"(saddr), "l"(g));
}
__device__ __forceinline__ void cp_commit() {
    asm volatile("cp.async.commit_group;");
}
template <int N>
__device__ __forceinline__ void cp_wait() {
    asm volatile("cp.async.wait_group %0;" :: "n"(N));
}

__device__ __forceinline__ uint32_t pack_bf2(__nv_bfloat16 lo, __nv_bfloat16 hi) {
    __nv_bfloat162 t(lo, hi);   // .x = lo 16 bits
    return *(uint32_t*)&t;
}

// ---------------------------------------------------------------------------
// Split / transpose helpers
// ---------------------------------------------------------------------------
__global__ __launch_bounds__(256) void split2_kernel(
    const float* __restrict__ x, __nv_bfloat16* __restrict__ h,
    __nv_bfloat16* __restrict__ l, int n4)
{
    int i = blockIdx.x * blockDim.x + threadIdx.x;
    if (i >= n4) return;
    float4 v = ((const float4*)x)[i];
    __nv_bfloat16 ha[4], la[4];
    float f[4] = {v.x, v.y, v.z, v.w};
#pragma unroll
    for (int j = 0; j < 4; j++) {
        ha[j] = __float2bfloat16(f[j]);
        la[j] = __float2bfloat16(f[j] - __bfloat162float(ha[j]));
    }
    ((uint2*)h)[i] = *(const uint2*)ha;
    ((uint2*)l)[i] = *(const uint2*)la;
}

// W [K,N] fp32 -> Wt hi/lo [N,K] bf16, 4 weights via blockIdx.z
__global__ __launch_bounds__(256) void tsplit_kernel(
    const float* __restrict__ W0, const float* __restrict__ W1,
    const float* __restrict__ W2, const float* __restrict__ W3,
    __nv_bfloat16* __restrict__ Th0, __nv_bfloat16* __restrict__ Tl0)
{
    __shared__ float t[32][33];
    const int z = blockIdx.z;
    const float* W = (z == 0) ? W0 : ((z == 1) ? W1 : ((z == 2) ? W2 : W3));
    __nv_bfloat16* Th = Th0 + (size_t)z * DM * DM;
    __nv_bfloat16* Tl = Tl0 + (size_t)z * DM * DM;
    const int n0 = blockIdx.x * 32, k0 = blockIdx.y * 32;
    const int tx = threadIdx.x, ty = threadIdx.y;  // 32 x 8
    for (int i = ty; i < 32; i += 8)
        t[i][tx] = W[(size_t)(k0 + i) * DM + n0 + tx];
    __syncthreads();
    for (int i = ty; i < 32; i += 8) {
        float v = t[tx][i];  // = W[k0+tx][n0+i]
        __nv_bfloat16 hi = __float2bfloat16(v);
        __nv_bfloat16 lo = __float2bfloat16(v - __bfloat162float(hi));
        Th[(size_t)(n0 + i) * DM + k0 + tx] = hi;
        Tl[(size_t)(n0 + i) * DM + k0 + tx] = lo;
    }
}

// ---------------------------------------------------------------------------
// mma.sync GEMM, 2-stage cp.async pipeline, BK=32, 2 CTAs/SM.
// C[M,N] = A[M,K] @ Wt^T + bias via bf16x3 split.
// CTA 128x128 tile, 256 threads (8 warps 2x4), warp tile 64x32.
// smem rows padded to 80B: ldmatrix banks (row*20 mod 32) all distinct.
// ---------------------------------------------------------------------------
constexpr int GK = 32;
constexpr int GROWB = 80;                         // bytes per padded row
constexpr int GT_BYTES = 128 * GROWB;             // 10240 per tile
constexpr int GSTAGE = 4 * GT_BYTES;              // 40960 per stage
constexpr int SMG_TOTAL = 2 * GSTAGE;             // 81920

template<bool SPLIT>
__global__ __launch_bounds__(256, 2) void gemm_mma(
    const __nv_bfloat16* __restrict__ Ah, const __nv_bfloat16* __restrict__ Al,
    const __nv_bfloat16* __restrict__ Wh0, const __nv_bfloat16* __restrict__ Wl0,
    const float* __restrict__ b0, const float* __restrict__ b1,
    const float* __restrict__ b2,
    float* __restrict__ F0,
    __nv_bfloat16* __restrict__ H0, __nv_bfloat16* __restrict__ H1,
    __nv_bfloat16* __restrict__ H2,
    __nv_bfloat16* __restrict__ L0, __nv_bfloat16* __restrict__ L1,
    __nv_bfloat16* __restrict__ L2)
{
    extern __shared__ char smem[];
    const int z = blockIdx.z;
    const __nv_bfloat16* Wh = Wh0 + (size_t)z * DM * DM;
    const __nv_bfloat16* Wl = Wl0 + (size_t)z * DM * DM;
    const float* bias = (z == 0) ? b0 : ((z == 1) ? b1 : b2);

    const int tid  = threadIdx.x;
    const int wid  = tid >> 5, lane = tid & 31;
    const int mBase = blockIdx.y * 128, nBase = blockIdx.x * 128;

    const uint32_t sb = smem_u32(smem);

    const int wm = wid >> 2, wn = wid & 3;
    const int mrow0 = wm * 64, nrow0 = wn * 32;

    const uint32_t aOff = (uint32_t)(((lane & 7) + ((lane >> 3) & 1) * 8) * GROWB
                                     + (lane >> 4) * 16);
    const int l15 = lane & 15;
    const uint32_t bOff = (uint32_t)((l15 & 7) * GROWB + (l15 >> 3) * 16);

    // fill: 2 threads per row; each covers 2x16B chunks of the 64B row data
    const int frow = tid >> 1;           // 0..127
    const int fcb  = (tid & 1) * 32;     // byte offset in row data

    const __nv_bfloat16* gAh = Ah + (size_t)mBase * DM;
    const __nv_bfloat16* gAl = Al + (size_t)mBase * DM;
    const __nv_bfloat16* gBh = Wh + (size_t)nBase * DM;
    const __nv_bfloat16* gBl = Wl + (size_t)nBase * DM;

    auto issue = [&](int it, int st) {
        const int k0 = it * GK;
        const uint32_t s0 = sb + (uint32_t)st * GSTAGE;
        const size_t go = (size_t)frow * DM + k0 + fcb / 2;
        const uint32_t so = (uint32_t)(frow * GROWB + fcb);
#pragma unroll
        for (int u = 0; u < 2; u++) {
            cp16(s0 + 0 * GT_BYTES + so + u * 16, gAh + go + u * 8);
            cp16(s0 + 1 * GT_BYTES + so + u * 16, gAl + go + u * 8);
            cp16(s0 + 2 * GT_BYTES + so + u * 16, gBh + go + u * 8);
            cp16(s0 + 3 * GT_BYTES + so + u * 16, gBl + go + u * 8);
        }
        cp_commit();
    };

    float c[4][4][4];
#pragma unroll
    for (int i = 0; i < 4; i++)
#pragma unroll
        for (int j = 0; j < 4; j++)
#pragma unroll
            for (int e = 0; e < 4; e++) c[i][j][e] = 0.0f;

    constexpr int NIT = DM / GK;   // 32
    issue(0, 0);

    for (int it = 0; it < NIT; it++) {
        const int cur = it & 1;
        if (it + 1 < NIT) {
            issue(it + 1, cur ^ 1);
            cp_wait<1>();
        } else {
            cp_wait<0>();
        }
        __syncthreads();

        const uint32_t sAH = sb + (uint32_t)cur * GSTAGE;
        const uint32_t sAL = sAH + GT_BYTES;
        const uint32_t sBH = sAH + 2 * GT_BYTES;
        const uint32_t sBL = sAH + 3 * GT_BYTES;

#pragma unroll
        for (int ks = 0; ks < GK / 16; ks++) {
            const uint32_t kb = (uint32_t)(ks * 32);
            uint32_t ah[4][4], al[4][4], bh[4][2], bl[4][2];
#pragma unroll
            for (int mf = 0; mf < 4; mf++) {
                const uint32_t ro = (uint32_t)((mrow0 + mf * 16) * GROWB) + kb + aOff;
                ldmx4(ah[mf], sAH + ro);
                ldmx4(al[mf], sAL + ro);
            }
#pragma unroll
            for (int nf = 0; nf < 4; nf++) {
                const uint32_t ro = (uint32_t)((nrow0 + nf * 8) * GROWB) + kb + bOff;
                ldmx2(bh[nf], sBH + ro);
                ldmx2(bl[nf], sBL + ro);
            }
#pragma unroll
            for (int mf = 0; mf < 4; mf++)
#pragma unroll
                for (int nf = 0; nf < 4; nf++) {
                    mma16816(c[mf][nf], ah[mf], bh[nf]);
                    mma16816(c[mf][nf], al[mf], bh[nf]);
                    mma16816(c[mf][nf], ah[mf], bl[nf]);
                }
        }
        __syncthreads();   // stage cur reusable at it+2's issue
    }

    const int crow = lane >> 2, ccol = (lane & 3) * 2;
    if (SPLIT) {
        __nv_bfloat16* Hd = (z == 0) ? H0 : ((z == 1) ? H1 : H2);
        __nv_bfloat16* Ld = (z == 0) ? L0 : ((z == 1) ? L1 : L2);
        const float scale = (z == 0) ? 0.125f : 1.0f;   // fold 1/sqrt(DK) into Q
#pragma unroll
        for (int mf = 0; mf < 4; mf++) {
#pragma unroll
            for (int nf = 0; nf < 4; nf++) {
                const int r  = mBase + mrow0 + mf * 16 + crow;
                const int cc = nBase + nrow0 + nf * 8 + ccol;
                const float bx = bias[cc], by = bias[cc + 1];
#pragma unroll
                for (int half = 0; half < 2; half++) {
                    const int rr = r + half * 8;
                    float v0 = (c[mf][nf][half * 2 + 0] + bx) * scale;
                    float v1 = (c[mf][nf][half * 2 + 1] + by) * scale;
                    __nv_bfloat16 h0 = __float2bfloat16(v0);
                    __nv_bfloat16 h1 = __float2bfloat16(v1);
                    __nv_bfloat16 r0 = __float2bfloat16(v0 - __bfloat162float(h0));
                    __nv_bfloat16 r1 = __float2bfloat16(v1 - __bfloat162float(h1));
                    *(uint32_t*)(Hd + (size_t)rr * DM + cc) = pack_bf2(h0, h1);
                    *(uint32_t*)(Ld + (size_t)rr * DM + cc) = pack_bf2(r0, r1);
                }
            }
        }
    } else {
#pragma unroll
        for (int mf = 0; mf < 4; mf++) {
#pragma unroll
            for (int nf = 0; nf < 4; nf++) {
                const int r  = mBase + mrow0 + mf * 16 + crow;
                const int cc = nBase + nrow0 + nf * 8 + ccol;
                const float bx = bias[cc], by = bias[cc + 1];
                float2 v0 = { c[mf][nf][0] + bx, c[mf][nf][1] + by };
                float2 v1 = { c[mf][nf][2] + bx, c[mf][nf][3] + by };
                *(float2*)(F0 + (size_t)r * DM + cc)       = v0;
                *(float2*)(F0 + (size_t)(r + 8) * DM + cc) = v1;
            }
        }
    }
}

// ---------------------------------------------------------------------------
// Flash attention on tensor cores, 2-stage cp.async K/V pipeline, 2 CTAs/SM.
// CTA: 128 q-rows for one (b,h); 8 warps x 16 rows. KV tiles of 64.
// smem: Qh,Ql [128][72]; 2 stages of {Kh,Kl,Vh,Vl}[64][72]
// ---------------------------------------------------------------------------
constexpr int AT_Q   = 0;
constexpr int AT_QL  = 128 * 144;                    // 18432
constexpr int AT_KV0 = 2 * 128 * 144;                // 36864
constexpr int KV_T   = 64 * 144;                     // 9216 per tile
constexpr int KV_STAGE = 4 * KV_T;                   // 36864 per stage
constexpr int SMA_TOTAL = AT_KV0 + 2 * KV_STAGE;     // 110592

__global__ __launch_bounds__(256, 2) void attn_mma(
    const __nv_bfloat16* __restrict__ Qh, const __nv_bfloat16* __restrict__ Ql,
    const __nv_bfloat16* __restrict__ Kh, const __nv_bfloat16* __restrict__ Kl,
    const __nv_bfloat16* __restrict__ Vh, const __nv_bfloat16* __restrict__ Vl,
    __nv_bfloat16* __restrict__ Oh, __nv_bfloat16* __restrict__ Ol)
{
    extern __shared__ char smem[];
    const uint32_t sb = smem_u32(smem);
    const int tid = threadIdx.x;
    const int wid = tid >> 5, lane = tid & 31;
    const int b = blockIdx.z, h = blockIdx.y;
    const int q0 = blockIdx.x * 128;
    const int hc = h * DK;

    const int frow = tid >> 2, fcb = (tid & 3) * 16;   // KV fill: 64 rows x 64 cols

    auto issueKV = [&](int kv0, int st) {
        const size_t go = (size_t)(b * S + kv0 + frow) * DM + hc + fcb;
        const uint32_t s0 = sb + AT_KV0 + (uint32_t)st * KV_STAGE;
        const uint32_t so = (uint32_t)(frow * 144 + fcb * 2);
#pragma unroll
        for (int u = 0; u < 2; u++) {
            cp16(s0 + 0 * KV_T + so + u * 16, Kh + go + u * 8);
            cp16(s0 + 1 * KV_T + so + u * 16, Kl + go + u * 8);
            cp16(s0 + 2 * KV_T + so + u * 16, Vh + go + u * 8);
            cp16(s0 + 3 * KV_T + so + u * 16, Vl + go + u * 8);
        }
        cp_commit();
    };

    // ---- fill Q tile (128 x 64 bf16, hi+lo)
    {
        const int row = tid >> 1, cb = (tid & 1) * 32;
        const size_t go = (size_t)(b * S + q0 + row) * DM + hc + cb;
        const uint32_t so = (uint32_t)(row * 144 + cb * 2);
#pragma unroll
        for (int u = 0; u < 4; u++) {
            *(uint4*)(smem + AT_Q  + so + u * 16) = *(const uint4*)(Qh + go + u * 8);
            *(uint4*)(smem + AT_QL + so + u * 16) = *(const uint4*)(Ql + go + u * 8);
        }
    }
    issueKV(0, 0);
    __syncthreads();

    // ---- preload Q fragments
    const uint32_t aOff = (uint32_t)(((lane & 7) + ((lane >> 3) & 1) * 8) * 144
                                     + (lane >> 4) * 16);
    const int l15 = lane & 15;
    const uint32_t bOff = (uint32_t)((l15 & 7) * 144 + (l15 >> 3) * 16);
    const uint32_t vOff = (uint32_t)(l15 * 144);

    uint32_t qhF[4][4], qlF[4][4];
#pragma unroll
    for (int kd = 0; kd < 4; kd++) {
        const uint32_t ro = (uint32_t)(wid * 16 * 144) + kd * 32 + aOff;
        ldmx4(qhF[kd], sb + AT_Q  + ro);
        ldmx4(qlF[kd], sb + AT_QL + ro);
    }

    float o[8][4];
#pragma unroll
    for (int nd = 0; nd < 8; nd++)
#pragma unroll
        for (int e = 0; e < 4; e++) o[nd][e] = 0.0f;
    float m0 = -1e30f, m1 = -1e30f, l0 = 0.0f, l1 = 0.0f;

    constexpr int NT = S / 64;   // 32
    for (int t = 0; t < NT; t++) {
        const int cur = t & 1;
        if (t + 1 < NT) {
            issueKV((t + 1) * 64, cur ^ 1);
            cp_wait<1>();
        } else {
            cp_wait<0>();
        }
        __syncthreads();

        const uint32_t sKH = sb + AT_KV0 + (uint32_t)cur * KV_STAGE;
        const uint32_t sKL = sKH + KV_T;
        const uint32_t sVH = sKH + 2 * KV_T;
        const uint32_t sVL = sKH + 3 * KV_T;

        // ---- S = Q K^T
        float s[8][4];
#pragma unroll
        for (int nf = 0; nf < 8; nf++)
#pragma unroll
            for (int e = 0; e < 4; e++) s[nf][e] = 0.0f;

#pragma unroll
        for (int nf = 0; nf < 8; nf++) {
#pragma unroll
            for (int kd = 0; kd < 4; kd++) {
                const uint32_t ro = (uint32_t)(nf * 8 * 144) + kd * 32 + bOff;
                uint32_t kh[2], kl[2];
                ldmx2(kh, sKH + ro);
                ldmx2(kl, sKL + ro);
                mma16816(s[nf], qhF[kd], kh);
                mma16816(s[nf], qlF[kd], kh);
                mma16816(s[nf], qhF[kd], kl);
            }
        }

        // ---- online softmax
        float mx0 = -1e30f, mx1 = -1e30f;
#pragma unroll
        for (int nf = 0; nf < 8; nf++) {
            mx0 = fmaxf(mx0, fmaxf(s[nf][0], s[nf][1]));
            mx1 = fmaxf(mx1, fmaxf(s[nf][2], s[nf][3]));
        }
        mx0 = fmaxf(mx0, __shfl_xor_sync(0xffffffffu, mx0, 1));
        mx0 = fmaxf(mx0, __shfl_xor_sync(0xffffffffu, mx0, 2));
        mx1 = fmaxf(mx1, __shfl_xor_sync(0xffffffffu, mx1, 1));
        mx1 = fmaxf(mx1, __shfl_xor_sync(0xffffffffu, mx1, 2));

        const float nm0 = fmaxf(m0, mx0), nm1 = fmaxf(m1, mx1);
        const float a0 = __expf(m0 - nm0), a1 = __expf(m1 - nm1);
        m0 = nm0; m1 = nm1;

        float ls0 = 0.0f, ls1 = 0.0f;
#pragma unroll
        for (int nf = 0; nf < 8; nf++) {
            s[nf][0] = __expf(s[nf][0] - m0);
            s[nf][1] = __expf(s[nf][1] - m0);
            s[nf][2] = __expf(s[nf][2] - m1);
            s[nf][3] = __expf(s[nf][3] - m1);
            ls0 += s[nf][0] + s[nf][1];
            ls1 += s[nf][2] + s[nf][3];
        }
        ls0 += __shfl_xor_sync(0xffffffffu, ls0, 1);
        ls0 += __shfl_xor_sync(0xffffffffu, ls0, 2);
        ls1 += __shfl_xor_sync(0xffffffffu, ls1, 1);
        ls1 += __shfl_xor_sync(0xffffffffu, ls1, 2);
        l0 = l0 * a0 + ls0;
        l1 = l1 * a1 + ls1;
#pragma unroll
        for (int nd = 0; nd < 8; nd++) {
            o[nd][0] *= a0; o[nd][1] *= a0;
            o[nd][2] *= a1; o[nd][3] *= a1;
        }

        // ---- O += P V
#pragma unroll
        for (int kd = 0; kd < 4; kd++) {
            uint32_t pah[4], pal[4];
#pragma unroll
            for (int half = 0; half < 2; half++) {
                const int nf = 2 * kd + half;
#pragma unroll
                for (int rr = 0; rr < 2; rr++) {
                    float p0 = s[nf][rr * 2 + 0];
                    float p1 = s[nf][rr * 2 + 1];
                    __nv_bfloat16 h0 = __float2bfloat16(p0);
                    __nv_bfloat16 h1 = __float2bfloat16(p1);
                    __nv_bfloat16 r0b = __float2bfloat16(p0 - __bfloat162float(h0));
                    __nv_bfloat16 r1b = __float2bfloat16(p1 - __bfloat162float(h1));
                    pah[half * 2 + rr] = pack_bf2(h0, h1);
                    pal[half * 2 + rr] = pack_bf2(r0b, r1b);
                }
            }
#pragma unroll
            for (int nd = 0; nd < 8; nd++) {
                const uint32_t ro = (uint32_t)(kd * 16 * 144) + vOff + nd * 16;
                uint32_t vh[2], vl[2];
                ldmx2t(vh, sVH + ro);
                ldmx2t(vl, sVL + ro);
                mma16816(o[nd], pah, vh);
                mma16816(o[nd], pal, vh);
                mma16816(o[nd], pah, vl);
            }
        }
        __syncthreads();
    }

    // ---- epilogue: normalize, split to bf16 hi/lo, store
    const float inv0 = 1.0f / l0, inv1 = 1.0f / l1;
    const int gr0 = b * S + q0 + wid * 16 + (lane >> 2);
#pragma unroll
    for (int nd = 0; nd < 8; nd++) {
        const int cc = hc + nd * 8 + (lane & 3) * 2;
#pragma unroll
        for (int half = 0; half < 2; half++) {
            const int rr = gr0 + half * 8;
            const float inv = half ? inv1 : inv0;
            float v0 = o[nd][half * 2 + 0] * inv;
            float v1 = o[nd][half * 2 + 1] * inv;
            __nv_bfloat16 h0 = __float2bfloat16(v0);
            __nv_bfloat16 h1 = __float2bfloat16(v1);
            __nv_bfloat16 r0b = __float2bfloat16(v0 - __bfloat162float(h0));
            __nv_bfloat16 r1b = __float2bfloat16(v1 - __bfloat162float(h1));
            *(uint32_t*)(Oh + (size_t)rr * DM + cc) = pack_bf2(h0, h1);
            *(uint32_t*)(Ol + (size_t)rr * DM + cc) = pack_bf2(r0b, r1b);
        }
    }
}

// ===========================================================================
// Launch
// ===========================================================================
extern "C" void kernel_launch(void* const* d_in, const int* in_sizes, int n_in,
                              void* d_out, int out_size)
{
    const float* x  = (const float*)d_in[0];
    const float* wq = (const float*)d_in[1];
    const float* bq = (const float*)d_in[2];
    const float* wk = (const float*)d_in[3];
    const float* bk = (const float*)d_in[4];
    const float* wv = (const float*)d_in[5];
    const float* bv = (const float*)d_in[6];
    const float* wo = (const float*)d_in[7];
    const float* bo = (const float*)d_in[8];
    float* out = (float*)d_out;

    __nv_bfloat16 *xh, *xl, *qh, *ql, *kh, *kl, *vh, *vl, *ah, *al, *wth, *wtl;
    cudaGetSymbolAddress((void**)&xh, g_xh);
    cudaGetSymbolAddress((void**)&xl, g_xl);
    cudaGetSymbolAddress((void**)&qh, g_qh);
    cudaGetSymbolAddress((void**)&ql, g_ql);
    cudaGetSymbolAddress((void**)&kh, g_kh);
    cudaGetSymbolAddress((void**)&kl, g_kl);
    cudaGetSymbolAddress((void**)&vh, g_vh);
    cudaGetSymbolAddress((void**)&vl, g_vl);
    cudaGetSymbolAddress((void**)&ah, g_ah);
    cudaGetSymbolAddress((void**)&al, g_al);
    cudaGetSymbolAddress((void**)&wth, g_wth);
    cudaGetSymbolAddress((void**)&wtl, g_wtl);

    cudaFuncSetAttribute(gemm_mma<true>,  cudaFuncAttributeMaxDynamicSharedMemorySize, SMG_TOTAL);
    cudaFuncSetAttribute(gemm_mma<false>, cudaFuncAttributeMaxDynamicSharedMemorySize, SMG_TOTAL);
    cudaFuncSetAttribute(attn_mma, cudaFuncAttributeMaxDynamicSharedMemorySize, SMA_TOTAL);

    const size_t WSZ = (size_t)DM * DM;

    // 1) operand prep
    split2_kernel<<<(MR * DM / 4 + 255) / 256, 256>>>(x, xh, xl, MR * DM / 4);
    dim3 gT(DM / 32, DM / 32, 4);
    tsplit_kernel<<<gT, dim3(32, 8)>>>(wq, wk, wv, wo, wth, wtl);

    // 2) fused QKV projections -> bf16 hi/lo (Q pre-scaled by 1/sqrt(DK))
    dim3 gQKV(DM / 128, MR / 128, 3);
    gemm_mma<true><<<gQKV, 256, SMG_TOTAL>>>(
        xh, xl, wth, wtl, bq, bk, bv,
        nullptr, qh, kh, vh, ql, kl, vl);

    // 3) attention (tensor cores) -> bf16 hi/lo
    dim3 gAttn(S / 128, H, B);   // (16, 16, 2)
    attn_mma<<<gAttn, 256, SMA_TOTAL>>>(qh, ql, kh, kl, vh, vl, ah, al);

    // 4) output projection -> fp32 out
    dim3 gO(DM / 128, MR / 128, 1);
    gemm_mma<false><<<gO, 256, SMG_TOTAL>>>(
        ah, al, wth + 3 * WSZ, wtl + 3 * WSZ, bo, bo, bo,
        out, nullptr, nullptr, nullptr, nullptr, nullptr, nullptr);
}

// round 10
// speedup vs baseline: 1.0730x; 1.0730x over previous
#include <cuda_runtime.h>
#include <cuda_bf16.h>
#include <cstdint>
#include <math.h>

// Problem constants
constexpr int B  = 2;
constexpr int S  = 2048;
constexpr int DM = 1024;   // d_model
constexpr int H  = 16;
constexpr int DK = 64;
constexpr int MR = B * S;  // 4096 rows

// ---------------------------------------------------------------------------
// Scratch (allocation-free: __device__ globals)
// ---------------------------------------------------------------------------
__device__ __nv_bfloat16 g_xh[MR * DM];
__device__ __nv_bfloat16 g_xl[MR * DM];
__device__ __nv_bfloat16 g_qh[MR * DM];
__device__ __nv_bfloat16 g_ql[MR * DM];
__device__ __nv_bfloat16 g_kh[MR * DM];
__device__ __nv_bfloat16 g_kl[MR * DM];
__device__ __nv_bfloat16 g_vh[MR * DM];
__device__ __nv_bfloat16 g_vl[MR * DM];
__device__ __nv_bfloat16 g_ah[MR * DM];
__device__ __nv_bfloat16 g_al[MR * DM];
__device__ __nv_bfloat16 g_wth[4 * DM * DM];  // transposed weights, hi part
__device__ __nv_bfloat16 g_wtl[4 * DM * DM];  // transposed weights, lo part

// ---------------------------------------------------------------------------
// mma.sync / ldmatrix / cp.async helpers (non-'a' PTX surface)
// ---------------------------------------------------------------------------
__device__ __forceinline__ uint32_t smem_u32(const void* p) {
    uint32_t a;
    asm("{ .reg .u64 t; cvta.to.shared.u64 t, %1; cvt.u32.u64 %0, t; }"
        : "=r"(a) : "l"(p));
    return a;
}

__device__ __forceinline__ void ldmx4(uint32_t* r, uint32_t addr) {
    asm volatile("ldmatrix.sync.aligned.m8n8.x4.shared.b16 {%0,%1,%2,%3}, [%4];"
                 : "=r"(r[0]), "=r"(r[1]), "=r"(r[2]), "=r"(r[3]) : "r"(addr));
}
__device__ __forceinline__ void ldmx2(uint32_t* r, uint32_t addr) {
    asm volatile("ldmatrix.sync.aligned.m8n8.x2.shared.b16 {%0,%1}, [%2];"
                 : "=r"(r[0]), "=r"(r[1]) : "r"(addr));
}
__device__ __forceinline__ void ldmx2t(uint32_t* r, uint32_t addr) {
    asm volatile("ldmatrix.sync.aligned.m8n8.x2.trans.shared.b16 {%0,%1}, [%2];"
                 : "=r"(r[0]), "=r"(r[1]) : "r"(addr));
}
__device__ __forceinline__ void mma16816(float* c, const uint32_t* a, const uint32_t* b) {
    asm volatile(
        "mma.sync.aligned.m16n8k16.row.col.f32.bf16.bf16.f32 "
        "{%0,%1,%2,%3}, {%4,%5,%6,%7}, {%8,%9}, {%0,%1,%2,%3};"
        : "+f"(c[0]), "+f"(c[1]), "+f"(c[2]), "+f"(c[3])
        : "r"(a[0]), "r"(a[1]), "r"(a[2]), "r"(a[3]), "r"(b[0]), "r"(b[1]));
}
__device__ __forceinline__ void cp16(uint32_t saddr, const void* g) {
    asm volatile("cp.async.cg.shared.global [%0], [%1], 16;"
                 :: "r"(saddr), "l"(g));
}
__device__ __forceinline__ void cp_commit() {
    asm volatile("cp.async.commit_group;");
}
template <int N>
__device__ __forceinline__ void cp_wait() {
    asm volatile("cp.async.wait_group %0;" :: "n"(N));
}

// Split two fp32 into packed bf16 hi pair + bf16 lo (residual) pair.
// hi.x/lo.x correspond to v0; hi.y/lo.y to v1.
__device__ __forceinline__ void split_pack2(float v0, float v1,
                                            uint32_t& hi, uint32_t& lo) {
    float2 f = {v0, v1};
    __nv_bfloat162 h = __float22bfloat162_rn(f);
    hi = *(uint32_t*)&h;
    float r0 = v0 - __uint_as_float(hi << 16);
    float r1 = v1 - __uint_as_float(hi & 0xffff0000u);
    float2 fr = {r0, r1};
    __nv_bfloat162 l = __float22bfloat162_rn(fr);
    lo = *(uint32_t*)&l;
}

// ---------------------------------------------------------------------------
// Split / transpose helpers
// ---------------------------------------------------------------------------
__global__ __launch_bounds__(256) void split2_kernel(
    const float* __restrict__ x, __nv_bfloat16* __restrict__ h,
    __nv_bfloat16* __restrict__ l, int n4)
{
    int i = blockIdx.x * blockDim.x + threadIdx.x;
    if (i >= n4) return;
    float4 v = ((const float4*)x)[i];
    uint32_t h0, l0, h1, l1;
    split_pack2(v.x, v.y, h0, l0);
    split_pack2(v.z, v.w, h1, l1);
    ((uint2*)h)[i] = make_uint2(h0, h1);
    ((uint2*)l)[i] = make_uint2(l0, l1);
}

// W [K,N] fp32 -> Wt hi/lo [N,K] bf16, 4 weights via blockIdx.z
__global__ __launch_bounds__(256) void tsplit_kernel(
    const float* __restrict__ W0, const float* __restrict__ W1,
    const float* __restrict__ W2, const float* __restrict__ W3,
    __nv_bfloat16* __restrict__ Th0, __nv_bfloat16* __restrict__ Tl0)
{
    __shared__ float t[32][33];
    const int z = blockIdx.z;
    const float* W = (z == 0) ? W0 : ((z == 1) ? W1 : ((z == 2) ? W2 : W3));
    __nv_bfloat16* Th = Th0 + (size_t)z * DM * DM;
    __nv_bfloat16* Tl = Tl0 + (size_t)z * DM * DM;
    const int n0 = blockIdx.x * 32, k0 = blockIdx.y * 32;
    const int tx = threadIdx.x, ty = threadIdx.y;  // 32 x 8
    for (int i = ty; i < 32; i += 8)
        t[i][tx] = W[(size_t)(k0 + i) * DM + n0 + tx];
    __syncthreads();
    for (int i = ty; i < 32; i += 8) {
        float v = t[tx][i];  // = W[k0+tx][n0+i]
        __nv_bfloat16 hi = __float2bfloat16(v);
        __nv_bfloat16 lo = __float2bfloat16(v - __bfloat162float(hi));
        Th[(size_t)(n0 + i) * DM + k0 + tx] = hi;
        Tl[(size_t)(n0 + i) * DM + k0 + tx] = lo;
    }
}

// ---------------------------------------------------------------------------
// mma.sync GEMM, 2-stage cp.async pipeline, BK=64 (R7 config), term-major MMA.
// C[M,N] = A[M,K] @ Wt^T + bias via bf16x3 split.
// CTA 128x128 tile, 256 threads (8 warps 2x4), warp tile 64x32.
// ---------------------------------------------------------------------------
constexpr int GK = 64;
constexpr int GPAD = 72;
constexpr int GT_BYTES = 128 * GPAD * 2;          // 18432 per tile
constexpr int GSTAGE = 4 * GT_BYTES;              // 73728 per stage
constexpr int SMG_TOTAL = 2 * GSTAGE;             // 147456

template<bool SPLIT>
__global__ __launch_bounds__(256) void gemm_mma(
    const __nv_bfloat16* __restrict__ Ah, const __nv_bfloat16* __restrict__ Al,
    const __nv_bfloat16* __restrict__ Wh0, const __nv_bfloat16* __restrict__ Wl0,
    const float* __restrict__ b0, const float* __restrict__ b1,
    const float* __restrict__ b2,
    float* __restrict__ F0,
    __nv_bfloat16* __restrict__ H0, __nv_bfloat16* __restrict__ H1,
    __nv_bfloat16* __restrict__ H2,
    __nv_bfloat16* __restrict__ L0, __nv_bfloat16* __restrict__ L1,
    __nv_bfloat16* __restrict__ L2)
{
    extern __shared__ char smem[];
    const int z = blockIdx.z;
    const __nv_bfloat16* Wh = Wh0 + (size_t)z * DM * DM;
    const __nv_bfloat16* Wl = Wl0 + (size_t)z * DM * DM;
    const float* bias = (z == 0) ? b0 : ((z == 1) ? b1 : b2);

    const int tid  = threadIdx.x;
    const int wid  = tid >> 5, lane = tid & 31;
    const int mBase = blockIdx.y * 128, nBase = blockIdx.x * 128;

    const uint32_t sb = smem_u32(smem);

    const int wm = wid >> 2, wn = wid & 3;
    const int mrow0 = wm * 64, nrow0 = wn * 32;

    const uint32_t aOff = (uint32_t)(((lane & 7) + ((lane >> 3) & 1) * 8) * 144
                                     + (lane >> 4) * 16);
    const int l15 = lane & 15;
    const uint32_t bOff = (uint32_t)((l15 & 7) * 144 + (l15 >> 3) * 16);

    const int frow = tid >> 3;           // 0..31
    const int fcol = (tid & 7) * 8;      // bf16 elems

    const __nv_bfloat16* gAh = Ah + (size_t)mBase * DM;
    const __nv_bfloat16* gAl = Al + (size_t)mBase * DM;
    const __nv_bfloat16* gBh = Wh + (size_t)nBase * DM;
    const __nv_bfloat16* gBl = Wl + (size_t)nBase * DM;

    auto issue = [&](int it, int st) {
        const int k0 = it * GK;
        const uint32_t s0 = sb + (uint32_t)st * GSTAGE;
#pragma unroll
        for (int p = 0; p < 4; p++) {
            const int row = p * 32 + frow;
            const size_t go = (size_t)row * DM + k0 + fcol;
            const uint32_t so = (uint32_t)(row * GPAD + fcol) * 2;
            cp16(s0 + 0 * GT_BYTES + so, gAh + go);
            cp16(s0 + 1 * GT_BYTES + so, gAl + go);
            cp16(s0 + 2 * GT_BYTES + so, gBh + go);
            cp16(s0 + 3 * GT_BYTES + so, gBl + go);
        }
        cp_commit();
    };

    float c[4][4][4];
#pragma unroll
    for (int i = 0; i < 4; i++)
#pragma unroll
        for (int j = 0; j < 4; j++)
#pragma unroll
            for (int e = 0; e < 4; e++) c[i][j][e] = 0.0f;

    constexpr int NIT = DM / GK;   // 16
    issue(0, 0);

    for (int it = 0; it < NIT; it++) {
        const int cur = it & 1;
        if (it + 1 < NIT) {
            issue(it + 1, cur ^ 1);
            cp_wait<1>();
        } else {
            cp_wait<0>();
        }
        __syncthreads();

        const uint32_t sAH = sb + (uint32_t)cur * GSTAGE;
        const uint32_t sAL = sAH + GT_BYTES;
        const uint32_t sBH = sAH + 2 * GT_BYTES;
        const uint32_t sBL = sAH + 3 * GT_BYTES;

#pragma unroll
        for (int ks = 0; ks < GK / 16; ks++) {
            const uint32_t kb = (uint32_t)(ks * 32);
            uint32_t ah[4][4], al[4][4], bh[4][2], bl[4][2];
#pragma unroll
            for (int mf = 0; mf < 4; mf++) {
                const uint32_t ro = (uint32_t)((mrow0 + mf * 16) * 144) + kb + aOff;
                ldmx4(ah[mf], sAH + ro);
                ldmx4(al[mf], sAL + ro);
            }
#pragma unroll
            for (int nf = 0; nf < 4; nf++) {
                const uint32_t ro = (uint32_t)((nrow0 + nf * 8) * 144) + kb + bOff;
                ldmx2(bh[nf], sBH + ro);
                ldmx2(bl[nf], sBL + ro);
            }
            // term-major: 16 independent accumulators between same-c MMAs
#pragma unroll
            for (int mf = 0; mf < 4; mf++)
#pragma unroll
                for (int nf = 0; nf < 4; nf++)
                    mma16816(c[mf][nf], ah[mf], bh[nf]);
#pragma unroll
            for (int mf = 0; mf < 4; mf++)
#pragma unroll
                for (int nf = 0; nf < 4; nf++)
                    mma16816(c[mf][nf], al[mf], bh[nf]);
#pragma unroll
            for (int mf = 0; mf < 4; mf++)
#pragma unroll
                for (int nf = 0; nf < 4; nf++)
                    mma16816(c[mf][nf], ah[mf], bl[nf]);
        }
        __syncthreads();   // stage cur reusable at it+2's issue
    }

    const int crow = lane >> 2, ccol = (lane & 3) * 2;
    if (SPLIT) {
        __nv_bfloat16* Hd = (z == 0) ? H0 : ((z == 1) ? H1 : H2);
        __nv_bfloat16* Ld = (z == 0) ? L0 : ((z == 1) ? L1 : L2);
        const float scale = (z == 0) ? 0.125f : 1.0f;   // fold 1/sqrt(DK) into Q
#pragma unroll
        for (int mf = 0; mf < 4; mf++) {
#pragma unroll
            for (int nf = 0; nf < 4; nf++) {
                const int r  = mBase + mrow0 + mf * 16 + crow;
                const int cc = nBase + nrow0 + nf * 8 + ccol;
                const float bx = bias[cc], by = bias[cc + 1];
#pragma unroll
                for (int half = 0; half < 2; half++) {
                    const int rr = r + half * 8;
                    float v0 = (c[mf][nf][half * 2 + 0] + bx) * scale;
                    float v1 = (c[mf][nf][half * 2 + 1] + by) * scale;
                    uint32_t hp, lp;
                    split_pack2(v0, v1, hp, lp);
                    *(uint32_t*)(Hd + (size_t)rr * DM + cc) = hp;
                    *(uint32_t*)(Ld + (size_t)rr * DM + cc) = lp;
                }
            }
        }
    } else {
#pragma unroll
        for (int mf = 0; mf < 4; mf++) {
#pragma unroll
            for (int nf = 0; nf < 4; nf++) {
                const int r  = mBase + mrow0 + mf * 16 + crow;
                const int cc = nBase + nrow0 + nf * 8 + ccol;
                const float bx = bias[cc], by = bias[cc + 1];
                float2 v0 = { c[mf][nf][0] + bx, c[mf][nf][1] + by };
                float2 v1 = { c[mf][nf][2] + bx, c[mf][nf][3] + by };
                *(float2*)(F0 + (size_t)r * DM + cc)       = v0;
                *(float2*)(F0 + (size_t)(r + 8) * DM + cc) = v1;
            }
        }
    }
}

// ---------------------------------------------------------------------------
// Flash attention on tensor cores, 2-stage cp.async K/V pipeline, 2 CTAs/SM.
// CTA: 128 q-rows for one (b,h); 8 warps x 16 rows. KV tiles of 64.
// Term-grouped MMA issue (RAW distance 4).
// smem: Qh,Ql [128][72]; 2 stages of {Kh,Kl,Vh,Vl}[64][72]
// ---------------------------------------------------------------------------
constexpr int AT_Q   = 0;
constexpr int AT_QL  = 128 * 144;                    // 18432
constexpr int AT_KV0 = 2 * 128 * 144;                // 36864
constexpr int KV_T   = 64 * 144;                     // 9216 per tile
constexpr int KV_STAGE = 4 * KV_T;                   // 36864 per stage
constexpr int SMA_TOTAL = AT_KV0 + 2 * KV_STAGE;     // 110592

__global__ __launch_bounds__(256, 2) void attn_mma(
    const __nv_bfloat16* __restrict__ Qh, const __nv_bfloat16* __restrict__ Ql,
    const __nv_bfloat16* __restrict__ Kh, const __nv_bfloat16* __restrict__ Kl,
    const __nv_bfloat16* __restrict__ Vh, const __nv_bfloat16* __restrict__ Vl,
    __nv_bfloat16* __restrict__ Oh, __nv_bfloat16* __restrict__ Ol)
{
    extern __shared__ char smem[];
    const uint32_t sb = smem_u32(smem);
    const int tid = threadIdx.x;
    const int wid = tid >> 5, lane = tid & 31;
    const int b = blockIdx.z, h = blockIdx.y;
    const int q0 = blockIdx.x * 128;
    const int hc = h * DK;

    const int frow = tid >> 2, fcb = (tid & 3) * 16;   // KV fill: 64 rows x 64 cols

    auto issueKV = [&](int kv0, int st) {
        const size_t go = (size_t)(b * S + kv0 + frow) * DM + hc + fcb;
        const uint32_t s0 = sb + AT_KV0 + (uint32_t)st * KV_STAGE;
        const uint32_t so = (uint32_t)(frow * 144 + fcb * 2);
#pragma unroll
        for (int u = 0; u < 2; u++) {
            cp16(s0 + 0 * KV_T + so + u * 16, Kh + go + u * 8);
            cp16(s0 + 1 * KV_T + so + u * 16, Kl + go + u * 8);
            cp16(s0 + 2 * KV_T + so + u * 16, Vh + go + u * 8);
            cp16(s0 + 3 * KV_T + so + u * 16, Vl + go + u * 8);
        }
        cp_commit();
    };

    // ---- fill Q tile (128 x 64 bf16, hi+lo)
    {
        const int row = tid >> 1, cb = (tid & 1) * 32;
        const size_t go = (size_t)(b * S + q0 + row) * DM + hc + cb;
        const uint32_t so = (uint32_t)(row * 144 + cb * 2);
#pragma unroll
        for (int u = 0; u < 4; u++) {
            *(uint4*)(smem + AT_Q  + so + u * 16) = *(const uint4*)(Qh + go + u * 8);
            *(uint4*)(smem + AT_QL + so + u * 16) = *(const uint4*)(Ql + go + u * 8);
        }
    }
    issueKV(0, 0);
    __syncthreads();

    // ---- preload Q fragments
    const uint32_t aOff = (uint32_t)(((lane & 7) + ((lane >> 3) & 1) * 8) * 144
                                     + (lane >> 4) * 16);
    const int l15 = lane & 15;
    const uint32_t bOff = (uint32_t)((l15 & 7) * 144 + (l15 >> 3) * 16);
    const uint32_t vOff = (uint32_t)(l15 * 144);

    uint32_t qhF[4][4], qlF[4][4];
#pragma unroll
    for (int kd = 0; kd < 4; kd++) {
        const uint32_t ro = (uint32_t)(wid * 16 * 144) + kd * 32 + aOff;
        ldmx4(qhF[kd], sb + AT_Q  + ro);
        ldmx4(qlF[kd], sb + AT_QL + ro);
    }

    float o[8][4];
#pragma unroll
    for (int nd = 0; nd < 8; nd++)
#pragma unroll
        for (int e = 0; e < 4; e++) o[nd][e] = 0.0f;
    float m0 = -1e30f, m1 = -1e30f, l0 = 0.0f, l1 = 0.0f;

    constexpr int NT = S / 64;   // 32
    for (int t = 0; t < NT; t++) {
        const int cur = t & 1;
        if (t + 1 < NT) {
            issueKV((t + 1) * 64, cur ^ 1);
            cp_wait<1>();
        } else {
            cp_wait<0>();
        }
        __syncthreads();

        const uint32_t sKH = sb + AT_KV0 + (uint32_t)cur * KV_STAGE;
        const uint32_t sKL = sKH + KV_T;
        const uint32_t sVH = sKH + 2 * KV_T;
        const uint32_t sVL = sKH + 3 * KV_T;

        // ---- S = Q K^T  (term-grouped, RAW distance 4)
        float s[8][4];
#pragma unroll
        for (int nf = 0; nf < 8; nf++)
#pragma unroll
            for (int e = 0; e < 4; e++) s[nf][e] = 0.0f;

#pragma unroll
        for (int kd = 0; kd < 4; kd++) {
#pragma unroll
            for (int g = 0; g < 2; g++) {
                uint32_t kh[4][2], kl[4][2];
#pragma unroll
                for (int j = 0; j < 4; j++) {
                    const int nf = g * 4 + j;
                    const uint32_t ro = (uint32_t)(nf * 8 * 144) + kd * 32 + bOff;
                    ldmx2(kh[j], sKH + ro);
                    ldmx2(kl[j], sKL + ro);
                }
#pragma unroll
                for (int j = 0; j < 4; j++) mma16816(s[g * 4 + j], qhF[kd], kh[j]);
#pragma unroll
                for (int j = 0; j < 4; j++) mma16816(s[g * 4 + j], qlF[kd], kh[j]);
#pragma unroll
                for (int j = 0; j < 4; j++) mma16816(s[g * 4 + j], qhF[kd], kl[j]);
            }
        }

        // ---- online softmax
        float mx0 = -1e30f, mx1 = -1e30f;
#pragma unroll
        for (int nf = 0; nf < 8; nf++) {
            mx0 = fmaxf(mx0, fmaxf(s[nf][0], s[nf][1]));
            mx1 = fmaxf(mx1, fmaxf(s[nf][2], s[nf][3]));
        }
        mx0 = fmaxf(mx0, __shfl_xor_sync(0xffffffffu, mx0, 1));
        mx0 = fmaxf(mx0, __shfl_xor_sync(0xffffffffu, mx0, 2));
        mx1 = fmaxf(mx1, __shfl_xor_sync(0xffffffffu, mx1, 1));
        mx1 = fmaxf(mx1, __shfl_xor_sync(0xffffffffu, mx1, 2));

        const float nm0 = fmaxf(m0, mx0), nm1 = fmaxf(m1, mx1);
        const float a0 = __expf(m0 - nm0), a1 = __expf(m1 - nm1);
        m0 = nm0; m1 = nm1;

        float ls0 = 0.0f, ls1 = 0.0f;
#pragma unroll
        for (int nf = 0; nf < 8; nf++) {
            s[nf][0] = __expf(s[nf][0] - m0);
            s[nf][1] = __expf(s[nf][1] - m0);
            s[nf][2] = __expf(s[nf][2] - m1);
            s[nf][3] = __expf(s[nf][3] - m1);
            ls0 += s[nf][0] + s[nf][1];
            ls1 += s[nf][2] + s[nf][3];
        }
        ls0 += __shfl_xor_sync(0xffffffffu, ls0, 1);
        ls0 += __shfl_xor_sync(0xffffffffu, ls0, 2);
        ls1 += __shfl_xor_sync(0xffffffffu, ls1, 1);
        ls1 += __shfl_xor_sync(0xffffffffu, ls1, 2);
        l0 = l0 * a0 + ls0;
        l1 = l1 * a1 + ls1;
#pragma unroll
        for (int nd = 0; nd < 8; nd++) {
            o[nd][0] *= a0; o[nd][1] *= a0;
            o[nd][2] *= a1; o[nd][3] *= a1;
        }

        // ---- O += P V  (term-grouped, RAW distance 4)
#pragma unroll
        for (int kd = 0; kd < 4; kd++) {
            uint32_t pah[4], pal[4];
#pragma unroll
            for (int half = 0; half < 2; half++) {
                const int nf = 2 * kd + half;
#pragma unroll
                for (int rr = 0; rr < 2; rr++) {
                    split_pack2(s[nf][rr * 2 + 0], s[nf][rr * 2 + 1],
                                pah[half * 2 + rr], pal[half * 2 + rr]);
                }
            }
#pragma unroll
            for (int g = 0; g < 2; g++) {
                uint32_t vh[4][2], vl[4][2];
#pragma unroll
                for (int j = 0; j < 4; j++) {
                    const int nd = g * 4 + j;
                    const uint32_t ro = (uint32_t)(kd * 16 * 144) + vOff + nd * 16;
                    ldmx2t(vh[j], sVH + ro);
                    ldmx2t(vl[j], sVL + ro);
                }
#pragma unroll
                for (int j = 0; j < 4; j++) mma16816(o[g * 4 + j], pah, vh[j]);
#pragma unroll
                for (int j = 0; j < 4; j++) mma16816(o[g * 4 + j], pal, vh[j]);
#pragma unroll
                for (int j = 0; j < 4; j++) mma16816(o[g * 4 + j], pah, vl[j]);
            }
        }
        __syncthreads();
    }

    // ---- epilogue: normalize, split to bf16 hi/lo, store
    const float inv0 = 1.0f / l0, inv1 = 1.0f / l1;
    const int gr0 = b * S + q0 + wid * 16 + (lane >> 2);
#pragma unroll
    for (int nd = 0; nd < 8; nd++) {
        const int cc = hc + nd * 8 + (lane & 3) * 2;
#pragma unroll
        for (int half = 0; half < 2; half++) {
            const int rr = gr0 + half * 8;
            const float inv = half ? inv1 : inv0;
            uint32_t hp, lp;
            split_pack2(o[nd][half * 2 + 0] * inv, o[nd][half * 2 + 1] * inv, hp, lp);
            *(uint32_t*)(Oh + (size_t)rr * DM + cc) = hp;
            *(uint32_t*)(Ol + (size_t)rr * DM + cc) = lp;
        }
    }
}

// ===========================================================================
// Launch
// ===========================================================================
extern "C" void kernel_launch(void* const* d_in, const int* in_sizes, int n_in,
                              void* d_out, int out_size)
{
    const float* x  = (const float*)d_in[0];
    const float* wq = (const float*)d_in[1];
    const float* bq = (const float*)d_in[2];
    const float* wk = (const float*)d_in[3];
    const float* bk = (const float*)d_in[4];
    const float* wv = (const float*)d_in[5];
    const float* bv = (const float*)d_in[6];
    const float* wo = (const float*)d_in[7];
    const float* bo = (const float*)d_in[8];
    float* out = (float*)d_out;

    __nv_bfloat16 *xh, *xl, *qh, *ql, *kh, *kl, *vh, *vl, *ah, *al, *wth, *wtl;
    cudaGetSymbolAddress((void**)&xh, g_xh);
    cudaGetSymbolAddress((void**)&xl, g_xl);
    cudaGetSymbolAddress((void**)&qh, g_qh);
    cudaGetSymbolAddress((void**)&ql, g_ql);
    cudaGetSymbolAddress((void**)&kh, g_kh);
    cudaGetSymbolAddress((void**)&kl, g_kl);
    cudaGetSymbolAddress((void**)&vh, g_vh);
    cudaGetSymbolAddress((void**)&vl, g_vl);
    cudaGetSymbolAddress((void**)&ah, g_ah);
    cudaGetSymbolAddress((void**)&al, g_al);
    cudaGetSymbolAddress((void**)&wth, g_wth);
    cudaGetSymbolAddress((void**)&wtl, g_wtl);

    cudaFuncSetAttribute(gemm_mma<true>,  cudaFuncAttributeMaxDynamicSharedMemorySize, SMG_TOTAL);
    cudaFuncSetAttribute(gemm_mma<false>, cudaFuncAttributeMaxDynamicSharedMemorySize, SMG_TOTAL);
    cudaFuncSetAttribute(attn_mma, cudaFuncAttributeMaxDynamicSharedMemorySize, SMA_TOTAL);

    const size_t WSZ = (size_t)DM * DM;

    // 1) operand prep
    split2_kernel<<<(MR * DM / 4 + 255) / 256, 256>>>(x, xh, xl, MR * DM / 4);
    dim3 gT(DM / 32, DM / 32, 4);
    tsplit_kernel<<<gT, dim3(32, 8)>>>(wq, wk, wv, wo, wth, wtl);

    // 2) fused QKV projections -> bf16 hi/lo (Q pre-scaled by 1/sqrt(DK))
    dim3 gQKV(DM / 128, MR / 128, 3);
    gemm_mma<true><<<gQKV, 256, SMG_TOTAL>>>(
        xh, xl, wth, wtl, bq, bk, bv,
        nullptr, qh, kh, vh, ql, kl, vl);

    // 3) attention (tensor cores) -> bf16 hi/lo
    dim3 gAttn(S / 128, H, B);   // (16, 16, 2)
    attn_mma<<<gAttn, 256, SMA_TOTAL>>>(qh, ql, kh, kl, vh, vl, ah, al);

    // 4) output projection -> fp32 out
    dim3 gO(DM / 128, MR / 128, 1);
    gemm_mma<false><<<gO, 256, SMG_TOTAL>>>(
        ah, al, wth + 3 * WSZ, wtl + 3 * WSZ, bo, bo, bo,
        out, nullptr, nullptr, nullptr, nullptr, nullptr, nullptr);
}

// round 11
// speedup vs baseline: 1.1044x; 1.0292x over previous
#include <cuda_runtime.h>
#include <cuda_bf16.h>
#include <cstdint>
#include <math.h>

// Problem constants
constexpr int B  = 2;
constexpr int S  = 2048;
constexpr int DM = 1024;   // d_model
constexpr int H  = 16;
constexpr int DK = 64;
constexpr int MR = B * S;  // 4096 rows

// ---------------------------------------------------------------------------
// Scratch (allocation-free: __device__ globals)
// ---------------------------------------------------------------------------
__device__ __nv_bfloat16 g_xh[MR * DM];
__device__ __nv_bfloat16 g_xl[MR * DM];
__device__ __nv_bfloat16 g_qh[MR * DM];
__device__ __nv_bfloat16 g_ql[MR * DM];
__device__ __nv_bfloat16 g_kh[MR * DM];
__device__ __nv_bfloat16 g_kl[MR * DM];
__device__ __nv_bfloat16 g_vh[MR * DM];
__device__ __nv_bfloat16 g_vl[MR * DM];
__device__ __nv_bfloat16 g_ah[MR * DM];
__device__ __nv_bfloat16 g_al[MR * DM];
__device__ __nv_bfloat16 g_wth[4 * DM * DM];  // transposed weights, hi part
__device__ __nv_bfloat16 g_wtl[4 * DM * DM];  // transposed weights, lo part

// ---------------------------------------------------------------------------
// mma.sync / ldmatrix / cp.async helpers (non-'a' PTX surface)
// ---------------------------------------------------------------------------
__device__ __forceinline__ uint32_t smem_u32(const void* p) {
    uint32_t a;
    asm("{ .reg .u64 t; cvta.to.shared.u64 t, %1; cvt.u32.u64 %0, t; }"
        : "=r"(a) : "l"(p));
    return a;
}

__device__ __forceinline__ void ldmx4(uint32_t* r, uint32_t addr) {
    asm volatile("ldmatrix.sync.aligned.m8n8.x4.shared.b16 {%0,%1,%2,%3}, [%4];"
                 : "=r"(r[0]), "=r"(r[1]), "=r"(r[2]), "=r"(r[3]) : "r"(addr));
}
__device__ __forceinline__ void ldmx4t(uint32_t* r, uint32_t addr) {
    asm volatile("ldmatrix.sync.aligned.m8n8.x4.trans.shared.b16 {%0,%1,%2,%3}, [%4];"
                 : "=r"(r[0]), "=r"(r[1]), "=r"(r[2]), "=r"(r[3]) : "r"(addr));
}
__device__ __forceinline__ void mma16816(float* c, const uint32_t* a, const uint32_t* b) {
    asm volatile(
        "mma.sync.aligned.m16n8k16.row.col.f32.bf16.bf16.f32 "
        "{%0,%1,%2,%3}, {%4,%5,%6,%7}, {%8,%9}, {%0,%1,%2,%3};"
        : "+f"(c[0]), "+f"(c[1]), "+f"(c[2]), "+f"(c[3])
        : "r"(a[0]), "r"(a[1]), "r"(a[2]), "r"(a[3]), "r"(b[0]), "r"(b[1]));
}
__device__ __forceinline__ void cp16(uint32_t saddr, const void* g) {
    asm volatile("cp.async.cg.shared.global [%0], [%1], 16;"
                 :: "r"(saddr), "l"(g));
}
__device__ __forceinline__ void cp_commit() {
    asm volatile("cp.async.commit_group;");
}
template <int N>
__device__ __forceinline__ void cp_wait() {
    asm volatile("cp.async.wait_group %0;" :: "n"(N));
}

// Split two fp32 into packed bf16 hi pair + bf16 lo (residual) pair.
__device__ __forceinline__ void split_pack2(float v0, float v1,
                                            uint32_t& hi, uint32_t& lo) {
    float2 f = {v0, v1};
    __nv_bfloat162 h = __float22bfloat162_rn(f);
    hi = *(uint32_t*)&h;
    float r0 = v0 - __uint_as_float(hi << 16);
    float r1 = v1 - __uint_as_float(hi & 0xffff0000u);
    float2 fr = {r0, r1};
    __nv_bfloat162 l = __float22bfloat162_rn(fr);
    lo = *(uint32_t*)&l;
}

// ---------------------------------------------------------------------------
// Split / transpose helpers
// ---------------------------------------------------------------------------
__global__ __launch_bounds__(256) void split2_kernel(
    const float* __restrict__ x, __nv_bfloat16* __restrict__ h,
    __nv_bfloat16* __restrict__ l, int n4)
{
    int i = blockIdx.x * blockDim.x + threadIdx.x;
    if (i >= n4) return;
    float4 v = ((const float4*)x)[i];
    uint32_t h0, l0, h1, l1;
    split_pack2(v.x, v.y, h0, l0);
    split_pack2(v.z, v.w, h1, l1);
    ((uint2*)h)[i] = make_uint2(h0, h1);
    ((uint2*)l)[i] = make_uint2(l0, l1);
}

// W [K,N] fp32 -> Wt hi/lo [N,K] bf16, 4 weights via blockIdx.z
__global__ __launch_bounds__(256) void tsplit_kernel(
    const float* __restrict__ W0, const float* __restrict__ W1,
    const float* __restrict__ W2, const float* __restrict__ W3,
    __nv_bfloat16* __restrict__ Th0, __nv_bfloat16* __restrict__ Tl0)
{
    __shared__ float t[32][33];
    const int z = blockIdx.z;
    const float* W = (z == 0) ? W0 : ((z == 1) ? W1 : ((z == 2) ? W2 : W3));
    __nv_bfloat16* Th = Th0 + (size_t)z * DM * DM;
    __nv_bfloat16* Tl = Tl0 + (size_t)z * DM * DM;
    const int n0 = blockIdx.x * 32, k0 = blockIdx.y * 32;
    const int tx = threadIdx.x, ty = threadIdx.y;  // 32 x 8
    for (int i = ty; i < 32; i += 8)
        t[i][tx] = W[(size_t)(k0 + i) * DM + n0 + tx];
    __syncthreads();
    for (int i = ty; i < 32; i += 8) {
        float v = t[tx][i];  // = W[k0+tx][n0+i]
        __nv_bfloat16 hi = __float2bfloat16(v);
        __nv_bfloat16 lo = __float2bfloat16(v - __bfloat162float(hi));
        Th[(size_t)(n0 + i) * DM + k0 + tx] = hi;
        Tl[(size_t)(n0 + i) * DM + k0 + tx] = lo;
    }
}

// ---------------------------------------------------------------------------
// mma.sync GEMM, 2-stage cp.async pipeline, BK=64, term-major MMA,
// ldmatrix.x4 pair-loads for the B operand.
// CTA 128x128 tile, 256 threads (8 warps 2x4), warp tile 64x32.
// ---------------------------------------------------------------------------
constexpr int GK = 64;
constexpr int GPAD = 72;
constexpr int GT_BYTES = 128 * GPAD * 2;          // 18432 per tile
constexpr int GSTAGE = 4 * GT_BYTES;              // 73728 per stage
constexpr int SMG_TOTAL = 2 * GSTAGE;             // 147456

template<bool SPLIT>
__global__ __launch_bounds__(256) void gemm_mma(
    const __nv_bfloat16* __restrict__ Ah, const __nv_bfloat16* __restrict__ Al,
    const __nv_bfloat16* __restrict__ Wh0, const __nv_bfloat16* __restrict__ Wl0,
    const float* __restrict__ b0, const float* __restrict__ b1,
    const float* __restrict__ b2,
    float* __restrict__ F0,
    __nv_bfloat16* __restrict__ H0, __nv_bfloat16* __restrict__ H1,
    __nv_bfloat16* __restrict__ H2,
    __nv_bfloat16* __restrict__ L0, __nv_bfloat16* __restrict__ L1,
    __nv_bfloat16* __restrict__ L2)
{
    extern __shared__ char smem[];
    const int z = blockIdx.z;
    const __nv_bfloat16* Wh = Wh0 + (size_t)z * DM * DM;
    const __nv_bfloat16* Wl = Wl0 + (size_t)z * DM * DM;
    const float* bias = (z == 0) ? b0 : ((z == 1) ? b1 : b2);

    const int tid  = threadIdx.x;
    const int wid  = tid >> 5, lane = tid & 31;
    const int mBase = blockIdx.y * 128, nBase = blockIdx.x * 128;

    const uint32_t sb = smem_u32(smem);

    const int wm = wid >> 2, wn = wid & 3;
    const int mrow0 = wm * 64, nrow0 = wn * 32;

    // A-operand x4 offset (bit3 -> +8 rows, bit4 -> +16B)
    const uint32_t aOff = (uint32_t)(((lane & 7) + ((lane >> 3) & 1) * 8) * 144
                                     + (lane >> 4) * 16);
    // B-operand pair x4 offset (bit4 -> +8 rows [second n-frag], bit3 -> +16B)
    const uint32_t bOff4 = (uint32_t)(((lane & 7) + ((lane >> 4) & 1) * 8) * 144
                                      + ((lane >> 3) & 1) * 16);

    const int frow = tid >> 3;           // 0..31
    const int fcol = (tid & 7) * 8;      // bf16 elems

    const __nv_bfloat16* gAh = Ah + (size_t)mBase * DM;
    const __nv_bfloat16* gAl = Al + (size_t)mBase * DM;
    const __nv_bfloat16* gBh = Wh + (size_t)nBase * DM;
    const __nv_bfloat16* gBl = Wl + (size_t)nBase * DM;

    auto issue = [&](int it, int st) {
        const int k0 = it * GK;
        const uint32_t s0 = sb + (uint32_t)st * GSTAGE;
#pragma unroll
        for (int p = 0; p < 4; p++) {
            const int row = p * 32 + frow;
            const size_t go = (size_t)row * DM + k0 + fcol;
            const uint32_t so = (uint32_t)(row * GPAD + fcol) * 2;
            cp16(s0 + 0 * GT_BYTES + so, gAh + go);
            cp16(s0 + 1 * GT_BYTES + so, gAl + go);
            cp16(s0 + 2 * GT_BYTES + so, gBh + go);
            cp16(s0 + 3 * GT_BYTES + so, gBl + go);
        }
        cp_commit();
    };

    float c[4][4][4];
#pragma unroll
    for (int i = 0; i < 4; i++)
#pragma unroll
        for (int j = 0; j < 4; j++)
#pragma unroll
            for (int e = 0; e < 4; e++) c[i][j][e] = 0.0f;

    constexpr int NIT = DM / GK;   // 16
    issue(0, 0);

    for (int it = 0; it < NIT; it++) {
        const int cur = it & 1;
        if (it + 1 < NIT) {
            issue(it + 1, cur ^ 1);
            cp_wait<1>();
        } else {
            cp_wait<0>();
        }
        __syncthreads();

        const uint32_t sAH = sb + (uint32_t)cur * GSTAGE;
        const uint32_t sAL = sAH + GT_BYTES;
        const uint32_t sBH = sAH + 2 * GT_BYTES;
        const uint32_t sBL = sAH + 3 * GT_BYTES;

#pragma unroll
        for (int ks = 0; ks < GK / 16; ks++) {
            const uint32_t kb = (uint32_t)(ks * 32);
            uint32_t ah[4][4], al[4][4], bh[4][2], bl[4][2];
#pragma unroll
            for (int mf = 0; mf < 4; mf++) {
                const uint32_t ro = (uint32_t)((mrow0 + mf * 16) * 144) + kb + aOff;
                ldmx4(ah[mf], sAH + ro);
                ldmx4(al[mf], sAL + ro);
            }
            // B pairs: one x4 loads frags (2p, 2p+1)
#pragma unroll
            for (int p = 0; p < 2; p++) {
                const uint32_t ro = (uint32_t)((nrow0 + p * 16) * 144) + kb + bOff4;
                ldmx4(&bh[2 * p][0], sBH + ro);
                ldmx4(&bl[2 * p][0], sBL + ro);
            }
            // term-major: 16 independent accumulators between same-c MMAs
#pragma unroll
            for (int mf = 0; mf < 4; mf++)
#pragma unroll
                for (int nf = 0; nf < 4; nf++)
                    mma16816(c[mf][nf], ah[mf], bh[nf]);
#pragma unroll
            for (int mf = 0; mf < 4; mf++)
#pragma unroll
                for (int nf = 0; nf < 4; nf++)
                    mma16816(c[mf][nf], al[mf], bh[nf]);
#pragma unroll
            for (int mf = 0; mf < 4; mf++)
#pragma unroll
                for (int nf = 0; nf < 4; nf++)
                    mma16816(c[mf][nf], ah[mf], bl[nf]);
        }
        __syncthreads();   // stage cur reusable at it+2's issue
    }

    const int crow = lane >> 2, ccol = (lane & 3) * 2;
    if (SPLIT) {
        __nv_bfloat16* Hd = (z == 0) ? H0 : ((z == 1) ? H1 : H2);
        __nv_bfloat16* Ld = (z == 0) ? L0 : ((z == 1) ? L1 : L2);
        const float scale = (z == 0) ? 0.125f : 1.0f;   // fold 1/sqrt(DK) into Q
#pragma unroll
        for (int mf = 0; mf < 4; mf++) {
#pragma unroll
            for (int nf = 0; nf < 4; nf++) {
                const int r  = mBase + mrow0 + mf * 16 + crow;
                const int cc = nBase + nrow0 + nf * 8 + ccol;
                const float bx = bias[cc], by = bias[cc + 1];
#pragma unroll
                for (int half = 0; half < 2; half++) {
                    const int rr = r + half * 8;
                    float v0 = (c[mf][nf][half * 2 + 0] + bx) * scale;
                    float v1 = (c[mf][nf][half * 2 + 1] + by) * scale;
                    uint32_t hp, lp;
                    split_pack2(v0, v1, hp, lp);
                    *(uint32_t*)(Hd + (size_t)rr * DM + cc) = hp;
                    *(uint32_t*)(Ld + (size_t)rr * DM + cc) = lp;
                }
            }
        }
    } else {
#pragma unroll
        for (int mf = 0; mf < 4; mf++) {
#pragma unroll
            for (int nf = 0; nf < 4; nf++) {
                const int r  = mBase + mrow0 + mf * 16 + crow;
                const int cc = nBase + nrow0 + nf * 8 + ccol;
                const float bx = bias[cc], by = bias[cc + 1];
                float2 v0 = { c[mf][nf][0] + bx, c[mf][nf][1] + by };
                float2 v1 = { c[mf][nf][2] + bx, c[mf][nf][3] + by };
                *(float2*)(F0 + (size_t)r * DM + cc)       = v0;
                *(float2*)(F0 + (size_t)(r + 8) * DM + cc) = v1;
            }
        }
    }
}

// ---------------------------------------------------------------------------
// Flash attention on tensor cores, 2-stage cp.async K/V pipeline, 2 CTAs/SM,
// ldmatrix.x4 pair-loads for K (non-trans) and V (trans).
// CTA: 128 q-rows for one (b,h); 8 warps x 16 rows. KV tiles of 64.
// smem: Qh,Ql [128][72]; 2 stages of {Kh,Kl,Vh,Vl}[64][72]
// ---------------------------------------------------------------------------
constexpr int AT_Q   = 0;
constexpr int AT_QL  = 128 * 144;                    // 18432
constexpr int AT_KV0 = 2 * 128 * 144;                // 36864
constexpr int KV_T   = 64 * 144;                     // 9216 per tile
constexpr int KV_STAGE = 4 * KV_T;                   // 36864 per stage
constexpr int SMA_TOTAL = AT_KV0 + 2 * KV_STAGE;     // 110592

__global__ __launch_bounds__(256, 2) void attn_mma(
    const __nv_bfloat16* __restrict__ Qh, const __nv_bfloat16* __restrict__ Ql,
    const __nv_bfloat16* __restrict__ Kh, const __nv_bfloat16* __restrict__ Kl,
    const __nv_bfloat16* __restrict__ Vh, const __nv_bfloat16* __restrict__ Vl,
    __nv_bfloat16* __restrict__ Oh, __nv_bfloat16* __restrict__ Ol)
{
    extern __shared__ char smem[];
    const uint32_t sb = smem_u32(smem);
    const int tid = threadIdx.x;
    const int wid = tid >> 5, lane = tid & 31;
    const int b = blockIdx.z, h = blockIdx.y;
    const int q0 = blockIdx.x * 128;
    const int hc = h * DK;

    const int frow = tid >> 2, fcb = (tid & 3) * 16;   // KV fill: 64 rows x 64 cols

    auto issueKV = [&](int kv0, int st) {
        const size_t go = (size_t)(b * S + kv0 + frow) * DM + hc + fcb;
        const uint32_t s0 = sb + AT_KV0 + (uint32_t)st * KV_STAGE;
        const uint32_t so = (uint32_t)(frow * 144 + fcb * 2);
#pragma unroll
        for (int u = 0; u < 2; u++) {
            cp16(s0 + 0 * KV_T + so + u * 16, Kh + go + u * 8);
            cp16(s0 + 1 * KV_T + so + u * 16, Kl + go + u * 8);
            cp16(s0 + 2 * KV_T + so + u * 16, Vh + go + u * 8);
            cp16(s0 + 3 * KV_T + so + u * 16, Vl + go + u * 8);
        }
        cp_commit();
    };

    // ---- fill Q tile (128 x 64 bf16, hi+lo)
    {
        const int row = tid >> 1, cb = (tid & 1) * 32;
        const size_t go = (size_t)(b * S + q0 + row) * DM + hc + cb;
        const uint32_t so = (uint32_t)(row * 144 + cb * 2);
#pragma unroll
        for (int u = 0; u < 4; u++) {
            *(uint4*)(smem + AT_Q  + so + u * 16) = *(const uint4*)(Qh + go + u * 8);
            *(uint4*)(smem + AT_QL + so + u * 16) = *(const uint4*)(Ql + go + u * 8);
        }
    }
    issueKV(0, 0);
    __syncthreads();

    // ---- preload Q fragments
    const uint32_t aOff = (uint32_t)(((lane & 7) + ((lane >> 3) & 1) * 8) * 144
                                     + (lane >> 4) * 16);
    // K pair x4: bit4 -> +8 rows (second n-frag), bit3 -> +16B (k half)
    const uint32_t bOff4 = (uint32_t)(((lane & 7) + ((lane >> 4) & 1) * 8) * 144
                                      + ((lane >> 3) & 1) * 16);
    // V pair x4 trans: lanes 0-15 rows k0-15 @nd0, lanes 16-31 same rows @nd1
    const uint32_t vOff4 = (uint32_t)((lane & 15) * 144 + (lane >> 4) * 16);

    uint32_t qhF[4][4], qlF[4][4];
#pragma unroll
    for (int kd = 0; kd < 4; kd++) {
        const uint32_t ro = (uint32_t)(wid * 16 * 144) + kd * 32 + aOff;
        ldmx4(qhF[kd], sb + AT_Q  + ro);
        ldmx4(qlF[kd], sb + AT_QL + ro);
    }

    float o[8][4];
#pragma unroll
    for (int nd = 0; nd < 8; nd++)
#pragma unroll
        for (int e = 0; e < 4; e++) o[nd][e] = 0.0f;
    float m0 = -1e30f, m1 = -1e30f, l0 = 0.0f, l1 = 0.0f;

    constexpr int NT = S / 64;   // 32
    for (int t = 0; t < NT; t++) {
        const int cur = t & 1;
        if (t + 1 < NT) {
            issueKV((t + 1) * 64, cur ^ 1);
            cp_wait<1>();
        } else {
            cp_wait<0>();
        }
        __syncthreads();

        const uint32_t sKH = sb + AT_KV0 + (uint32_t)cur * KV_STAGE;
        const uint32_t sKL = sKH + KV_T;
        const uint32_t sVH = sKH + 2 * KV_T;
        const uint32_t sVL = sKH + 3 * KV_T;

        // ---- S = Q K^T  (x4 pair loads, term-grouped)
        float s[8][4];
#pragma unroll
        for (int nf = 0; nf < 8; nf++)
#pragma unroll
            for (int e = 0; e < 4; e++) s[nf][e] = 0.0f;

#pragma unroll
        for (int kd = 0; kd < 4; kd++) {
#pragma unroll
            for (int g = 0; g < 2; g++) {
                uint32_t kh[4][2], kl[4][2];
#pragma unroll
                for (int p = 0; p < 2; p++) {
                    const int nf = g * 4 + p * 2;
                    const uint32_t ro = (uint32_t)(nf * 8 * 144) + kd * 32 + bOff4;
                    ldmx4(&kh[2 * p][0], sKH + ro);
                    ldmx4(&kl[2 * p][0], sKL + ro);
                }
#pragma unroll
                for (int j = 0; j < 4; j++) mma16816(s[g * 4 + j], qhF[kd], kh[j]);
#pragma unroll
                for (int j = 0; j < 4; j++) mma16816(s[g * 4 + j], qlF[kd], kh[j]);
#pragma unroll
                for (int j = 0; j < 4; j++) mma16816(s[g * 4 + j], qhF[kd], kl[j]);
            }
        }

        // ---- online softmax
        float mx0 = -1e30f, mx1 = -1e30f;
#pragma unroll
        for (int nf = 0; nf < 8; nf++) {
            mx0 = fmaxf(mx0, fmaxf(s[nf][0], s[nf][1]));
            mx1 = fmaxf(mx1, fmaxf(s[nf][2], s[nf][3]));
        }
        mx0 = fmaxf(mx0, __shfl_xor_sync(0xffffffffu, mx0, 1));
        mx0 = fmaxf(mx0, __shfl_xor_sync(0xffffffffu, mx0, 2));
        mx1 = fmaxf(mx1, __shfl_xor_sync(0xffffffffu, mx1, 1));
        mx1 = fmaxf(mx1, __shfl_xor_sync(0xffffffffu, mx1, 2));

        const float nm0 = fmaxf(m0, mx0), nm1 = fmaxf(m1, mx1);
        const float a0 = __expf(m0 - nm0), a1 = __expf(m1 - nm1);
        m0 = nm0; m1 = nm1;

        float ls0 = 0.0f, ls1 = 0.0f;
#pragma unroll
        for (int nf = 0; nf < 8; nf++) {
            s[nf][0] = __expf(s[nf][0] - m0);
            s[nf][1] = __expf(s[nf][1] - m0);
            s[nf][2] = __expf(s[nf][2] - m1);
            s[nf][3] = __expf(s[nf][3] - m1);
            ls0 += s[nf][0] + s[nf][1];
            ls1 += s[nf][2] + s[nf][3];
        }
        ls0 += __shfl_xor_sync(0xffffffffu, ls0, 1);
        ls0 += __shfl_xor_sync(0xffffffffu, ls0, 2);
        ls1 += __shfl_xor_sync(0xffffffffu, ls1, 1);
        ls1 += __shfl_xor_sync(0xffffffffu, ls1, 2);
        l0 = l0 * a0 + ls0;
        l1 = l1 * a1 + ls1;
#pragma unroll
        for (int nd = 0; nd < 8; nd++) {
            o[nd][0] *= a0; o[nd][1] *= a0;
            o[nd][2] *= a1; o[nd][3] *= a1;
        }

        // ---- O += P V  (x4 trans pair loads, term-grouped)
#pragma unroll
        for (int kd = 0; kd < 4; kd++) {
            uint32_t pah[4], pal[4];
#pragma unroll
            for (int half = 0; half < 2; half++) {
                const int nf = 2 * kd + half;
#pragma unroll
                for (int rr = 0; rr < 2; rr++) {
                    split_pack2(s[nf][rr * 2 + 0], s[nf][rr * 2 + 1],
                                pah[half * 2 + rr], pal[half * 2 + rr]);
                }
            }
#pragma unroll
            for (int g = 0; g < 2; g++) {
                uint32_t vh[4][2], vl[4][2];
#pragma unroll
                for (int p = 0; p < 2; p++) {
                    const int nd = g * 4 + p * 2;
                    const uint32_t ro = (uint32_t)(kd * 16 * 144) + nd * 16 + vOff4;
                    ldmx4t(&vh[2 * p][0], sVH + ro);
                    ldmx4t(&vl[2 * p][0], sVL + ro);
                }
#pragma unroll
                for (int j = 0; j < 4; j++) mma16816(o[g * 4 + j], pah, vh[j]);
#pragma unroll
                for (int j = 0; j < 4; j++) mma16816(o[g * 4 + j], pal, vh[j]);
#pragma unroll
                for (int j = 0; j < 4; j++) mma16816(o[g * 4 + j], pah, vl[j]);
            }
        }
        __syncthreads();
    }

    // ---- epilogue: normalize, split to bf16 hi/lo, store
    const float inv0 = 1.0f / l0, inv1 = 1.0f / l1;
    const int gr0 = b * S + q0 + wid * 16 + (lane >> 2);
#pragma unroll
    for (int nd = 0; nd < 8; nd++) {
        const int cc = hc + nd * 8 + (lane & 3) * 2;
#pragma unroll
        for (int half = 0; half < 2; half++) {
            const int rr = gr0 + half * 8;
            const float inv = half ? inv1 : inv0;
            uint32_t hp, lp;
            split_pack2(o[nd][half * 2 + 0] * inv, o[nd][half * 2 + 1] * inv, hp, lp);
            *(uint32_t*)(Oh + (size_t)rr * DM + cc) = hp;
            *(uint32_t*)(Ol + (size_t)rr * DM + cc) = lp;
        }
    }
}

// ===========================================================================
// Launch
// ===========================================================================
extern "C" void kernel_launch(void* const* d_in, const int* in_sizes, int n_in,
                              void* d_out, int out_size)
{
    const float* x  = (const float*)d_in[0];
    const float* wq = (const float*)d_in[1];
    const float* bq = (const float*)d_in[2];
    const float* wk = (const float*)d_in[3];
    const float* bk = (const float*)d_in[4];
    const float* wv = (const float*)d_in[5];
    const float* bv = (const float*)d_in[6];
    const float* wo = (const float*)d_in[7];
    const float* bo = (const float*)d_in[8];
    float* out = (float*)d_out;

    __nv_bfloat16 *xh, *xl, *qh, *ql, *kh, *kl, *vh, *vl, *ah, *al, *wth, *wtl;
    cudaGetSymbolAddress((void**)&xh, g_xh);
    cudaGetSymbolAddress((void**)&xl, g_xl);
    cudaGetSymbolAddress((void**)&qh, g_qh);
    cudaGetSymbolAddress((void**)&ql, g_ql);
    cudaGetSymbolAddress((void**)&kh, g_kh);
    cudaGetSymbolAddress((void**)&kl, g_kl);
    cudaGetSymbolAddress((void**)&vh, g_vh);
    cudaGetSymbolAddress((void**)&vl, g_vl);
    cudaGetSymbolAddress((void**)&ah, g_ah);
    cudaGetSymbolAddress((void**)&al, g_al);
    cudaGetSymbolAddress((void**)&wth, g_wth);
    cudaGetSymbolAddress((void**)&wtl, g_wtl);

    cudaFuncSetAttribute(gemm_mma<true>,  cudaFuncAttributeMaxDynamicSharedMemorySize, SMG_TOTAL);
    cudaFuncSetAttribute(gemm_mma<false>, cudaFuncAttributeMaxDynamicSharedMemorySize, SMG_TOTAL);
    cudaFuncSetAttribute(attn_mma, cudaFuncAttributeMaxDynamicSharedMemorySize, SMA_TOTAL);

    const size_t WSZ = (size_t)DM * DM;

    // 1) operand prep
    split2_kernel<<<(MR * DM / 4 + 255) / 256, 256>>>(x, xh, xl, MR * DM / 4);
    dim3 gT(DM / 32, DM / 32, 4);
    tsplit_kernel<<<gT, dim3(32, 8)>>>(wq, wk, wv, wo, wth, wtl);

    // 2) fused QKV projections -> bf16 hi/lo (Q pre-scaled by 1/sqrt(DK))
    dim3 gQKV(DM / 128, MR / 128, 3);
    gemm_mma<true><<<gQKV, 256, SMG_TOTAL>>>(
        xh, xl, wth, wtl, bq, bk, bv,
        nullptr, qh, kh, vh, ql, kl, vl);

    // 3) attention (tensor cores) -> bf16 hi/lo
    dim3 gAttn(S / 128, H, B);   // (16, 16, 2)
    attn_mma<<<gAttn, 256, SMA_TOTAL>>>(qh, ql, kh, kl, vh, vl, ah, al);

    // 4) output projection -> fp32 out
    dim3 gO(DM / 128, MR / 128, 1);
    gemm_mma<false><<<gO, 256, SMG_TOTAL>>>(
        ah, al, wth + 3 * WSZ, wtl + 3 * WSZ, bo, bo, bo,
        out, nullptr, nullptr, nullptr, nullptr, nullptr, nullptr);
}

// round 12
// speedup vs baseline: 1.4156x; 1.2818x over previous
#include <cuda_runtime.h>
#include <cuda_fp16.h>
#include <cstdint>
#include <math.h>

// Problem constants
constexpr int B  = 2;
constexpr int S  = 2048;
constexpr int DM = 1024;   // d_model
constexpr int H  = 16;
constexpr int DK = 64;
constexpr int MR = B * S;  // 4096 rows

// ---------------------------------------------------------------------------
// Scratch (allocation-free: __device__ globals)
// ---------------------------------------------------------------------------
__device__ __half g_xh[MR * DM];
__device__ __half g_xl[MR * DM];
__device__ __half g_qh[MR * DM];
__device__ __half g_ql[MR * DM];
__device__ __half g_kh[MR * DM];
__device__ __half g_vh[MR * DM];
__device__ __half g_ah[MR * DM];
__device__ __half g_al[MR * DM];
__device__ __half g_wt[4 * DM * DM];   // transposed weights, single fp16

// ---------------------------------------------------------------------------
// mma.sync / ldmatrix / cp.async helpers (non-'a' PTX surface)
// ---------------------------------------------------------------------------
__device__ __forceinline__ uint32_t smem_u32(const void* p) {
    uint32_t a;
    asm("{ .reg .u64 t; cvta.to.shared.u64 t, %1; cvt.u32.u64 %0, t; }"
        : "=r"(a) : "l"(p));
    return a;
}

__device__ __forceinline__ void ldmx4(uint32_t* r, uint32_t addr) {
    asm volatile("ldmatrix.sync.aligned.m8n8.x4.shared.b16 {%0,%1,%2,%3}, [%4];"
                 : "=r"(r[0]), "=r"(r[1]), "=r"(r[2]), "=r"(r[3]) : "r"(addr));
}
__device__ __forceinline__ void ldmx4t(uint32_t* r, uint32_t addr) {
    asm volatile("ldmatrix.sync.aligned.m8n8.x4.trans.shared.b16 {%0,%1,%2,%3}, [%4];"
                 : "=r"(r[0]), "=r"(r[1]), "=r"(r[2]), "=r"(r[3]) : "r"(addr));
}
__device__ __forceinline__ void mma16816(float* c, const uint32_t* a, const uint32_t* b) {
    asm volatile(
        "mma.sync.aligned.m16n8k16.row.col.f32.f16.f16.f32 "
        "{%0,%1,%2,%3}, {%4,%5,%6,%7}, {%8,%9}, {%0,%1,%2,%3};"
        : "+f"(c[0]), "+f"(c[1]), "+f"(c[2]), "+f"(c[3])
        : "r"(a[0]), "r"(a[1]), "r"(a[2]), "r"(a[3]), "r"(b[0]), "r"(b[1]));
}
__device__ __forceinline__ void cp16(uint32_t saddr, const void* g) {
    asm volatile("cp.async.cg.shared.global [%0], [%1], 16;"
                 :: "r"(saddr), "l"(g));
}
__device__ __forceinline__ void cp_commit() {
    asm volatile("cp.async.commit_group;");
}
template <int N>
__device__ __forceinline__ void cp_wait() {
    asm volatile("cp.async.wait_group %0;" :: "n"(N));
}

// fp16 pack / 2-word split helpers
__device__ __forceinline__ uint32_t pack_h2(float v0, float v1) {
    __half2 h = __floats2half2_rn(v0, v1);
    return *(uint32_t*)&h;
}
__device__ __forceinline__ void split_pack2h(float v0, float v1,
                                             uint32_t& hi, uint32_t& lo) {
    __half2 h = __floats2half2_rn(v0, v1);
    hi = *(uint32_t*)&h;
    float r0 = v0 - __half2float(__low2half(h));
    float r1 = v1 - __half2float(__high2half(h));
    __half2 l = __floats2half2_rn(r0, r1);
    lo = *(uint32_t*)&l;
}

// ---------------------------------------------------------------------------
// Split / transpose helpers
// ---------------------------------------------------------------------------
__global__ __launch_bounds__(256) void split2_kernel(
    const float* __restrict__ x, __half* __restrict__ h,
    __half* __restrict__ l, int n4)
{
    int i = blockIdx.x * blockDim.x + threadIdx.x;
    if (i >= n4) return;
    float4 v = ((const float4*)x)[i];
    uint32_t h0, l0, h1, l1;
    split_pack2h(v.x, v.y, h0, l0);
    split_pack2h(v.z, v.w, h1, l1);
    ((uint2*)h)[i] = make_uint2(h0, h1);
    ((uint2*)l)[i] = make_uint2(l0, l1);
}

// W [K,N] fp32 -> Wt [N,K] single fp16, 4 weights via blockIdx.z
__global__ __launch_bounds__(256) void tsplit_kernel(
    const float* __restrict__ W0, const float* __restrict__ W1,
    const float* __restrict__ W2, const float* __restrict__ W3,
    __half* __restrict__ T0)
{
    __shared__ float t[32][33];
    const int z = blockIdx.z;
    const float* W = (z == 0) ? W0 : ((z == 1) ? W1 : ((z == 2) ? W2 : W3));
    __half* Th = T0 + (size_t)z * DM * DM;
    const int n0 = blockIdx.x * 32, k0 = blockIdx.y * 32;
    const int tx = threadIdx.x, ty = threadIdx.y;  // 32 x 8
    for (int i = ty; i < 32; i += 8)
        t[i][tx] = W[(size_t)(k0 + i) * DM + n0 + tx];
    __syncthreads();
    for (int i = ty; i < 32; i += 8)
        Th[(size_t)(n0 + i) * DM + k0 + tx] = __float2half(t[tx][i]);
}

// ---------------------------------------------------------------------------
// fp16 2-term GEMM, 2-stage cp.async pipeline, BK=64, 2 CTAs/SM.
// C[M,N] = (Ah+Al)[M,K] @ Wt^T + bias.  Wt is single fp16.
// CTA 128x128 tile, 256 threads (8 warps 2x4), warp tile 64x32.
// Epilogue: z=0 -> Q hi/lo fp16 (scaled 0.125); z=1 -> K fp16; z=2 -> V fp16.
// SPLIT=false -> fp32 out.
// ---------------------------------------------------------------------------
constexpr int GK = 64;
constexpr int GT_BYTES = 128 * 144;               // 18432 per tile (64h data + pad)
constexpr int GSTAGE = 3 * GT_BYTES;              // 55296 per stage (Ah, Al, B)
constexpr int SMG_TOTAL = 2 * GSTAGE;             // 110592

template<bool SPLIT>
__global__ __launch_bounds__(256, 2) void gemm_mma(
    const __half* __restrict__ Ah, const __half* __restrict__ Al,
    const __half* __restrict__ Wt0,
    const float* __restrict__ b0, const float* __restrict__ b1,
    const float* __restrict__ b2,
    float* __restrict__ F0,
    __half* __restrict__ Qh, __half* __restrict__ Ql,
    __half* __restrict__ Kd, __half* __restrict__ Vd)
{
    extern __shared__ char smem[];
    const int z = blockIdx.z;
    const __half* Wt = Wt0 + (size_t)z * DM * DM;
    const float* bias = (z == 0) ? b0 : ((z == 1) ? b1 : b2);

    const int tid  = threadIdx.x;
    const int wid  = tid >> 5, lane = tid & 31;
    const int mBase = blockIdx.y * 128, nBase = blockIdx.x * 128;

    const uint32_t sb = smem_u32(smem);

    const int wm = wid >> 2, wn = wid & 3;
    const int mrow0 = wm * 64, nrow0 = wn * 32;

    const uint32_t aOff = (uint32_t)(((lane & 7) + ((lane >> 3) & 1) * 8) * 144
                                     + (lane >> 4) * 16);
    const uint32_t bOff4 = (uint32_t)(((lane & 7) + ((lane >> 4) & 1) * 8) * 144
                                      + ((lane >> 3) & 1) * 16);

    const int frow = tid >> 1;           // 0..127
    const int fch  = (tid & 1) * 32;     // half-elems within 64-wide k chunk

    const __half* gAh = Ah + (size_t)mBase * DM;
    const __half* gAl = Al + (size_t)mBase * DM;
    const __half* gB  = Wt + (size_t)nBase * DM;

    auto issue = [&](int it, int st) {
        const int k0 = it * GK;
        const uint32_t s0 = sb + (uint32_t)st * GSTAGE;
        const size_t go = (size_t)frow * DM + k0 + fch;
        const uint32_t so = (uint32_t)(frow * 144 + fch * 2);
#pragma unroll
        for (int u = 0; u < 4; u++) {
            cp16(s0 + 0 * GT_BYTES + so + u * 16, gAh + go + u * 8);
            cp16(s0 + 1 * GT_BYTES + so + u * 16, gAl + go + u * 8);
            cp16(s0 + 2 * GT_BYTES + so + u * 16, gB  + go + u * 8);
        }
        cp_commit();
    };

    float c[4][4][4];
#pragma unroll
    for (int i = 0; i < 4; i++)
#pragma unroll
        for (int j = 0; j < 4; j++)
#pragma unroll
            for (int e = 0; e < 4; e++) c[i][j][e] = 0.0f;

    constexpr int NIT = DM / GK;   // 16
    issue(0, 0);

    for (int it = 0; it < NIT; it++) {
        const int cur = it & 1;
        if (it + 1 < NIT) {
            issue(it + 1, cur ^ 1);
            cp_wait<1>();
        } else {
            cp_wait<0>();
        }
        __syncthreads();

        const uint32_t sAH = sb + (uint32_t)cur * GSTAGE;
        const uint32_t sAL = sAH + GT_BYTES;
        const uint32_t sB  = sAH + 2 * GT_BYTES;

#pragma unroll
        for (int ks = 0; ks < GK / 16; ks++) {
            const uint32_t kb = (uint32_t)(ks * 32);
            uint32_t ah[4][4], al[4][4], bf[4][2];
#pragma unroll
            for (int mf = 0; mf < 4; mf++) {
                const uint32_t ro = (uint32_t)((mrow0 + mf * 16) * 144) + kb + aOff;
                ldmx4(ah[mf], sAH + ro);
                ldmx4(al[mf], sAL + ro);
            }
#pragma unroll
            for (int p = 0; p < 2; p++) {
                const uint32_t ro = (uint32_t)((nrow0 + p * 16) * 144) + kb + bOff4;
                ldmx4(&bf[2 * p][0], sB + ro);
            }
            // term-major, 16 independent accumulators per term pass
#pragma unroll
            for (int mf = 0; mf < 4; mf++)
#pragma unroll
                for (int nf = 0; nf < 4; nf++)
                    mma16816(c[mf][nf], ah[mf], bf[nf]);
#pragma unroll
            for (int mf = 0; mf < 4; mf++)
#pragma unroll
                for (int nf = 0; nf < 4; nf++)
                    mma16816(c[mf][nf], al[mf], bf[nf]);
        }
        __syncthreads();
    }

    const int crow = lane >> 2, ccol = (lane & 3) * 2;
    if (SPLIT) {
#pragma unroll
        for (int mf = 0; mf < 4; mf++) {
#pragma unroll
            for (int nf = 0; nf < 4; nf++) {
                const int r  = mBase + mrow0 + mf * 16 + crow;
                const int cc = nBase + nrow0 + nf * 8 + ccol;
                const float bx = bias[cc], by = bias[cc + 1];
#pragma unroll
                for (int half = 0; half < 2; half++) {
                    const int rr = r + half * 8;
                    float v0 = c[mf][nf][half * 2 + 0] + bx;
                    float v1 = c[mf][nf][half * 2 + 1] + by;
                    if (z == 0) {
                        uint32_t hp, lp;
                        split_pack2h(v0 * 0.125f, v1 * 0.125f, hp, lp);
                        *(uint32_t*)(Qh + (size_t)rr * DM + cc) = hp;
                        *(uint32_t*)(Ql + (size_t)rr * DM + cc) = lp;
                    } else if (z == 1) {
                        *(uint32_t*)(Kd + (size_t)rr * DM + cc) = pack_h2(v0, v1);
                    } else {
                        *(uint32_t*)(Vd + (size_t)rr * DM + cc) = pack_h2(v0, v1);
                    }
                }
            }
        }
    } else {
#pragma unroll
        for (int mf = 0; mf < 4; mf++) {
#pragma unroll
            for (int nf = 0; nf < 4; nf++) {
                const int r  = mBase + mrow0 + mf * 16 + crow;
                const int cc = nBase + nrow0 + nf * 8 + ccol;
                const float bx = bias[cc], by = bias[cc + 1];
                float2 v0 = { c[mf][nf][0] + bx, c[mf][nf][1] + by };
                float2 v1 = { c[mf][nf][2] + bx, c[mf][nf][3] + by };
                *(float2*)(F0 + (size_t)r * DM + cc)       = v0;
                *(float2*)(F0 + (size_t)(r + 8) * DM + cc) = v1;
            }
        }
    }
}

// ---------------------------------------------------------------------------
// Flash attention, fp16 2-term (Q/P split, K/V single), 2-stage cp.async,
// 2 CTAs/SM. CTA: 128 q-rows for one (b,h); 8 warps x 16 rows; KV tiles of 64.
// smem: Qh,Ql [128][72h]; 2 stages of {K, V}[64][72h]  (72h = 144B rows)
// ---------------------------------------------------------------------------
constexpr int AT_Q   = 0;
constexpr int AT_QL  = 128 * 144;                    // 18432
constexpr int AT_KV0 = 2 * 128 * 144;                // 36864
constexpr int KV_T   = 64 * 144;                     // 9216 per tile
constexpr int KV_STAGE = 2 * KV_T;                   // 18432 per stage
constexpr int SMA_TOTAL = AT_KV0 + 2 * KV_STAGE;     // 73728

__global__ __launch_bounds__(256, 2) void attn_mma(
    const __half* __restrict__ Qh, const __half* __restrict__ Ql,
    const __half* __restrict__ Kd, const __half* __restrict__ Vd,
    __half* __restrict__ Oh, __half* __restrict__ Ol)
{
    extern __shared__ char smem[];
    const uint32_t sb = smem_u32(smem);
    const int tid = threadIdx.x;
    const int wid = tid >> 5, lane = tid & 31;
    const int b = blockIdx.z, h = blockIdx.y;
    const int q0 = blockIdx.x * 128;
    const int hc = h * DK;

    const int frow = tid >> 2, fch = (tid & 3) * 16;   // KV fill: 64 rows, 16h each

    auto issueKV = [&](int kv0, int st) {
        const size_t go = (size_t)(b * S + kv0 + frow) * DM + hc + fch;
        const uint32_t s0 = sb + AT_KV0 + (uint32_t)st * KV_STAGE;
        const uint32_t so = (uint32_t)(frow * 144 + fch * 2);
#pragma unroll
        for (int u = 0; u < 2; u++) {
            cp16(s0 + 0 * KV_T + so + u * 16, Kd + go + u * 8);
            cp16(s0 + 1 * KV_T + so + u * 16, Vd + go + u * 8);
        }
        cp_commit();
    };

    // ---- fill Q tile (128 x 64 fp16, hi+lo)
    {
        const int row = tid >> 1, cb = (tid & 1) * 32;
        const size_t go = (size_t)(b * S + q0 + row) * DM + hc + cb;
        const uint32_t so = (uint32_t)(row * 144 + cb * 2);
#pragma unroll
        for (int u = 0; u < 4; u++) {
            *(uint4*)(smem + AT_Q  + so + u * 16) = *(const uint4*)(Qh + go + u * 8);
            *(uint4*)(smem + AT_QL + so + u * 16) = *(const uint4*)(Ql + go + u * 8);
        }
    }
    issueKV(0, 0);
    __syncthreads();

    // ---- preload Q fragments
    const uint32_t aOff = (uint32_t)(((lane & 7) + ((lane >> 3) & 1) * 8) * 144
                                     + (lane >> 4) * 16);
    const uint32_t bOff4 = (uint32_t)(((lane & 7) + ((lane >> 4) & 1) * 8) * 144
                                      + ((lane >> 3) & 1) * 16);
    const uint32_t vOff4 = (uint32_t)((lane & 15) * 144 + (lane >> 4) * 16);

    uint32_t qhF[4][4], qlF[4][4];
#pragma unroll
    for (int kd = 0; kd < 4; kd++) {
        const uint32_t ro = (uint32_t)(wid * 16 * 144) + kd * 32 + aOff;
        ldmx4(qhF[kd], sb + AT_Q  + ro);
        ldmx4(qlF[kd], sb + AT_QL + ro);
    }

    float o[8][4];
#pragma unroll
    for (int nd = 0; nd < 8; nd++)
#pragma unroll
        for (int e = 0; e < 4; e++) o[nd][e] = 0.0f;
    float m0 = -1e30f, m1 = -1e30f, l0 = 0.0f, l1 = 0.0f;

    constexpr int NT = S / 64;   // 32
    for (int t = 0; t < NT; t++) {
        const int cur = t & 1;
        if (t + 1 < NT) {
            issueKV((t + 1) * 64, cur ^ 1);
            cp_wait<1>();
        } else {
            cp_wait<0>();
        }
        __syncthreads();

        const uint32_t sK = sb + AT_KV0 + (uint32_t)cur * KV_STAGE;
        const uint32_t sV = sK + KV_T;

        // ---- S = Q K^T  (2 terms: qh*k, ql*k)
        float s[8][4];
#pragma unroll
        for (int nf = 0; nf < 8; nf++)
#pragma unroll
            for (int e = 0; e < 4; e++) s[nf][e] = 0.0f;

#pragma unroll
        for (int kd = 0; kd < 4; kd++) {
#pragma unroll
            for (int g = 0; g < 2; g++) {
                uint32_t kf[4][2];
#pragma unroll
                for (int p = 0; p < 2; p++) {
                    const int nf = g * 4 + p * 2;
                    const uint32_t ro = (uint32_t)(nf * 8 * 144) + kd * 32 + bOff4;
                    ldmx4(&kf[2 * p][0], sK + ro);
                }
#pragma unroll
                for (int j = 0; j < 4; j++) mma16816(s[g * 4 + j], qhF[kd], kf[j]);
#pragma unroll
                for (int j = 0; j < 4; j++) mma16816(s[g * 4 + j], qlF[kd], kf[j]);
            }
        }

        // ---- online softmax
        float mx0 = -1e30f, mx1 = -1e30f;
#pragma unroll
        for (int nf = 0; nf < 8; nf++) {
            mx0 = fmaxf(mx0, fmaxf(s[nf][0], s[nf][1]));
            mx1 = fmaxf(mx1, fmaxf(s[nf][2], s[nf][3]));
        }
        mx0 = fmaxf(mx0, __shfl_xor_sync(0xffffffffu, mx0, 1));
        mx0 = fmaxf(mx0, __shfl_xor_sync(0xffffffffu, mx0, 2));
        mx1 = fmaxf(mx1, __shfl_xor_sync(0xffffffffu, mx1, 1));
        mx1 = fmaxf(mx1, __shfl_xor_sync(0xffffffffu, mx1, 2));

        const float nm0 = fmaxf(m0, mx0), nm1 = fmaxf(m1, mx1);
        const float a0 = __expf(m0 - nm0), a1 = __expf(m1 - nm1);
        m0 = nm0; m1 = nm1;

        float ls0 = 0.0f, ls1 = 0.0f;
#pragma unroll
        for (int nf = 0; nf < 8; nf++) {
            s[nf][0] = __expf(s[nf][0] - m0);
            s[nf][1] = __expf(s[nf][1] - m0);
            s[nf][2] = __expf(s[nf][2] - m1);
            s[nf][3] = __expf(s[nf][3] - m1);
            ls0 += s[nf][0] + s[nf][1];
            ls1 += s[nf][2] + s[nf][3];
        }
        ls0 += __shfl_xor_sync(0xffffffffu, ls0, 1);
        ls0 += __shfl_xor_sync(0xffffffffu, ls0, 2);
        ls1 += __shfl_xor_sync(0xffffffffu, ls1, 1);
        ls1 += __shfl_xor_sync(0xffffffffu, ls1, 2);
        l0 = l0 * a0 + ls0;
        l1 = l1 * a1 + ls1;
#pragma unroll
        for (int nd = 0; nd < 8; nd++) {
            o[nd][0] *= a0; o[nd][1] *= a0;
            o[nd][2] *= a1; o[nd][3] *= a1;
        }

        // ---- O += P V  (2 terms: ph*v, pl*v)
#pragma unroll
        for (int kd = 0; kd < 4; kd++) {
            uint32_t pah[4], pal[4];
#pragma unroll
            for (int half = 0; half < 2; half++) {
                const int nf = 2 * kd + half;
#pragma unroll
                for (int rr = 0; rr < 2; rr++) {
                    split_pack2h(s[nf][rr * 2 + 0], s[nf][rr * 2 + 1],
                                 pah[half * 2 + rr], pal[half * 2 + rr]);
                }
            }
#pragma unroll
            for (int g = 0; g < 2; g++) {
                uint32_t vf[4][2];
#pragma unroll
                for (int p = 0; p < 2; p++) {
                    const int nd = g * 4 + p * 2;
                    const uint32_t ro = (uint32_t)(kd * 16 * 144) + nd * 16 + vOff4;
                    ldmx4t(&vf[2 * p][0], sV + ro);
                }
#pragma unroll
                for (int j = 0; j < 4; j++) mma16816(o[g * 4 + j], pah, vf[j]);
#pragma unroll
                for (int j = 0; j < 4; j++) mma16816(o[g * 4 + j], pal, vf[j]);
            }
        }
        __syncthreads();
    }

    // ---- epilogue: normalize, split to fp16 hi/lo, store
    const float inv0 = 1.0f / l0, inv1 = 1.0f / l1;
    const int gr0 = b * S + q0 + wid * 16 + (lane >> 2);
#pragma unroll
    for (int nd = 0; nd < 8; nd++) {
        const int cc = hc + nd * 8 + (lane & 3) * 2;
#pragma unroll
        for (int half = 0; half < 2; half++) {
            const int rr = gr0 + half * 8;
            const float inv = half ? inv1 : inv0;
            uint32_t hp, lp;
            split_pack2h(o[nd][half * 2 + 0] * inv, o[nd][half * 2 + 1] * inv, hp, lp);
            *(uint32_t*)(Oh + (size_t)rr * DM + cc) = hp;
            *(uint32_t*)(Ol + (size_t)rr * DM + cc) = lp;
        }
    }
}

// ===========================================================================
// Launch
// ===========================================================================
extern "C" void kernel_launch(void* const* d_in, const int* in_sizes, int n_in,
                              void* d_out, int out_size)
{
    const float* x  = (const float*)d_in[0];
    const float* wq = (const float*)d_in[1];
    const float* bq = (const float*)d_in[2];
    const float* wk = (const float*)d_in[3];
    const float* bk = (const float*)d_in[4];
    const float* wv = (const float*)d_in[5];
    const float* bv = (const float*)d_in[6];
    const float* wo = (const float*)d_in[7];
    const float* bo = (const float*)d_in[8];
    float* out = (float*)d_out;

    __half *xh, *xl, *qh, *ql, *kh, *vh, *ah, *al, *wt;
    cudaGetSymbolAddress((void**)&xh, g_xh);
    cudaGetSymbolAddress((void**)&xl, g_xl);
    cudaGetSymbolAddress((void**)&qh, g_qh);
    cudaGetSymbolAddress((void**)&ql, g_ql);
    cudaGetSymbolAddress((void**)&kh, g_kh);
    cudaGetSymbolAddress((void**)&vh, g_vh);
    cudaGetSymbolAddress((void**)&ah, g_ah);
    cudaGetSymbolAddress((void**)&al, g_al);
    cudaGetSymbolAddress((void**)&wt, g_wt);

    cudaFuncSetAttribute(gemm_mma<true>,  cudaFuncAttributeMaxDynamicSharedMemorySize, SMG_TOTAL);
    cudaFuncSetAttribute(gemm_mma<false>, cudaFuncAttributeMaxDynamicSharedMemorySize, SMG_TOTAL);
    cudaFuncSetAttribute(attn_mma, cudaFuncAttributeMaxDynamicSharedMemorySize, SMA_TOTAL);

    const size_t WSZ = (size_t)DM * DM;

    // 1) operand prep
    split2_kernel<<<(MR * DM / 4 + 255) / 256, 256>>>(x, xh, xl, MR * DM / 4);
    dim3 gT(DM / 32, DM / 32, 4);
    tsplit_kernel<<<gT, dim3(32, 8)>>>(wq, wk, wv, wo, wt);

    // 2) fused QKV projections (Q split+scaled; K,V single fp16)
    dim3 gQKV(DM / 128, MR / 128, 3);
    gemm_mma<true><<<gQKV, 256, SMG_TOTAL>>>(
        xh, xl, wt, bq, bk, bv,
        nullptr, qh, ql, kh, vh);

    // 3) attention (fp16 tensor cores) -> fp16 hi/lo
    dim3 gAttn(S / 128, H, B);   // (16, 16, 2)
    attn_mma<<<gAttn, 256, SMA_TOTAL>>>(qh, ql, kh, vh, ah, al);

    // 4) output projection -> fp32 out
    dim3 gO(DM / 128, MR / 128, 1);
    gemm_mma<false><<<gO, 256, SMG_TOTAL>>>(
        ah, al, wt + 3 * WSZ, bo, bo, bo,
        out, nullptr, nullptr, nullptr, nullptr);
}

// round 13
// speedup vs baseline: 1.5460x; 1.0921x over previous
#include <cuda_runtime.h>
#include <cuda_fp16.h>
#include <cstdint>
#include <math.h>

// Problem constants
constexpr int B  = 2;
constexpr int S  = 2048;
constexpr int DM = 1024;   // d_model
constexpr int H  = 16;
constexpr int DK = 64;
constexpr int MR = B * S;  // 4096 rows

// ---------------------------------------------------------------------------
// Scratch (allocation-free: __device__ globals)
// ---------------------------------------------------------------------------
__device__ __half g_xh[MR * DM];
__device__ __half g_xl[MR * DM];
__device__ __half g_qh[MR * DM];
__device__ __half g_ql[MR * DM];
__device__ __half g_kh[MR * DM];
__device__ __half g_vh[MR * DM];
__device__ __half g_ah[MR * DM];
__device__ __half g_al[MR * DM];
__device__ __half g_wt[4 * DM * DM];   // transposed weights, single fp16

// ---------------------------------------------------------------------------
// mma.sync / ldmatrix / cp.async helpers (non-'a' PTX surface)
// ---------------------------------------------------------------------------
__device__ __forceinline__ uint32_t smem_u32(const void* p) {
    uint32_t a;
    asm("{ .reg .u64 t; cvta.to.shared.u64 t, %1; cvt.u32.u64 %0, t; }"
        : "=r"(a) : "l"(p));
    return a;
}

__device__ __forceinline__ void ldmx4(uint32_t* r, uint32_t addr) {
    asm volatile("ldmatrix.sync.aligned.m8n8.x4.shared.b16 {%0,%1,%2,%3}, [%4];"
                 : "=r"(r[0]), "=r"(r[1]), "=r"(r[2]), "=r"(r[3]) : "r"(addr));
}
__device__ __forceinline__ void ldmx4t(uint32_t* r, uint32_t addr) {
    asm volatile("ldmatrix.sync.aligned.m8n8.x4.trans.shared.b16 {%0,%1,%2,%3}, [%4];"
                 : "=r"(r[0]), "=r"(r[1]), "=r"(r[2]), "=r"(r[3]) : "r"(addr));
}
__device__ __forceinline__ void mma16816(float* c, const uint32_t* a, const uint32_t* b) {
    asm volatile(
        "mma.sync.aligned.m16n8k16.row.col.f32.f16.f16.f32 "
        "{%0,%1,%2,%3}, {%4,%5,%6,%7}, {%8,%9}, {%0,%1,%2,%3};"
        : "+f"(c[0]), "+f"(c[1]), "+f"(c[2]), "+f"(c[3])
        : "r"(a[0]), "r"(a[1]), "r"(a[2]), "r"(a[3]), "r"(b[0]), "r"(b[1]));
}
__device__ __forceinline__ void cp16(uint32_t saddr, const void* g) {
    asm volatile("cp.async.cg.shared.global [%0], [%1], 16;"
                 :: "r"(saddr), "l"(g));
}
__device__ __forceinline__ void cp_commit() {
    asm volatile("cp.async.commit_group;");
}
template <int N>
__device__ __forceinline__ void cp_wait() {
    asm volatile("cp.async.wait_group %0;" :: "n"(N));
}

// fp16 pack / 2-word split helpers
__device__ __forceinline__ uint32_t pack_h2(float v0, float v1) {
    __half2 h = __floats2half2_rn(v0, v1);
    return *(uint32_t*)&h;
}
__device__ __forceinline__ void split_pack2h(float v0, float v1,
                                             uint32_t& hi, uint32_t& lo) {
    __half2 h = __floats2half2_rn(v0, v1);
    hi = *(uint32_t*)&h;
    float r0 = v0 - __half2float(__low2half(h));
    float r1 = v1 - __half2float(__high2half(h));
    __half2 l = __floats2half2_rn(r0, r1);
    lo = *(uint32_t*)&l;
}

// ---------------------------------------------------------------------------
// Split / transpose helpers
// ---------------------------------------------------------------------------
__global__ __launch_bounds__(256) void split2_kernel(
    const float* __restrict__ x, __half* __restrict__ h,
    __half* __restrict__ l, int n4)
{
    int i = blockIdx.x * blockDim.x + threadIdx.x;
    if (i >= n4) return;
    float4 v = ((const float4*)x)[i];
    uint32_t h0, l0, h1, l1;
    split_pack2h(v.x, v.y, h0, l0);
    split_pack2h(v.z, v.w, h1, l1);
    ((uint2*)h)[i] = make_uint2(h0, h1);
    ((uint2*)l)[i] = make_uint2(l0, l1);
}

// W [K,N] fp32 -> Wt [N,K] single fp16, 4 weights via blockIdx.z
__global__ __launch_bounds__(256) void tsplit_kernel(
    const float* __restrict__ W0, const float* __restrict__ W1,
    const float* __restrict__ W2, const float* __restrict__ W3,
    __half* __restrict__ T0)
{
    __shared__ float t[32][33];
    const int z = blockIdx.z;
    const float* W = (z == 0) ? W0 : ((z == 1) ? W1 : ((z == 2) ? W2 : W3));
    __half* Th = T0 + (size_t)z * DM * DM;
    const int n0 = blockIdx.x * 32, k0 = blockIdx.y * 32;
    const int tx = threadIdx.x, ty = threadIdx.y;  // 32 x 8
    for (int i = ty; i < 32; i += 8)
        t[i][tx] = W[(size_t)(k0 + i) * DM + n0 + tx];
    __syncthreads();
    for (int i = ty; i < 32; i += 8)
        Th[(size_t)(n0 + i) * DM + k0 + tx] = __float2half(t[tx][i]);
}

// ---------------------------------------------------------------------------
// fp16 2-term GEMM, 2-stage cp.async pipeline, BK=64, 2 CTAs/SM.
// C[M,N] = (Ah+Al)[M,K] @ Wt^T + bias.  Wt is single fp16.
// CTA 128x128 tile, 256 threads (8 warps 2x4), warp tile 64x32.
// Epilogue: z=0 -> Q hi/lo fp16 (scaled 0.125); z=1 -> K fp16; z=2 -> V fp16.
// SPLIT=false -> fp32 out.
// ---------------------------------------------------------------------------
constexpr int GK = 64;
constexpr int GT_BYTES = 128 * 144;               // 18432 per tile (64h data + pad)
constexpr int GSTAGE = 3 * GT_BYTES;              // 55296 per stage (Ah, Al, B)
constexpr int SMG_TOTAL = 2 * GSTAGE;             // 110592

template<bool SPLIT>
__global__ __launch_bounds__(256, 2) void gemm_mma(
    const __half* __restrict__ Ah, const __half* __restrict__ Al,
    const __half* __restrict__ Wt0,
    const float* __restrict__ b0, const float* __restrict__ b1,
    const float* __restrict__ b2,
    float* __restrict__ F0,
    __half* __restrict__ Qh, __half* __restrict__ Ql,
    __half* __restrict__ Kd, __half* __restrict__ Vd)
{
    extern __shared__ char smem[];
    const int z = blockIdx.z;
    const __half* Wt = Wt0 + (size_t)z * DM * DM;
    const float* bias = (z == 0) ? b0 : ((z == 1) ? b1 : b2);

    const int tid  = threadIdx.x;
    const int wid  = tid >> 5, lane = tid & 31;
    const int mBase = blockIdx.y * 128, nBase = blockIdx.x * 128;

    const uint32_t sb = smem_u32(smem);

    const int wm = wid >> 2, wn = wid & 3;
    const int mrow0 = wm * 64, nrow0 = wn * 32;

    const uint32_t aOff = (uint32_t)(((lane & 7) + ((lane >> 3) & 1) * 8) * 144
                                     + (lane >> 4) * 16);
    const uint32_t bOff4 = (uint32_t)(((lane & 7) + ((lane >> 4) & 1) * 8) * 144
                                      + ((lane >> 3) & 1) * 16);

    const int frow = tid >> 1;           // 0..127
    const int fch  = (tid & 1) * 32;     // half-elems within 64-wide k chunk

    const __half* gAh = Ah + (size_t)mBase * DM;
    const __half* gAl = Al + (size_t)mBase * DM;
    const __half* gB  = Wt + (size_t)nBase * DM;

    auto issue = [&](int it, int st) {
        const int k0 = it * GK;
        const uint32_t s0 = sb + (uint32_t)st * GSTAGE;
        const size_t go = (size_t)frow * DM + k0 + fch;
        const uint32_t so = (uint32_t)(frow * 144 + fch * 2);
#pragma unroll
        for (int u = 0; u < 4; u++) {
            cp16(s0 + 0 * GT_BYTES + so + u * 16, gAh + go + u * 8);
            cp16(s0 + 1 * GT_BYTES + so + u * 16, gAl + go + u * 8);
            cp16(s0 + 2 * GT_BYTES + so + u * 16, gB  + go + u * 8);
        }
        cp_commit();
    };

    float c[4][4][4];
#pragma unroll
    for (int i = 0; i < 4; i++)
#pragma unroll
        for (int j = 0; j < 4; j++)
#pragma unroll
            for (int e = 0; e < 4; e++) c[i][j][e] = 0.0f;

    constexpr int NIT = DM / GK;   // 16
    issue(0, 0);

    for (int it = 0; it < NIT; it++) {
        const int cur = it & 1;
        if (it + 1 < NIT) {
            issue(it + 1, cur ^ 1);
            cp_wait<1>();
        } else {
            cp_wait<0>();
        }
        __syncthreads();

        const uint32_t sAH = sb + (uint32_t)cur * GSTAGE;
        const uint32_t sAL = sAH + GT_BYTES;
        const uint32_t sB  = sAH + 2 * GT_BYTES;

#pragma unroll
        for (int ks = 0; ks < GK / 16; ks++) {
            const uint32_t kb = (uint32_t)(ks * 32);
            uint32_t ah[4][4], al[4][4], bf[4][2];
#pragma unroll
            for (int mf = 0; mf < 4; mf++) {
                const uint32_t ro = (uint32_t)((mrow0 + mf * 16) * 144) + kb + aOff;
                ldmx4(ah[mf], sAH + ro);
                ldmx4(al[mf], sAL + ro);
            }
#pragma unroll
            for (int p = 0; p < 2; p++) {
                const uint32_t ro = (uint32_t)((nrow0 + p * 16) * 144) + kb + bOff4;
                ldmx4(&bf[2 * p][0], sB + ro);
            }
            // term-major, 16 independent accumulators per term pass
#pragma unroll
            for (int mf = 0; mf < 4; mf++)
#pragma unroll
                for (int nf = 0; nf < 4; nf++)
                    mma16816(c[mf][nf], ah[mf], bf[nf]);
#pragma unroll
            for (int mf = 0; mf < 4; mf++)
#pragma unroll
                for (int nf = 0; nf < 4; nf++)
                    mma16816(c[mf][nf], al[mf], bf[nf]);
        }
        __syncthreads();
    }

    const int crow = lane >> 2, ccol = (lane & 3) * 2;
    if (SPLIT) {
#pragma unroll
        for (int mf = 0; mf < 4; mf++) {
#pragma unroll
            for (int nf = 0; nf < 4; nf++) {
                const int r  = mBase + mrow0 + mf * 16 + crow;
                const int cc = nBase + nrow0 + nf * 8 + ccol;
                const float bx = bias[cc], by = bias[cc + 1];
#pragma unroll
                for (int half = 0; half < 2; half++) {
                    const int rr = r + half * 8;
                    float v0 = c[mf][nf][half * 2 + 0] + bx;
                    float v1 = c[mf][nf][half * 2 + 1] + by;
                    if (z == 0) {
                        uint32_t hp, lp;
                        split_pack2h(v0 * 0.125f, v1 * 0.125f, hp, lp);
                        *(uint32_t*)(Qh + (size_t)rr * DM + cc) = hp;
                        *(uint32_t*)(Ql + (size_t)rr * DM + cc) = lp;
                    } else if (z == 1) {
                        *(uint32_t*)(Kd + (size_t)rr * DM + cc) = pack_h2(v0, v1);
                    } else {
                        *(uint32_t*)(Vd + (size_t)rr * DM + cc) = pack_h2(v0, v1);
                    }
                }
            }
        }
    } else {
#pragma unroll
        for (int mf = 0; mf < 4; mf++) {
#pragma unroll
            for (int nf = 0; nf < 4; nf++) {
                const int r  = mBase + mrow0 + mf * 16 + crow;
                const int cc = nBase + nrow0 + nf * 8 + ccol;
                const float bx = bias[cc], by = bias[cc + 1];
                float2 v0 = { c[mf][nf][0] + bx, c[mf][nf][1] + by };
                float2 v1 = { c[mf][nf][2] + bx, c[mf][nf][3] + by };
                *(float2*)(F0 + (size_t)r * DM + cc)       = v0;
                *(float2*)(F0 + (size_t)(r + 8) * DM + cc) = v1;
            }
        }
    }
}

// ---------------------------------------------------------------------------
// Flash attention, fp16 (Q split 2-term for scores; P single fp16 for PV),
// 2-stage cp.async, 2 CTAs/SM. CTA: 128 q-rows, 8 warps x 16 rows, KV tiles 64.
// smem: Qh,Ql [128][72h]; 2 stages of {K, V}[64][72h]
// ---------------------------------------------------------------------------
constexpr int AT_Q   = 0;
constexpr int AT_QL  = 128 * 144;                    // 18432
constexpr int AT_KV0 = 2 * 128 * 144;                // 36864
constexpr int KV_T   = 64 * 144;                     // 9216 per tile
constexpr int KV_STAGE = 2 * KV_T;                   // 18432 per stage
constexpr int SMA_TOTAL = AT_KV0 + 2 * KV_STAGE;     // 73728

__global__ __launch_bounds__(256, 2) void attn_mma(
    const __half* __restrict__ Qh, const __half* __restrict__ Ql,
    const __half* __restrict__ Kd, const __half* __restrict__ Vd,
    __half* __restrict__ Oh, __half* __restrict__ Ol)
{
    extern __shared__ char smem[];
    const uint32_t sb = smem_u32(smem);
    const int tid = threadIdx.x;
    const int wid = tid >> 5, lane = tid & 31;
    const int b = blockIdx.z, h = blockIdx.y;
    const int q0 = blockIdx.x * 128;
    const int hc = h * DK;

    const int frow = tid >> 2, fch = (tid & 3) * 16;   // KV fill: 64 rows, 16h each

    auto issueKV = [&](int kv0, int st) {
        const size_t go = (size_t)(b * S + kv0 + frow) * DM + hc + fch;
        const uint32_t s0 = sb + AT_KV0 + (uint32_t)st * KV_STAGE;
        const uint32_t so = (uint32_t)(frow * 144 + fch * 2);
#pragma unroll
        for (int u = 0; u < 2; u++) {
            cp16(s0 + 0 * KV_T + so + u * 16, Kd + go + u * 8);
            cp16(s0 + 1 * KV_T + so + u * 16, Vd + go + u * 8);
        }
        cp_commit();
    };

    // ---- fill Q tile (128 x 64 fp16, hi+lo)
    {
        const int row = tid >> 1, cb = (tid & 1) * 32;
        const size_t go = (size_t)(b * S + q0 + row) * DM + hc + cb;
        const uint32_t so = (uint32_t)(row * 144 + cb * 2);
#pragma unroll
        for (int u = 0; u < 4; u++) {
            *(uint4*)(smem + AT_Q  + so + u * 16) = *(const uint4*)(Qh + go + u * 8);
            *(uint4*)(smem + AT_QL + so + u * 16) = *(const uint4*)(Ql + go + u * 8);
        }
    }
    issueKV(0, 0);
    __syncthreads();

    // ---- preload Q fragments
    const uint32_t aOff = (uint32_t)(((lane & 7) + ((lane >> 3) & 1) * 8) * 144
                                     + (lane >> 4) * 16);
    const uint32_t bOff4 = (uint32_t)(((lane & 7) + ((lane >> 4) & 1) * 8) * 144
                                      + ((lane >> 3) & 1) * 16);
    const uint32_t vOff4 = (uint32_t)((lane & 15) * 144 + (lane >> 4) * 16);

    uint32_t qhF[4][4], qlF[4][4];
#pragma unroll
    for (int kd = 0; kd < 4; kd++) {
        const uint32_t ro = (uint32_t)(wid * 16 * 144) + kd * 32 + aOff;
        ldmx4(qhF[kd], sb + AT_Q  + ro);
        ldmx4(qlF[kd], sb + AT_QL + ro);
    }

    float o[8][4];
#pragma unroll
    for (int nd = 0; nd < 8; nd++)
#pragma unroll
        for (int e = 0; e < 4; e++) o[nd][e] = 0.0f;
    float m0 = -1e30f, m1 = -1e30f, l0 = 0.0f, l1 = 0.0f;

    constexpr int NT = S / 64;   // 32
    for (int t = 0; t < NT; t++) {
        const int cur = t & 1;
        if (t + 1 < NT) {
            issueKV((t + 1) * 64, cur ^ 1);
            cp_wait<1>();
        } else {
            cp_wait<0>();
        }
        __syncthreads();

        const uint32_t sK = sb + AT_KV0 + (uint32_t)cur * KV_STAGE;
        const uint32_t sV = sK + KV_T;

        // ---- S = Q K^T  (2 terms: qh*k, ql*k)
        float s[8][4];
#pragma unroll
        for (int nf = 0; nf < 8; nf++)
#pragma unroll
            for (int e = 0; e < 4; e++) s[nf][e] = 0.0f;

#pragma unroll
        for (int kd = 0; kd < 4; kd++) {
#pragma unroll
            for (int g = 0; g < 2; g++) {
                uint32_t kf[4][2];
#pragma unroll
                for (int p = 0; p < 2; p++) {
                    const int nf = g * 4 + p * 2;
                    const uint32_t ro = (uint32_t)(nf * 8 * 144) + kd * 32 + bOff4;
                    ldmx4(&kf[2 * p][0], sK + ro);
                }
#pragma unroll
                for (int j = 0; j < 4; j++) mma16816(s[g * 4 + j], qhF[kd], kf[j]);
#pragma unroll
                for (int j = 0; j < 4; j++) mma16816(s[g * 4 + j], qlF[kd], kf[j]);
            }
        }

        // ---- online softmax
        float mx0 = -1e30f, mx1 = -1e30f;
#pragma unroll
        for (int nf = 0; nf < 8; nf++) {
            mx0 = fmaxf(mx0, fmaxf(s[nf][0], s[nf][1]));
            mx1 = fmaxf(mx1, fmaxf(s[nf][2], s[nf][3]));
        }
        mx0 = fmaxf(mx0, __shfl_xor_sync(0xffffffffu, mx0, 1));
        mx0 = fmaxf(mx0, __shfl_xor_sync(0xffffffffu, mx0, 2));
        mx1 = fmaxf(mx1, __shfl_xor_sync(0xffffffffu, mx1, 1));
        mx1 = fmaxf(mx1, __shfl_xor_sync(0xffffffffu, mx1, 2));

        const float nm0 = fmaxf(m0, mx0), nm1 = fmaxf(m1, mx1);
        const float a0 = __expf(m0 - nm0), a1 = __expf(m1 - nm1);
        m0 = nm0; m1 = nm1;

        float ls0 = 0.0f, ls1 = 0.0f;
#pragma unroll
        for (int nf = 0; nf < 8; nf++) {
            s[nf][0] = __expf(s[nf][0] - m0);
            s[nf][1] = __expf(s[nf][1] - m0);
            s[nf][2] = __expf(s[nf][2] - m1);
            s[nf][3] = __expf(s[nf][3] - m1);
            ls0 += s[nf][0] + s[nf][1];
            ls1 += s[nf][2] + s[nf][3];
        }
        ls0 += __shfl_xor_sync(0xffffffffu, ls0, 1);
        ls0 += __shfl_xor_sync(0xffffffffu, ls0, 2);
        ls1 += __shfl_xor_sync(0xffffffffu, ls1, 1);
        ls1 += __shfl_xor_sync(0xffffffffu, ls1, 2);
        l0 = l0 * a0 + ls0;
        l1 = l1 * a1 + ls1;
#pragma unroll
        for (int nd = 0; nd < 8; nd++) {
            o[nd][0] *= a0; o[nd][1] *= a0;
            o[nd][2] *= a1; o[nd][3] *= a1;
        }

        // ---- O += P V  (single fp16 P)
#pragma unroll
        for (int kd = 0; kd < 4; kd++) {
            uint32_t pa[4];
#pragma unroll
            for (int half = 0; half < 2; half++) {
                const int nf = 2 * kd + half;
#pragma unroll
                for (int rr = 0; rr < 2; rr++)
                    pa[half * 2 + rr] = pack_h2(s[nf][rr * 2 + 0], s[nf][rr * 2 + 1]);
            }
#pragma unroll
            for (int g = 0; g < 2; g++) {
                uint32_t vf[4][2];
#pragma unroll
                for (int p = 0; p < 2; p++) {
                    const int nd = g * 4 + p * 2;
                    const uint32_t ro = (uint32_t)(kd * 16 * 144) + nd * 16 + vOff4;
                    ldmx4t(&vf[2 * p][0], sV + ro);
                }
#pragma unroll
                for (int j = 0; j < 4; j++) mma16816(o[g * 4 + j], pa, vf[j]);
            }
        }
        __syncthreads();
    }

    // ---- epilogue: normalize, split to fp16 hi/lo, store
    const float inv0 = 1.0f / l0, inv1 = 1.0f / l1;
    const int gr0 = b * S + q0 + wid * 16 + (lane >> 2);
#pragma unroll
    for (int nd = 0; nd < 8; nd++) {
        const int cc = hc + nd * 8 + (lane & 3) * 2;
#pragma unroll
        for (int half = 0; half < 2; half++) {
            const int rr = gr0 + half * 8;
            const float inv = half ? inv1 : inv0;
            uint32_t hp, lp;
            split_pack2h(o[nd][half * 2 + 0] * inv, o[nd][half * 2 + 1] * inv, hp, lp);
            *(uint32_t*)(Oh + (size_t)rr * DM + cc) = hp;
            *(uint32_t*)(Ol + (size_t)rr * DM + cc) = lp;
        }
    }
}

// ===========================================================================
// Launch
// ===========================================================================
extern "C" void kernel_launch(void* const* d_in, const int* in_sizes, int n_in,
                              void* d_out, int out_size)
{
    const float* x  = (const float*)d_in[0];
    const float* wq = (const float*)d_in[1];
    const float* bq = (const float*)d_in[2];
    const float* wk = (const float*)d_in[3];
    const float* bk = (const float*)d_in[4];
    const float* wv = (const float*)d_in[5];
    const float* bv = (const float*)d_in[6];
    const float* wo = (const float*)d_in[7];
    const float* bo = (const float*)d_in[8];
    float* out = (float*)d_out;

    __half *xh, *xl, *qh, *ql, *kh, *vh, *ah, *al, *wt;
    cudaGetSymbolAddress((void**)&xh, g_xh);
    cudaGetSymbolAddress((void**)&xl, g_xl);
    cudaGetSymbolAddress((void**)&qh, g_qh);
    cudaGetSymbolAddress((void**)&ql, g_ql);
    cudaGetSymbolAddress((void**)&kh, g_kh);
    cudaGetSymbolAddress((void**)&vh, g_vh);
    cudaGetSymbolAddress((void**)&ah, g_ah);
    cudaGetSymbolAddress((void**)&al, g_al);
    cudaGetSymbolAddress((void**)&wt, g_wt);

    cudaFuncSetAttribute(gemm_mma<true>,  cudaFuncAttributeMaxDynamicSharedMemorySize, SMG_TOTAL);
    cudaFuncSetAttribute(gemm_mma<false>, cudaFuncAttributeMaxDynamicSharedMemorySize, SMG_TOTAL);
    cudaFuncSetAttribute(attn_mma, cudaFuncAttributeMaxDynamicSharedMemorySize, SMA_TOTAL);

    const size_t WSZ = (size_t)DM * DM;

    // 1) operand prep
    split2_kernel<<<(MR * DM / 4 + 255) / 256, 256>>>(x, xh, xl, MR * DM / 4);
    dim3 gT(DM / 32, DM / 32, 4);
    tsplit_kernel<<<gT, dim3(32, 8)>>>(wq, wk, wv, wo, wt);

    // 2) fused QKV projections (Q split+scaled; K,V single fp16)
    dim3 gQKV(DM / 128, MR / 128, 3);
    gemm_mma<true><<<gQKV, 256, SMG_TOTAL>>>(
        xh, xl, wt, bq, bk, bv,
        nullptr, qh, ql, kh, vh);

    // 3) attention (fp16 tensor cores) -> fp16 hi/lo
    dim3 gAttn(S / 128, H, B);   // (16, 16, 2)
    attn_mma<<<gAttn, 256, SMA_TOTAL>>>(qh, ql, kh, vh, ah, al);

    // 4) output projection -> fp32 out
    dim3 gO(DM / 128, MR / 128, 1);
    gemm_mma<false><<<gO, 256, SMG_TOTAL>>>(
        ah, al, wt + 3 * WSZ, bo, bo, bo,
        out, nullptr, nullptr, nullptr, nullptr);
}

// round 15
// speedup vs baseline: 1.8893x; 1.2220x over previous
#include <cuda_runtime.h>
#include <cuda_fp16.h>
#include <cstdint>
#include <math.h>

// Problem constants
constexpr int B  = 2;
constexpr int S  = 2048;
constexpr int DM = 1024;   // d_model
constexpr int H  = 16;
constexpr int DK = 64;
constexpr int MR = B * S;  // 4096 rows

// ---------------------------------------------------------------------------
// Scratch (allocation-free: __device__ globals)
// ---------------------------------------------------------------------------
__device__ __half g_xh[MR * DM];
__device__ __half g_qh[MR * DM];
__device__ __half g_ql[MR * DM];
__device__ __half g_kh[MR * DM];
__device__ __half g_vh[MR * DM];
__device__ __half g_ah[MR * DM];
__device__ __half g_al[MR * DM];
__device__ __half g_wt[4 * DM * DM];   // transposed weights, single fp16

// ---------------------------------------------------------------------------
// mma.sync / ldmatrix / cp.async helpers (non-'a' PTX surface)
// ---------------------------------------------------------------------------
__device__ __forceinline__ uint32_t smem_u32(const void* p) {
    uint32_t a;
    asm("{ .reg .u64 t; cvta.to.shared.u64 t, %1; cvt.u32.u64 %0, t; }"
        : "=r"(a) : "l"(p));
    return a;
}

__device__ __forceinline__ void ldmx4(uint32_t* r, uint32_t addr) {
    asm volatile("ldmatrix.sync.aligned.m8n8.x4.shared.b16 {%0,%1,%2,%3}, [%4];"
                 : "=r"(r[0]), "=r"(r[1]), "=r"(r[2]), "=r"(r[3]) : "r"(addr));
}
__device__ __forceinline__ void ldmx4t(uint32_t* r, uint32_t addr) {
    asm volatile("ldmatrix.sync.aligned.m8n8.x4.trans.shared.b16 {%0,%1,%2,%3}, [%4];"
                 : "=r"(r[0]), "=r"(r[1]), "=r"(r[2]), "=r"(r[3]) : "r"(addr));
}
__device__ __forceinline__ void mma16816(float* c, const uint32_t* a, const uint32_t* b) {
    asm volatile(
        "mma.sync.aligned.m16n8k16.row.col.f32.f16.f16.f32 "
        "{%0,%1,%2,%3}, {%4,%5,%6,%7}, {%8,%9}, {%0,%1,%2,%3};"
        : "+f"(c[0]), "+f"(c[1]), "+f"(c[2]), "+f"(c[3])
        : "r"(a[0]), "r"(a[1]), "r"(a[2]), "r"(a[3]), "r"(b[0]), "r"(b[1]));
}
__device__ __forceinline__ void cp16(uint32_t saddr, const void* g) {
    asm volatile("cp.async.cg.shared.global [%0], [%1], 16;"
                 :: "r"(saddr), "l"(g));
}
__device__ __forceinline__ void cp_commit() {
    asm volatile("cp.async.commit_group;");
}
template <int N>
__device__ __forceinline__ void cp_wait() {
    asm volatile("cp.async.wait_group %0;" :: "n"(N));
}
__device__ __forceinline__ float ex2f(float x) {
    float y;
    asm("ex2.approx.f32 %0, %1;" : "=f"(y) : "f"(x));
    return y;
}

// fp16 pack / 2-word split helpers
__device__ __forceinline__ uint32_t pack_h2(float v0, float v1) {
    __half2 h = __floats2half2_rn(v0, v1);
    return *(uint32_t*)&h;
}
__device__ __forceinline__ void split_pack2h(float v0, float v1,
                                             uint32_t& hi, uint32_t& lo) {
    __half2 h = __floats2half2_rn(v0, v1);
    hi = *(uint32_t*)&h;
    float r0 = v0 - __half2float(__low2half(h));
    float r1 = v1 - __half2float(__high2half(h));
    __half2 l = __floats2half2_rn(r0, r1);
    lo = *(uint32_t*)&l;
}

// ---------------------------------------------------------------------------
// Convert / transpose helpers
// ---------------------------------------------------------------------------
__global__ __launch_bounds__(256) void convert_kernel(
    const float* __restrict__ x, __half* __restrict__ h, int n4)
{
    int i = blockIdx.x * blockDim.x + threadIdx.x;
    if (i >= n4) return;
    float4 v = ((const float4*)x)[i];
    uint32_t h0 = pack_h2(v.x, v.y);
    uint32_t h1 = pack_h2(v.z, v.w);
    ((uint2*)h)[i] = make_uint2(h0, h1);
}

// W [K,N] fp32 -> Wt [N,K] single fp16, 4 weights via blockIdx.z
__global__ __launch_bounds__(256) void tsplit_kernel(
    const float* __restrict__ W0, const float* __restrict__ W1,
    const float* __restrict__ W2, const float* __restrict__ W3,
    __half* __restrict__ T0)
{
    __shared__ float t[32][33];
    const int z = blockIdx.z;
    const float* W = (z == 0) ? W0 : ((z == 1) ? W1 : ((z == 2) ? W2 : W3));
    __half* Th = T0 + (size_t)z * DM * DM;
    const int n0 = blockIdx.x * 32, k0 = blockIdx.y * 32;
    const int tx = threadIdx.x, ty = threadIdx.y;  // 32 x 8
    for (int i = ty; i < 32; i += 8)
        t[i][tx] = W[(size_t)(k0 + i) * DM + n0 + tx];
    __syncthreads();
    for (int i = ty; i < 32; i += 8)
        Th[(size_t)(n0 + i) * DM + k0 + tx] = __float2half(t[tx][i]);
}

// ---------------------------------------------------------------------------
// fp16 GEMM (TERMS = 1 or 2 A-operand split terms), 2-stage cp.async, BK=64,
// 2 CTAs/SM. C[M,N] = A[M,K] @ Wt^T + bias, Wt single fp16.
// CTA 128x128 tile, 256 threads (8 warps 2x4), warp tile 64x32.
// SPLIT epilogue: z=0 -> Q hi/lo fp16 (scale folds 1/sqrt(DK)*log2e);
//                 z=1 -> K fp16; z=2 -> V fp16.   Else: fp32 + bias.
// ---------------------------------------------------------------------------
constexpr int GK = 64;
constexpr int GT_BYTES = 128 * 144;               // 18432 per tile

template<int TERMS, bool SPLIT>
__global__ __launch_bounds__(256, 2) void gemm_mma(
    const __half* __restrict__ Ah, const __half* __restrict__ Al,
    const __half* __restrict__ Wt0,
    const float* __restrict__ b0, const float* __restrict__ b1,
    const float* __restrict__ b2,
    float* __restrict__ F0,
    __half* __restrict__ Qh, __half* __restrict__ Ql,
    __half* __restrict__ Kd, __half* __restrict__ Vd)
{
    constexpr int GST = (TERMS + 1) * GT_BYTES;    // stage bytes
    extern __shared__ char smem[];
    const int z = blockIdx.z;
    const __half* Wt = Wt0 + (size_t)z * DM * DM;
    const float* bias = (z == 0) ? b0 : ((z == 1) ? b1 : b2);

    const int tid  = threadIdx.x;
    const int wid  = tid >> 5, lane = tid & 31;
    const int mBase = blockIdx.y * 128, nBase = blockIdx.x * 128;

    const uint32_t sb = smem_u32(smem);

    const int wm = wid >> 2, wn = wid & 3;
    const int mrow0 = wm * 64, nrow0 = wn * 32;

    const uint32_t aOff = (uint32_t)(((lane & 7) + ((lane >> 3) & 1) * 8) * 144
                                     + (lane >> 4) * 16);
    const uint32_t bOff4 = (uint32_t)(((lane & 7) + ((lane >> 4) & 1) * 8) * 144
                                      + ((lane >> 3) & 1) * 16);

    const int frow = tid >> 1;           // 0..127
    const int fch  = (tid & 1) * 32;     // half-elems within 64-wide k chunk

    const __half* gAh = Ah + (size_t)mBase * DM;
    const __half* gAl = Al + (size_t)mBase * DM;
    const __half* gB  = Wt + (size_t)nBase * DM;

    auto issue = [&](int it, int st) {
        const int k0 = it * GK;
        const uint32_t s0 = sb + (uint32_t)st * GST;
        const size_t go = (size_t)frow * DM + k0 + fch;
        const uint32_t so = (uint32_t)(frow * 144 + fch * 2);
#pragma unroll
        for (int u = 0; u < 4; u++) {
            cp16(s0 + so + u * 16, gAh + go + u * 8);
            if (TERMS == 2)
                cp16(s0 + GT_BYTES + so + u * 16, gAl + go + u * 8);
            cp16(s0 + TERMS * GT_BYTES + so + u * 16, gB + go + u * 8);
        }
        cp_commit();
    };

    float c[4][4][4];
#pragma unroll
    for (int i = 0; i < 4; i++)
#pragma unroll
        for (int j = 0; j < 4; j++)
#pragma unroll
            for (int e = 0; e < 4; e++) c[i][j][e] = 0.0f;

    constexpr int NIT = DM / GK;   // 16
    issue(0, 0);

    for (int it = 0; it < NIT; it++) {
        const int cur = it & 1;
        if (it + 1 < NIT) {
            issue(it + 1, cur ^ 1);
            cp_wait<1>();
        } else {
            cp_wait<0>();
        }
        __syncthreads();

        const uint32_t sAH = sb + (uint32_t)cur * GST;
        const uint32_t sAL = sAH + GT_BYTES;
        const uint32_t sB  = sAH + TERMS * GT_BYTES;

#pragma unroll
        for (int ks = 0; ks < GK / 16; ks++) {
            const uint32_t kb = (uint32_t)(ks * 32);
            uint32_t ah[4][4], al[4][4], bf[4][2];
#pragma unroll
            for (int mf = 0; mf < 4; mf++) {
                const uint32_t ro = (uint32_t)((mrow0 + mf * 16) * 144) + kb + aOff;
                ldmx4(ah[mf], sAH + ro);
                if (TERMS == 2) ldmx4(al[mf], sAL + ro);
            }
#pragma unroll
            for (int p = 0; p < 2; p++) {
                const uint32_t ro = (uint32_t)((nrow0 + p * 16) * 144) + kb + bOff4;
                ldmx4(&bf[2 * p][0], sB + ro);
            }
#pragma unroll
            for (int mf = 0; mf < 4; mf++)
#pragma unroll
                for (int nf = 0; nf < 4; nf++)
                    mma16816(c[mf][nf], ah[mf], bf[nf]);
            if (TERMS == 2) {
#pragma unroll
                for (int mf = 0; mf < 4; mf++)
#pragma unroll
                    for (int nf = 0; nf < 4; nf++)
                        mma16816(c[mf][nf], al[mf], bf[nf]);
            }
        }
        __syncthreads();
    }

    const int crow = lane >> 2, ccol = (lane & 3) * 2;
    if (SPLIT) {
        // q scale folds 1/sqrt(DK) and log2(e) for base-2 softmax
        const float QSCALE = 0.125f * 1.4426950408889634f;
#pragma unroll
        for (int mf = 0; mf < 4; mf++) {
#pragma unroll
            for (int nf = 0; nf < 4; nf++) {
                const int r  = mBase + mrow0 + mf * 16 + crow;
                const int cc = nBase + nrow0 + nf * 8 + ccol;
                const float bx = bias[cc], by = bias[cc + 1];
#pragma unroll
                for (int half = 0; half < 2; half++) {
                    const int rr = r + half * 8;
                    float v0 = c[mf][nf][half * 2 + 0] + bx;
                    float v1 = c[mf][nf][half * 2 + 1] + by;
                    if (z == 0) {
                        uint32_t hp, lp;
                        split_pack2h(v0 * QSCALE, v1 * QSCALE, hp, lp);
                        *(uint32_t*)(Qh + (size_t)rr * DM + cc) = hp;
                        *(uint32_t*)(Ql + (size_t)rr * DM + cc) = lp;
                    } else if (z == 1) {
                        *(uint32_t*)(Kd + (size_t)rr * DM + cc) = pack_h2(v0, v1);
                    } else {
                        *(uint32_t*)(Vd + (size_t)rr * DM + cc) = pack_h2(v0, v1);
                    }
                }
            }
        }
    } else {
#pragma unroll
        for (int mf = 0; mf < 4; mf++) {
#pragma unroll
            for (int nf = 0; nf < 4; nf++) {
                const int r  = mBase + mrow0 + mf * 16 + crow;
                const int cc = nBase + nrow0 + nf * 8 + ccol;
                const float bx = bias[cc], by = bias[cc + 1];
                float2 v0 = { c[mf][nf][0] + bx, c[mf][nf][1] + by };
                float2 v1 = { c[mf][nf][2] + bx, c[mf][nf][3] + by };
                *(float2*)(F0 + (size_t)r * DM + cc)       = v0;
                *(float2*)(F0 + (size_t)(r + 8) * DM + cc) = v1;
            }
        }
    }
}

constexpr int SMG1 = 2 * 2 * GT_BYTES;   // TERMS=1: 73728
constexpr int SMG2 = 2 * 3 * GT_BYTES;   // TERMS=2: 110592

// ---------------------------------------------------------------------------
// Flash attention, fp16 (Q split 2-term for scores; P single fp16 for PV),
// base-2 softmax (log2e folded into Q), 2-stage cp.async, 2 CTAs/SM.
// CTA: 128 q-rows, 8 warps x 16 rows, KV tiles 64.
// smem: Qh,Ql [128][72h]; 2 stages of {K, V}[64][72h]
// ---------------------------------------------------------------------------
constexpr int AT_Q   = 0;
constexpr int AT_QL  = 128 * 144;                    // 18432
constexpr int AT_KV0 = 2 * 128 * 144;                // 36864
constexpr int KV_T   = 64 * 144;                     // 9216 per tile
constexpr int KV_STAGE = 2 * KV_T;                   // 18432 per stage
constexpr int SMA_TOTAL = AT_KV0 + 2 * KV_STAGE;     // 73728

__global__ __launch_bounds__(256, 2) void attn_mma(
    const __half* __restrict__ Qh, const __half* __restrict__ Ql,
    const __half* __restrict__ Kd, const __half* __restrict__ Vd,
    __half* __restrict__ Oh, __half* __restrict__ Ol)
{
    extern __shared__ char smem[];
    const uint32_t sb = smem_u32(smem);
    const int tid = threadIdx.x;
    const int wid = tid >> 5, lane = tid & 31;
    const int b = blockIdx.z, h = blockIdx.y;
    const int q0 = blockIdx.x * 128;
    const int hc = h * DK;

    const int frow = tid >> 2, fch = (tid & 3) * 16;   // KV fill: 64 rows, 16h each

    auto issueKV = [&](int kv0, int st) {
        const size_t go = (size_t)(b * S + kv0 + frow) * DM + hc + fch;
        const uint32_t s0 = sb + AT_KV0 + (uint32_t)st * KV_STAGE;
        const uint32_t so = (uint32_t)(frow * 144 + fch * 2);
#pragma unroll
        for (int u = 0; u < 2; u++) {
            cp16(s0 + 0 * KV_T + so + u * 16, Kd + go + u * 8);
            cp16(s0 + 1 * KV_T + so + u * 16, Vd + go + u * 8);
        }
        cp_commit();
    };

    // ---- fill Q tile (128 x 64 fp16, hi+lo)
    {
        const int row = tid >> 1, cb = (tid & 1) * 32;
        const size_t go = (size_t)(b * S + q0 + row) * DM + hc + cb;
        const uint32_t so = (uint32_t)(row * 144 + cb * 2);
#pragma unroll
        for (int u = 0; u < 4; u++) {
            *(uint4*)(smem + AT_Q  + so + u * 16) = *(const uint4*)(Qh + go + u * 8);
            *(uint4*)(smem + AT_QL + so + u * 16) = *(const uint4*)(Ql + go + u * 8);
        }
    }
    issueKV(0, 0);
    __syncthreads();

    // ---- preload Q fragments
    const uint32_t aOff = (uint32_t)(((lane & 7) + ((lane >> 3) & 1) * 8) * 144
                                     + (lane >> 4) * 16);
    const uint32_t bOff4 = (uint32_t)(((lane & 7) + ((lane >> 4) & 1) * 8) * 144
                                      + ((lane >> 3) & 1) * 16);
    const uint32_t vOff4 = (uint32_t)((lane & 15) * 144 + (lane >> 4) * 16);

    uint32_t qhF[4][4], qlF[4][4];
#pragma unroll
    for (int kd = 0; kd < 4; kd++) {
        const uint32_t ro = (uint32_t)(wid * 16 * 144) + kd * 32 + aOff;
        ldmx4(qhF[kd], sb + AT_Q  + ro);
        ldmx4(qlF[kd], sb + AT_QL + ro);
    }

    float o[8][4];
#pragma unroll
    for (int nd = 0; nd < 8; nd++)
#pragma unroll
        for (int e = 0; e < 4; e++) o[nd][e] = 0.0f;
    float m0 = -1e30f, m1 = -1e30f, l0 = 0.0f, l1 = 0.0f;

    constexpr int NT = S / 64;   // 32
    for (int t = 0; t < NT; t++) {
        const int cur = t & 1;
        if (t + 1 < NT) {
            issueKV((t + 1) * 64, cur ^ 1);
            cp_wait<1>();
        } else {
            cp_wait<0>();
        }
        __syncthreads();

        const uint32_t sK = sb + AT_KV0 + (uint32_t)cur * KV_STAGE;
        const uint32_t sV = sK + KV_T;

        // ---- S = Q K^T  (2 terms: qh*k, ql*k); scores already in log2 units
        float s[8][4];
#pragma unroll
        for (int nf = 0; nf < 8; nf++)
#pragma unroll
            for (int e = 0; e < 4; e++) s[nf][e] = 0.0f;

#pragma unroll
        for (int kd = 0; kd < 4; kd++) {
#pragma unroll
            for (int g = 0; g < 2; g++) {
                uint32_t kf[4][2];
#pragma unroll
                for (int p = 0; p < 2; p++) {
                    const int nf = g * 4 + p * 2;
                    const uint32_t ro = (uint32_t)(nf * 8 * 144) + kd * 32 + bOff4;
                    ldmx4(&kf[2 * p][0], sK + ro);
                }
#pragma unroll
                for (int j = 0; j < 4; j++) mma16816(s[g * 4 + j], qhF[kd], kf[j]);
#pragma unroll
                for (int j = 0; j < 4; j++) mma16816(s[g * 4 + j], qlF[kd], kf[j]);
            }
        }

        // ---- online softmax (base 2)
        float mx0 = -1e30f, mx1 = -1e30f;
#pragma unroll
        for (int nf = 0; nf < 8; nf++) {
            mx0 = fmaxf(mx0, fmaxf(s[nf][0], s[nf][1]));
            mx1 = fmaxf(mx1, fmaxf(s[nf][2], s[nf][3]));
        }
        mx0 = fmaxf(mx0, __shfl_xor_sync(0xffffffffu, mx0, 1));
        mx0 = fmaxf(mx0, __shfl_xor_sync(0xffffffffu, mx0, 2));
        mx1 = fmaxf(mx1, __shfl_xor_sync(0xffffffffu, mx1, 1));
        mx1 = fmaxf(mx1, __shfl_xor_sync(0xffffffffu, mx1, 2));

        const float nm0 = fmaxf(m0, mx0), nm1 = fmaxf(m1, mx1);
        const float a0 = ex2f(m0 - nm0), a1 = ex2f(m1 - nm1);
        m0 = nm0; m1 = nm1;

        float ls0 = 0.0f, ls1 = 0.0f;
#pragma unroll
        for (int nf = 0; nf < 8; nf++) {
            s[nf][0] = ex2f(s[nf][0] - m0);
            s[nf][1] = ex2f(s[nf][1] - m0);
            s[nf][2] = ex2f(s[nf][2] - m1);
            s[nf][3] = ex2f(s[nf][3] - m1);
            ls0 += s[nf][0] + s[nf][1];
            ls1 += s[nf][2] + s[nf][3];
        }
        ls0 += __shfl_xor_sync(0xffffffffu, ls0, 1);
        ls0 += __shfl_xor_sync(0xffffffffu, ls0, 2);
        ls1 += __shfl_xor_sync(0xffffffffu, ls1, 1);
        ls1 += __shfl_xor_sync(0xffffffffu, ls1, 2);
        l0 = l0 * a0 + ls0;
        l1 = l1 * a1 + ls1;
#pragma unroll
        for (int nd = 0; nd < 8; nd++) {
            o[nd][0] *= a0; o[nd][1] *= a0;
            o[nd][2] *= a1; o[nd][3] *= a1;
        }

        // ---- O += P V  (single fp16 P)
#pragma unroll
        for (int kd = 0; kd < 4; kd++) {
            uint32_t pa[4];
#pragma unroll
            for (int half = 0; half < 2; half++) {
                const int nf = 2 * kd + half;
#pragma unroll
                for (int rr = 0; rr < 2; rr++)
                    pa[half * 2 + rr] = pack_h2(s[nf][rr * 2 + 0], s[nf][rr * 2 + 1]);
            }
#pragma unroll
            for (int g = 0; g < 2; g++) {
                uint32_t vf[4][2];
#pragma unroll
                for (int p = 0; p < 2; p++) {
                    const int nd = g * 4 + p * 2;
                    const uint32_t ro = (uint32_t)(kd * 16 * 144) + nd * 16 + vOff4;
                    ldmx4t(&vf[2 * p][0], sV + ro);
                }
#pragma unroll
                for (int j = 0; j < 4; j++) mma16816(o[g * 4 + j], pa, vf[j]);
            }
        }
        __syncthreads();
    }

    // ---- epilogue: normalize, split to fp16 hi/lo, store
    const float inv0 = 1.0f / l0, inv1 = 1.0f / l1;
    const int gr0 = b * S + q0 + wid * 16 + (lane >> 2);
#pragma unroll
    for (int nd = 0; nd < 8; nd++) {
        const int cc = hc + nd * 8 + (lane & 3) * 2;
#pragma unroll
        for (int half = 0; half < 2; half++) {
            const int rr = gr0 + half * 8;
            const float inv = half ? inv1 : inv0;
            uint32_t hp, lp;
            split_pack2h(o[nd][half * 2 + 0] * inv, o[nd][half * 2 + 1] * inv, hp, lp);
            *(uint32_t*)(Oh + (size_t)rr * DM + cc) = hp;
            *(uint32_t*)(Ol + (size_t)rr * DM + cc) = lp;
        }
    }
}

// ===========================================================================
// Launch
// ===========================================================================
extern "C" void kernel_launch(void* const* d_in, const int* in_sizes, int n_in,
                              void* d_out, int out_size)
{
    const float* x  = (const float*)d_in[0];
    const float* wq = (const float*)d_in[1];
    const float* bq = (const float*)d_in[2];
    const float* wk = (const float*)d_in[3];
    const float* bk = (const float*)d_in[4];
    const float* wv = (const float*)d_in[5];
    const float* bv = (const float*)d_in[6];
    const float* wo = (const float*)d_in[7];
    const float* bo = (const float*)d_in[8];
    float* out = (float*)d_out;

    __half *xh, *qh, *ql, *kh, *vh, *ah, *al, *wt;
    cudaGetSymbolAddress((void**)&xh, g_xh);
    cudaGetSymbolAddress((void**)&qh, g_qh);
    cudaGetSymbolAddress((void**)&ql, g_ql);
    cudaGetSymbolAddress((void**)&kh, g_kh);
    cudaGetSymbolAddress((void**)&vh, g_vh);
    cudaGetSymbolAddress((void**)&ah, g_ah);
    cudaGetSymbolAddress((void**)&al, g_al);
    cudaGetSymbolAddress((void**)&wt, g_wt);

    cudaFuncSetAttribute(gemm_mma<1, true>,  cudaFuncAttributeMaxDynamicSharedMemorySize, SMG1);
    cudaFuncSetAttribute(gemm_mma<2, false>, cudaFuncAttributeMaxDynamicSharedMemorySize, SMG2);
    cudaFuncSetAttribute(attn_mma, cudaFuncAttributeMaxDynamicSharedMemorySize, SMA_TOTAL);

    const size_t WSZ = (size_t)DM * DM;

    // 1) operand prep
    convert_kernel<<<(MR * DM / 4 + 255) / 256, 256>>>(x, xh, MR * DM / 4);
    dim3 gT(DM / 32, DM / 32, 4);
    tsplit_kernel<<<gT, dim3(32, 8)>>>(wq, wk, wv, wo, wt);

    // 2) fused QKV projections, single fp16 A (Q split+scaled; K,V single fp16)
    dim3 gQKV(DM / 128, MR / 128, 3);
    gemm_mma<1, true><<<gQKV, 256, SMG1>>>(
        xh, xh, wt, bq, bk, bv,
        nullptr, qh, ql, kh, vh);

    // 3) attention (fp16 tensor cores, base-2 softmax) -> fp16 hi/lo
    dim3 gAttn(S / 128, H, B);   // (16, 16, 2)
    attn_mma<<<gAttn, 256, SMA_TOTAL>>>(qh, ql, kh, vh, ah, al);

    // 4) output projection, 2-term A -> fp32 out
    dim3 gO(DM / 128, MR / 128, 1);
    gemm_mma<2, false><<<gO, 256, SMG2>>>(
        ah, al, wt + 3 * WSZ, bo, bo, bo,
        out, nullptr, nullptr, nullptr, nullptr);
}

// round 16
// speedup vs baseline: 2.0552x; 1.0878x over previous
#include <cuda_runtime.h>
#include <cuda_fp16.h>
#include <cstdint>
#include <math.h>

// Problem constants
constexpr int B  = 2;
constexpr int S  = 2048;
constexpr int DM = 1024;   // d_model
constexpr int H  = 16;
constexpr int DK = 64;
constexpr int MR = B * S;  // 4096 rows

// ---------------------------------------------------------------------------
// Scratch (allocation-free: __device__ globals)
// ---------------------------------------------------------------------------
__device__ __half g_xh[MR * DM];
__device__ __half g_qh[MR * DM];
__device__ __half g_ql[MR * DM];
__device__ __half g_kh[MR * DM];
__device__ __half g_vh[MR * DM];
__device__ __half g_ah[MR * DM];
__device__ __half g_wt[4 * DM * DM];   // transposed weights, single fp16

// ---------------------------------------------------------------------------
// mma.sync / ldmatrix / cp.async helpers (non-'a' PTX surface)
// ---------------------------------------------------------------------------
__device__ __forceinline__ uint32_t smem_u32(const void* p) {
    uint32_t a;
    asm("{ .reg .u64 t; cvta.to.shared.u64 t, %1; cvt.u32.u64 %0, t; }"
        : "=r"(a) : "l"(p));
    return a;
}

__device__ __forceinline__ void ldmx4(uint32_t* r, uint32_t addr) {
    asm volatile("ldmatrix.sync.aligned.m8n8.x4.shared.b16 {%0,%1,%2,%3}, [%4];"
                 : "=r"(r[0]), "=r"(r[1]), "=r"(r[2]), "=r"(r[3]) : "r"(addr));
}
__device__ __forceinline__ void ldmx4t(uint32_t* r, uint32_t addr) {
    asm volatile("ldmatrix.sync.aligned.m8n8.x4.trans.shared.b16 {%0,%1,%2,%3}, [%4];"
                 : "=r"(r[0]), "=r"(r[1]), "=r"(r[2]), "=r"(r[3]) : "r"(addr));
}
__device__ __forceinline__ void mma16816(float* c, const uint32_t* a, const uint32_t* b) {
    asm volatile(
        "mma.sync.aligned.m16n8k16.row.col.f32.f16.f16.f32 "
        "{%0,%1,%2,%3}, {%4,%5,%6,%7}, {%8,%9}, {%0,%1,%2,%3};"
        : "+f"(c[0]), "+f"(c[1]), "+f"(c[2]), "+f"(c[3])
        : "r"(a[0]), "r"(a[1]), "r"(a[2]), "r"(a[3]), "r"(b[0]), "r"(b[1]));
}
__device__ __forceinline__ void cp16(uint32_t saddr, const void* g) {
    asm volatile("cp.async.cg.shared.global [%0], [%1], 16;"
                 :: "r"(saddr), "l"(g));
}
__device__ __forceinline__ void cp_commit() {
    asm volatile("cp.async.commit_group;");
}
template <int N>
__device__ __forceinline__ void cp_wait() {
    asm volatile("cp.async.wait_group %0;" :: "n"(N));
}
__device__ __forceinline__ float ex2f(float x) {
    float y;
    asm("ex2.approx.f32 %0, %1;" : "=f"(y) : "f"(x));
    return y;
}

// fp16 pack / 2-word split helpers
__device__ __forceinline__ uint32_t pack_h2(float v0, float v1) {
    __half2 h = __floats2half2_rn(v0, v1);
    return *(uint32_t*)&h;
}
__device__ __forceinline__ void split_pack2h(float v0, float v1,
                                             uint32_t& hi, uint32_t& lo) {
    __half2 h = __floats2half2_rn(v0, v1);
    hi = *(uint32_t*)&h;
    float r0 = v0 - __half2float(__low2half(h));
    float r1 = v1 - __half2float(__high2half(h));
    __half2 l = __floats2half2_rn(r0, r1);
    lo = *(uint32_t*)&l;
}

// ---------------------------------------------------------------------------
// Convert / transpose helpers
// ---------------------------------------------------------------------------
__global__ __launch_bounds__(256) void convert_kernel(
    const float* __restrict__ x, __half* __restrict__ h, int n4)
{
    int i = blockIdx.x * blockDim.x + threadIdx.x;
    if (i >= n4) return;
    float4 v = ((const float4*)x)[i];
    uint32_t h0 = pack_h2(v.x, v.y);
    uint32_t h1 = pack_h2(v.z, v.w);
    ((uint2*)h)[i] = make_uint2(h0, h1);
}

// W [K,N] fp32 -> Wt [N,K] single fp16, 4 weights via blockIdx.z
__global__ __launch_bounds__(256) void tsplit_kernel(
    const float* __restrict__ W0, const float* __restrict__ W1,
    const float* __restrict__ W2, const float* __restrict__ W3,
    __half* __restrict__ T0)
{
    __shared__ float t[32][33];
    const int z = blockIdx.z;
    const float* W = (z == 0) ? W0 : ((z == 1) ? W1 : ((z == 2) ? W2 : W3));
    __half* Th = T0 + (size_t)z * DM * DM;
    const int n0 = blockIdx.x * 32, k0 = blockIdx.y * 32;
    const int tx = threadIdx.x, ty = threadIdx.y;  // 32 x 8
    for (int i = ty; i < 32; i += 8)
        t[i][tx] = W[(size_t)(k0 + i) * DM + n0 + tx];
    __syncthreads();
    for (int i = ty; i < 32; i += 8)
        Th[(size_t)(n0 + i) * DM + k0 + tx] = __float2half(t[tx][i]);
}

// ---------------------------------------------------------------------------
// fp16 single-term GEMM, 3-stage cp.async pipeline (1 barrier/iter), BK=64,
// 2 CTAs/SM. C[M,N] = A[M,K] @ Wt^T + bias, A and Wt single fp16.
// CTA 128x128 tile, 256 threads (8 warps 2x4), warp tile 64x32.
// SPLIT epilogue: z=0 -> Q hi/lo fp16 (scale folds 1/sqrt(DK)*log2e);
//                 z=1 -> K fp16; z=2 -> V fp16.   Else: fp32 + bias.
// ---------------------------------------------------------------------------
constexpr int GK = 64;
constexpr int GT_BYTES = 128 * 144;               // 18432 per tile
constexpr int GSTAGE   = 2 * GT_BYTES;            // A + B per stage = 36864
constexpr int SMG_TOTAL = 3 * GSTAGE;             // 110592

template<bool SPLIT>
__global__ __launch_bounds__(256, 2) void gemm_mma(
    const __half* __restrict__ Ah,
    const __half* __restrict__ Wt0,
    const float* __restrict__ b0, const float* __restrict__ b1,
    const float* __restrict__ b2,
    float* __restrict__ F0,
    __half* __restrict__ Qh, __half* __restrict__ Ql,
    __half* __restrict__ Kd, __half* __restrict__ Vd)
{
    extern __shared__ char smem[];
    const int z = blockIdx.z;
    const __half* Wt = Wt0 + (size_t)z * DM * DM;
    const float* bias = (z == 0) ? b0 : ((z == 1) ? b1 : b2);

    const int tid  = threadIdx.x;
    const int wid  = tid >> 5, lane = tid & 31;
    const int mBase = blockIdx.y * 128, nBase = blockIdx.x * 128;

    const uint32_t sb = smem_u32(smem);

    const int wm = wid >> 2, wn = wid & 3;
    const int mrow0 = wm * 64, nrow0 = wn * 32;

    const uint32_t aOff = (uint32_t)(((lane & 7) + ((lane >> 3) & 1) * 8) * 144
                                     + (lane >> 4) * 16);
    const uint32_t bOff4 = (uint32_t)(((lane & 7) + ((lane >> 4) & 1) * 8) * 144
                                      + ((lane >> 3) & 1) * 16);

    const int frow = tid >> 1;           // 0..127
    const int fch  = (tid & 1) * 32;     // half-elems within 64-wide k chunk

    const __half* gAh = Ah + (size_t)mBase * DM;
    const __half* gB  = Wt + (size_t)nBase * DM;

    auto issue = [&](int it, int st) {
        const int k0 = it * GK;
        const uint32_t s0 = sb + (uint32_t)st * GSTAGE;
        const size_t go = (size_t)frow * DM + k0 + fch;
        const uint32_t so = (uint32_t)(frow * 144 + fch * 2);
#pragma unroll
        for (int u = 0; u < 4; u++) {
            cp16(s0 + so + u * 16, gAh + go + u * 8);
            cp16(s0 + GT_BYTES + so + u * 16, gB + go + u * 8);
        }
        cp_commit();
    };

    float c[4][4][4];
#pragma unroll
    for (int i = 0; i < 4; i++)
#pragma unroll
        for (int j = 0; j < 4; j++)
#pragma unroll
            for (int e = 0; e < 4; e++) c[i][j][e] = 0.0f;

    constexpr int NIT = DM / GK;   // 16
    issue(0, 0);
    issue(1, 1);

    for (int it = 0; it < NIT; it++) {
        cp_wait<1>();        // stage it's group complete
        __syncthreads();     // also orders prior-iter consumers before refill
        if (it + 2 < NIT) issue(it + 2, (it + 2) % 3);

        const uint32_t sA = sb + (uint32_t)(it % 3) * GSTAGE;
        const uint32_t sB = sA + GT_BYTES;

#pragma unroll
        for (int ks = 0; ks < GK / 16; ks++) {
            const uint32_t kb = (uint32_t)(ks * 32);
            uint32_t ah[4][4], bf[4][2];
#pragma unroll
            for (int mf = 0; mf < 4; mf++) {
                const uint32_t ro = (uint32_t)((mrow0 + mf * 16) * 144) + kb + aOff;
                ldmx4(ah[mf], sA + ro);
            }
#pragma unroll
            for (int p = 0; p < 2; p++) {
                const uint32_t ro = (uint32_t)((nrow0 + p * 16) * 144) + kb + bOff4;
                ldmx4(&bf[2 * p][0], sB + ro);
            }
#pragma unroll
            for (int mf = 0; mf < 4; mf++)
#pragma unroll
                for (int nf = 0; nf < 4; nf++)
                    mma16816(c[mf][nf], ah[mf], bf[nf]);
        }
    }

    const int crow = lane >> 2, ccol = (lane & 3) * 2;
    if (SPLIT) {
        // q scale folds 1/sqrt(DK) and log2(e) for base-2 softmax
        const float QSCALE = 0.125f * 1.4426950408889634f;
#pragma unroll
        for (int mf = 0; mf < 4; mf++) {
#pragma unroll
            for (int nf = 0; nf < 4; nf++) {
                const int r  = mBase + mrow0 + mf * 16 + crow;
                const int cc = nBase + nrow0 + nf * 8 + ccol;
                const float bx = bias[cc], by = bias[cc + 1];
#pragma unroll
                for (int half = 0; half < 2; half++) {
                    const int rr = r + half * 8;
                    float v0 = c[mf][nf][half * 2 + 0] + bx;
                    float v1 = c[mf][nf][half * 2 + 1] + by;
                    if (z == 0) {
                        uint32_t hp, lp;
                        split_pack2h(v0 * QSCALE, v1 * QSCALE, hp, lp);
                        *(uint32_t*)(Qh + (size_t)rr * DM + cc) = hp;
                        *(uint32_t*)(Ql + (size_t)rr * DM + cc) = lp;
                    } else if (z == 1) {
                        *(uint32_t*)(Kd + (size_t)rr * DM + cc) = pack_h2(v0, v1);
                    } else {
                        *(uint32_t*)(Vd + (size_t)rr * DM + cc) = pack_h2(v0, v1);
                    }
                }
            }
        }
    } else {
#pragma unroll
        for (int mf = 0; mf < 4; mf++) {
#pragma unroll
            for (int nf = 0; nf < 4; nf++) {
                const int r  = mBase + mrow0 + mf * 16 + crow;
                const int cc = nBase + nrow0 + nf * 8 + ccol;
                const float bx = bias[cc], by = bias[cc + 1];
                float2 v0 = { c[mf][nf][0] + bx, c[mf][nf][1] + by };
                float2 v1 = { c[mf][nf][2] + bx, c[mf][nf][3] + by };
                *(float2*)(F0 + (size_t)r * DM + cc)       = v0;
                *(float2*)(F0 + (size_t)(r + 8) * DM + cc) = v1;
            }
        }
    }
}

// ---------------------------------------------------------------------------
// Flash attention, fp16 (Q split 2-term for scores; P single fp16 for PV),
// base-2 softmax, 3-stage cp.async K/V pipeline (1 barrier/tile), 2 CTAs/SM.
// CTA: 128 q-rows, 8 warps x 16 rows, KV tiles 64. Output: single fp16.
// smem: Qh,Ql [128][72h]; 3 stages of {K, V}[64][72h]
// ---------------------------------------------------------------------------
constexpr int AT_Q   = 0;
constexpr int AT_QL  = 128 * 144;                    // 18432
constexpr int AT_KV0 = 2 * 128 * 144;                // 36864
constexpr int KV_T   = 64 * 144;                     // 9216 per tile
constexpr int KV_STAGE = 2 * KV_T;                   // 18432 per stage
constexpr int SMA_TOTAL = AT_KV0 + 3 * KV_STAGE;     // 92160

__global__ __launch_bounds__(256, 2) void attn_mma(
    const __half* __restrict__ Qh, const __half* __restrict__ Ql,
    const __half* __restrict__ Kd, const __half* __restrict__ Vd,
    __half* __restrict__ Oh)
{
    extern __shared__ char smem[];
    const uint32_t sb = smem_u32(smem);
    const int tid = threadIdx.x;
    const int wid = tid >> 5, lane = tid & 31;
    const int b = blockIdx.z, h = blockIdx.y;
    const int q0 = blockIdx.x * 128;
    const int hc = h * DK;

    const int frow = tid >> 2, fch = (tid & 3) * 16;   // KV fill: 64 rows, 16h each

    auto issueKV = [&](int kv0, int st) {
        const size_t go = (size_t)(b * S + kv0 + frow) * DM + hc + fch;
        const uint32_t s0 = sb + AT_KV0 + (uint32_t)st * KV_STAGE;
        const uint32_t so = (uint32_t)(frow * 144 + fch * 2);
#pragma unroll
        for (int u = 0; u < 2; u++) {
            cp16(s0 + 0 * KV_T + so + u * 16, Kd + go + u * 8);
            cp16(s0 + 1 * KV_T + so + u * 16, Vd + go + u * 8);
        }
        cp_commit();
    };

    // ---- fill Q tile (128 x 64 fp16, hi+lo)
    {
        const int row = tid >> 1, cb = (tid & 1) * 32;
        const size_t go = (size_t)(b * S + q0 + row) * DM + hc + cb;
        const uint32_t so = (uint32_t)(row * 144 + cb * 2);
#pragma unroll
        for (int u = 0; u < 4; u++) {
            *(uint4*)(smem + AT_Q  + so + u * 16) = *(const uint4*)(Qh + go + u * 8);
            *(uint4*)(smem + AT_QL + so + u * 16) = *(const uint4*)(Ql + go + u * 8);
        }
    }
    issueKV(0, 0);
    issueKV(64, 1);
    __syncthreads();   // Q fill visible

    // ---- preload Q fragments
    const uint32_t aOff = (uint32_t)(((lane & 7) + ((lane >> 3) & 1) * 8) * 144
                                     + (lane >> 4) * 16);
    const uint32_t bOff4 = (uint32_t)(((lane & 7) + ((lane >> 4) & 1) * 8) * 144
                                      + ((lane >> 3) & 1) * 16);
    const uint32_t vOff4 = (uint32_t)((lane & 15) * 144 + (lane >> 4) * 16);

    uint32_t qhF[4][4], qlF[4][4];
#pragma unroll
    for (int kd = 0; kd < 4; kd++) {
        const uint32_t ro = (uint32_t)(wid * 16 * 144) + kd * 32 + aOff;
        ldmx4(qhF[kd], sb + AT_Q  + ro);
        ldmx4(qlF[kd], sb + AT_QL + ro);
    }

    float o[8][4];
#pragma unroll
    for (int nd = 0; nd < 8; nd++)
#pragma unroll
        for (int e = 0; e < 4; e++) o[nd][e] = 0.0f;
    float m0 = -1e30f, m1 = -1e30f, l0 = 0.0f, l1 = 0.0f;

    constexpr int NT = S / 64;   // 32
    for (int t = 0; t < NT; t++) {
        cp_wait<1>();        // tile t complete
        __syncthreads();     // cross-warp visibility + prior-stage consumers done
        if (t + 2 < NT) issueKV((t + 2) * 64, (t + 2) % 3);

        const uint32_t sK = sb + AT_KV0 + (uint32_t)(t % 3) * KV_STAGE;
        const uint32_t sV = sK + KV_T;

        // ---- S = Q K^T  (2 terms: qh*k, ql*k); scores already in log2 units
        float s[8][4];
#pragma unroll
        for (int nf = 0; nf < 8; nf++)
#pragma unroll
            for (int e = 0; e < 4; e++) s[nf][e] = 0.0f;

#pragma unroll
        for (int kd = 0; kd < 4; kd++) {
#pragma unroll
            for (int g = 0; g < 2; g++) {
                uint32_t kf[4][2];
#pragma unroll
                for (int p = 0; p < 2; p++) {
                    const int nf = g * 4 + p * 2;
                    const uint32_t ro = (uint32_t)(nf * 8 * 144) + kd * 32 + bOff4;
                    ldmx4(&kf[2 * p][0], sK + ro);
                }
#pragma unroll
                for (int j = 0; j < 4; j++) mma16816(s[g * 4 + j], qhF[kd], kf[j]);
#pragma unroll
                for (int j = 0; j < 4; j++) mma16816(s[g * 4 + j], qlF[kd], kf[j]);
            }
        }

        // ---- online softmax (base 2)
        float mx0 = -1e30f, mx1 = -1e30f;
#pragma unroll
        for (int nf = 0; nf < 8; nf++) {
            mx0 = fmaxf(mx0, fmaxf(s[nf][0], s[nf][1]));
            mx1 = fmaxf(mx1, fmaxf(s[nf][2], s[nf][3]));
        }
        mx0 = fmaxf(mx0, __shfl_xor_sync(0xffffffffu, mx0, 1));
        mx0 = fmaxf(mx0, __shfl_xor_sync(0xffffffffu, mx0, 2));
        mx1 = fmaxf(mx1, __shfl_xor_sync(0xffffffffu, mx1, 1));
        mx1 = fmaxf(mx1, __shfl_xor_sync(0xffffffffu, mx1, 2));

        const float nm0 = fmaxf(m0, mx0), nm1 = fmaxf(m1, mx1);
        const float a0 = ex2f(m0 - nm0), a1 = ex2f(m1 - nm1);
        m0 = nm0; m1 = nm1;

        float ls0 = 0.0f, ls1 = 0.0f;
#pragma unroll
        for (int nf = 0; nf < 8; nf++) {
            s[nf][0] = ex2f(s[nf][0] - m0);
            s[nf][1] = ex2f(s[nf][1] - m0);
            s[nf][2] = ex2f(s[nf][2] - m1);
            s[nf][3] = ex2f(s[nf][3] - m1);
            ls0 += s[nf][0] + s[nf][1];
            ls1 += s[nf][2] + s[nf][3];
        }
        ls0 += __shfl_xor_sync(0xffffffffu, ls0, 1);
        ls0 += __shfl_xor_sync(0xffffffffu, ls0, 2);
        ls1 += __shfl_xor_sync(0xffffffffu, ls1, 1);
        ls1 += __shfl_xor_sync(0xffffffffu, ls1, 2);
        l0 = l0 * a0 + ls0;
        l1 = l1 * a1 + ls1;
#pragma unroll
        for (int nd = 0; nd < 8; nd++) {
            o[nd][0] *= a0; o[nd][1] *= a0;
            o[nd][2] *= a1; o[nd][3] *= a1;
        }

        // ---- O += P V  (single fp16 P)
#pragma unroll
        for (int kd = 0; kd < 4; kd++) {
            uint32_t pa[4];
#pragma unroll
            for (int half = 0; half < 2; half++) {
                const int nf = 2 * kd + half;
#pragma unroll
                for (int rr = 0; rr < 2; rr++)
                    pa[half * 2 + rr] = pack_h2(s[nf][rr * 2 + 0], s[nf][rr * 2 + 1]);
            }
#pragma unroll
            for (int g = 0; g < 2; g++) {
                uint32_t vf[4][2];
#pragma unroll
                for (int p = 0; p < 2; p++) {
                    const int nd = g * 4 + p * 2;
                    const uint32_t ro = (uint32_t)(kd * 16 * 144) + nd * 16 + vOff4;
                    ldmx4t(&vf[2 * p][0], sV + ro);
                }
#pragma unroll
                for (int j = 0; j < 4; j++) mma16816(o[g * 4 + j], pa, vf[j]);
            }
        }
    }

    // ---- epilogue: normalize, single fp16 store
    const float inv0 = 1.0f / l0, inv1 = 1.0f / l1;
    const int gr0 = b * S + q0 + wid * 16 + (lane >> 2);
#pragma unroll
    for (int nd = 0; nd < 8; nd++) {
        const int cc = hc + nd * 8 + (lane & 3) * 2;
#pragma unroll
        for (int half = 0; half < 2; half++) {
            const int rr = gr0 + half * 8;
            const float inv = half ? inv1 : inv0;
            *(uint32_t*)(Oh + (size_t)rr * DM + cc) =
                pack_h2(o[nd][half * 2 + 0] * inv, o[nd][half * 2 + 1] * inv);
        }
    }
}

// ===========================================================================
// Launch
// ===========================================================================
extern "C" void kernel_launch(void* const* d_in, const int* in_sizes, int n_in,
                              void* d_out, int out_size)
{
    const float* x  = (const float*)d_in[0];
    const float* wq = (const float*)d_in[1];
    const float* bq = (const float*)d_in[2];
    const float* wk = (const float*)d_in[3];
    const float* bk = (const float*)d_in[4];
    const float* wv = (const float*)d_in[5];
    const float* bv = (const float*)d_in[6];
    const float* wo = (const float*)d_in[7];
    const float* bo = (const float*)d_in[8];
    float* out = (float*)d_out;

    __half *xh, *qh, *ql, *kh, *vh, *ah, *wt;
    cudaGetSymbolAddress((void**)&xh, g_xh);
    cudaGetSymbolAddress((void**)&qh, g_qh);
    cudaGetSymbolAddress((void**)&ql, g_ql);
    cudaGetSymbolAddress((void**)&kh, g_kh);
    cudaGetSymbolAddress((void**)&vh, g_vh);
    cudaGetSymbolAddress((void**)&ah, g_ah);
    cudaGetSymbolAddress((void**)&wt, g_wt);

    cudaFuncSetAttribute(gemm_mma<true>,  cudaFuncAttributeMaxDynamicSharedMemorySize, SMG_TOTAL);
    cudaFuncSetAttribute(gemm_mma<false>, cudaFuncAttributeMaxDynamicSharedMemorySize, SMG_TOTAL);
    cudaFuncSetAttribute(attn_mma, cudaFuncAttributeMaxDynamicSharedMemorySize, SMA_TOTAL);

    const size_t WSZ = (size_t)DM * DM;

    // 1) operand prep
    convert_kernel<<<(MR * DM / 4 + 255) / 256, 256>>>(x, xh, MR * DM / 4);
    dim3 gT(DM / 32, DM / 32, 4);
    tsplit_kernel<<<gT, dim3(32, 8)>>>(wq, wk, wv, wo, wt);

    // 2) fused QKV projections (Q split+scaled; K,V single fp16)
    dim3 gQKV(DM / 128, MR / 128, 3);
    gemm_mma<true><<<gQKV, 256, SMG_TOTAL>>>(
        xh, wt, bq, bk, bv,
        nullptr, qh, ql, kh, vh);

    // 3) attention (fp16 tensor cores, base-2 softmax) -> single fp16
    dim3 gAttn(S / 128, H, B);   // (16, 16, 2)
    attn_mma<<<gAttn, 256, SMA_TOTAL>>>(qh, ql, kh, vh, ah);

    // 4) output projection, single-term -> fp32 out
    dim3 gO(DM / 128, MR / 128, 1);
    gemm_mma<false><<<gO, 256, SMG_TOTAL>>>(
        ah, wt + 3 * WSZ, bo, bo, bo,
        out, nullptr, nullptr, nullptr, nullptr);
}

// round 17
// speedup vs baseline: 2.2512x; 1.0954x over previous
#include <cuda_runtime.h>
#include <cuda_fp16.h>
#include <cstdint>
#include <math.h>

// Problem constants
constexpr int B  = 2;
constexpr int S  = 2048;
constexpr int DM = 1024;   // d_model
constexpr int H  = 16;
constexpr int DK = 64;
constexpr int MR = B * S;  // 4096 rows

// ---------------------------------------------------------------------------
// Scratch (allocation-free: __device__ globals)
// ---------------------------------------------------------------------------
__device__ __half g_xh[MR * DM];
__device__ __half g_qh[MR * DM];
__device__ __half g_kh[MR * DM];
__device__ __half g_vh[MR * DM];
__device__ __half g_ah[MR * DM];
__device__ __half g_wt[4 * DM * DM];   // transposed weights, single fp16

// ---------------------------------------------------------------------------
// mma.sync / ldmatrix / cp.async helpers (non-'a' PTX surface)
// ---------------------------------------------------------------------------
__device__ __forceinline__ uint32_t smem_u32(const void* p) {
    uint32_t a;
    asm("{ .reg .u64 t; cvta.to.shared.u64 t, %1; cvt.u32.u64 %0, t; }"
        : "=r"(a) : "l"(p));
    return a;
}

__device__ __forceinline__ void ldmx4(uint32_t* r, uint32_t addr) {
    asm volatile("ldmatrix.sync.aligned.m8n8.x4.shared.b16 {%0,%1,%2,%3}, [%4];"
                 : "=r"(r[0]), "=r"(r[1]), "=r"(r[2]), "=r"(r[3]) : "r"(addr));
}
__device__ __forceinline__ void ldmx4t(uint32_t* r, uint32_t addr) {
    asm volatile("ldmatrix.sync.aligned.m8n8.x4.trans.shared.b16 {%0,%1,%2,%3}, [%4];"
                 : "=r"(r[0]), "=r"(r[1]), "=r"(r[2]), "=r"(r[3]) : "r"(addr));
}
__device__ __forceinline__ void mma16816(float* c, const uint32_t* a, const uint32_t* b) {
    asm volatile(
        "mma.sync.aligned.m16n8k16.row.col.f32.f16.f16.f32 "
        "{%0,%1,%2,%3}, {%4,%5,%6,%7}, {%8,%9}, {%0,%1,%2,%3};"
        : "+f"(c[0]), "+f"(c[1]), "+f"(c[2]), "+f"(c[3])
        : "r"(a[0]), "r"(a[1]), "r"(a[2]), "r"(a[3]), "r"(b[0]), "r"(b[1]));
}
__device__ __forceinline__ void cp16(uint32_t saddr, const void* g) {
    asm volatile("cp.async.cg.shared.global [%0], [%1], 16;"
                 :: "r"(saddr), "l"(g));
}
__device__ __forceinline__ void cp_commit() {
    asm volatile("cp.async.commit_group;");
}
template <int N>
__device__ __forceinline__ void cp_wait() {
    asm volatile("cp.async.wait_group %0;" :: "n"(N));
}
__device__ __forceinline__ float ex2f(float x) {
    float y;
    asm("ex2.approx.f32 %0, %1;" : "=f"(y) : "f"(x));
    return y;
}

// fp16 pack helper
__device__ __forceinline__ uint32_t pack_h2(float v0, float v1) {
    __half2 h = __floats2half2_rn(v0, v1);
    return *(uint32_t*)&h;
}

// ---------------------------------------------------------------------------
// Convert / transpose helpers
// ---------------------------------------------------------------------------
__global__ __launch_bounds__(256) void convert_kernel(
    const float* __restrict__ x, __half* __restrict__ h, int n4)
{
    int i = blockIdx.x * blockDim.x + threadIdx.x;
    if (i >= n4) return;
    float4 v = ((const float4*)x)[i];
    uint32_t h0 = pack_h2(v.x, v.y);
    uint32_t h1 = pack_h2(v.z, v.w);
    ((uint2*)h)[i] = make_uint2(h0, h1);
}

// W [K,N] fp32 -> Wt [N,K] single fp16, 4 weights via blockIdx.z
__global__ __launch_bounds__(256) void tsplit_kernel(
    const float* __restrict__ W0, const float* __restrict__ W1,
    const float* __restrict__ W2, const float* __restrict__ W3,
    __half* __restrict__ T0)
{
    __shared__ float t[32][33];
    const int z = blockIdx.z;
    const float* W = (z == 0) ? W0 : ((z == 1) ? W1 : ((z == 2) ? W2 : W3));
    __half* Th = T0 + (size_t)z * DM * DM;
    const int n0 = blockIdx.x * 32, k0 = blockIdx.y * 32;
    const int tx = threadIdx.x, ty = threadIdx.y;  // 32 x 8
    for (int i = ty; i < 32; i += 8)
        t[i][tx] = W[(size_t)(k0 + i) * DM + n0 + tx];
    __syncthreads();
    for (int i = ty; i < 32; i += 8)
        Th[(size_t)(n0 + i) * DM + k0 + tx] = __float2half(t[tx][i]);
}

// ---------------------------------------------------------------------------
// fp16 single-term GEMM, 3-stage cp.async pipeline (1 barrier/iter), BK=64,
// 2 CTAs/SM. C[M,N] = A[M,K] @ Wt^T + bias, A and Wt single fp16.
// CTA 128x128 tile, 256 threads (8 warps 2x4), warp tile 64x32.
// SPLIT epilogue: z=0 -> Q fp16 (scale folds 1/sqrt(DK)*log2e);
//                 z=1 -> K fp16; z=2 -> V fp16.   Else: fp32 + bias.
// ---------------------------------------------------------------------------
constexpr int GK = 64;
constexpr int GT_BYTES = 128 * 144;               // 18432 per tile
constexpr int GSTAGE   = 2 * GT_BYTES;            // A + B per stage = 36864
constexpr int SMG_TOTAL = 3 * GSTAGE;             // 110592

template<bool SPLIT>
__global__ __launch_bounds__(256, 2) void gemm_mma(
    const __half* __restrict__ Ah,
    const __half* __restrict__ Wt0,
    const float* __restrict__ b0, const float* __restrict__ b1,
    const float* __restrict__ b2,
    float* __restrict__ F0,
    __half* __restrict__ Qd, __half* __restrict__ Kd, __half* __restrict__ Vd)
{
    extern __shared__ char smem[];
    const int z = blockIdx.z;
    const __half* Wt = Wt0 + (size_t)z * DM * DM;
    const float* bias = (z == 0) ? b0 : ((z == 1) ? b1 : b2);

    const int tid  = threadIdx.x;
    const int wid  = tid >> 5, lane = tid & 31;
    const int mBase = blockIdx.y * 128, nBase = blockIdx.x * 128;

    const uint32_t sb = smem_u32(smem);

    const int wm = wid >> 2, wn = wid & 3;
    const int mrow0 = wm * 64, nrow0 = wn * 32;

    const uint32_t aOff = (uint32_t)(((lane & 7) + ((lane >> 3) & 1) * 8) * 144
                                     + (lane >> 4) * 16);
    const uint32_t bOff4 = (uint32_t)(((lane & 7) + ((lane >> 4) & 1) * 8) * 144
                                      + ((lane >> 3) & 1) * 16);

    const int frow = tid >> 1;           // 0..127
    const int fch  = (tid & 1) * 32;     // half-elems within 64-wide k chunk

    const __half* gAh = Ah + (size_t)mBase * DM;
    const __half* gB  = Wt + (size_t)nBase * DM;

    auto issue = [&](int it, int st) {
        const int k0 = it * GK;
        const uint32_t s0 = sb + (uint32_t)st * GSTAGE;
        const size_t go = (size_t)frow * DM + k0 + fch;
        const uint32_t so = (uint32_t)(frow * 144 + fch * 2);
#pragma unroll
        for (int u = 0; u < 4; u++) {
            cp16(s0 + so + u * 16, gAh + go + u * 8);
            cp16(s0 + GT_BYTES + so + u * 16, gB + go + u * 8);
        }
        cp_commit();
    };

    float c[4][4][4];
#pragma unroll
    for (int i = 0; i < 4; i++)
#pragma unroll
        for (int j = 0; j < 4; j++)
#pragma unroll
            for (int e = 0; e < 4; e++) c[i][j][e] = 0.0f;

    constexpr int NIT = DM / GK;   // 16
    issue(0, 0);
    issue(1, 1);

    for (int it = 0; it < NIT; it++) {
        cp_wait<1>();        // stage it's group complete
        __syncthreads();     // also orders prior-iter consumers before refill
        if (it + 2 < NIT) issue(it + 2, (it + 2) % 3);

        const uint32_t sA = sb + (uint32_t)(it % 3) * GSTAGE;
        const uint32_t sB = sA + GT_BYTES;

#pragma unroll
        for (int ks = 0; ks < GK / 16; ks++) {
            const uint32_t kb = (uint32_t)(ks * 32);
            uint32_t ah[4][4], bf[4][2];
#pragma unroll
            for (int mf = 0; mf < 4; mf++) {
                const uint32_t ro = (uint32_t)((mrow0 + mf * 16) * 144) + kb + aOff;
                ldmx4(ah[mf], sA + ro);
            }
#pragma unroll
            for (int p = 0; p < 2; p++) {
                const uint32_t ro = (uint32_t)((nrow0 + p * 16) * 144) + kb + bOff4;
                ldmx4(&bf[2 * p][0], sB + ro);
            }
#pragma unroll
            for (int mf = 0; mf < 4; mf++)
#pragma unroll
                for (int nf = 0; nf < 4; nf++)
                    mma16816(c[mf][nf], ah[mf], bf[nf]);
        }
    }

    const int crow = lane >> 2, ccol = (lane & 3) * 2;
    if (SPLIT) {
        // q scale folds 1/sqrt(DK) and log2(e) for base-2 softmax
        const float scale = (z == 0) ? 0.125f * 1.4426950408889634f : 1.0f;
        __half* Dst = (z == 0) ? Qd : ((z == 1) ? Kd : Vd);
#pragma unroll
        for (int mf = 0; mf < 4; mf++) {
#pragma unroll
            for (int nf = 0; nf < 4; nf++) {
                const int r  = mBase + mrow0 + mf * 16 + crow;
                const int cc = nBase + nrow0 + nf * 8 + ccol;
                const float bx = bias[cc], by = bias[cc + 1];
#pragma unroll
                for (int half = 0; half < 2; half++) {
                    const int rr = r + half * 8;
                    float v0 = (c[mf][nf][half * 2 + 0] + bx) * scale;
                    float v1 = (c[mf][nf][half * 2 + 1] + by) * scale;
                    *(uint32_t*)(Dst + (size_t)rr * DM + cc) = pack_h2(v0, v1);
                }
            }
        }
    } else {
#pragma unroll
        for (int mf = 0; mf < 4; mf++) {
#pragma unroll
            for (int nf = 0; nf < 4; nf++) {
                const int r  = mBase + mrow0 + mf * 16 + crow;
                const int cc = nBase + nrow0 + nf * 8 + ccol;
                const float bx = bias[cc], by = bias[cc + 1];
                float2 v0 = { c[mf][nf][0] + bx, c[mf][nf][1] + by };
                float2 v1 = { c[mf][nf][2] + bx, c[mf][nf][3] + by };
                *(float2*)(F0 + (size_t)r * DM + cc)       = v0;
                *(float2*)(F0 + (size_t)(r + 8) * DM + cc) = v1;
            }
        }
    }
}

// ---------------------------------------------------------------------------
// Flash attention, all-single-fp16 operands (Q, K, V, P), fp32 accumulate,
// base-2 softmax, 3-stage cp.async K/V pipeline (1 barrier/tile), 2 CTAs/SM.
// CTA: 128 q-rows, 8 warps x 16 rows, KV tiles 64. Output: single fp16.
// smem: Q [128][72h]; 3 stages of {K, V}[64][72h]
// ---------------------------------------------------------------------------
constexpr int AT_Q   = 0;
constexpr int AT_KV0 = 128 * 144;                    // 18432
constexpr int KV_T   = 64 * 144;                     // 9216 per tile
constexpr int KV_STAGE = 2 * KV_T;                   // 18432 per stage
constexpr int SMA_TOTAL = AT_KV0 + 3 * KV_STAGE;     // 73728

__global__ __launch_bounds__(256, 2) void attn_mma(
    const __half* __restrict__ Qd,
    const __half* __restrict__ Kd, const __half* __restrict__ Vd,
    __half* __restrict__ Oh)
{
    extern __shared__ char smem[];
    const uint32_t sb = smem_u32(smem);
    const int tid = threadIdx.x;
    const int wid = tid >> 5, lane = tid & 31;
    const int b = blockIdx.z, h = blockIdx.y;
    const int q0 = blockIdx.x * 128;
    const int hc = h * DK;

    const int frow = tid >> 2, fch = (tid & 3) * 16;   // KV fill: 64 rows, 16h each

    auto issueKV = [&](int kv0, int st) {
        const size_t go = (size_t)(b * S + kv0 + frow) * DM + hc + fch;
        const uint32_t s0 = sb + AT_KV0 + (uint32_t)st * KV_STAGE;
        const uint32_t so = (uint32_t)(frow * 144 + fch * 2);
#pragma unroll
        for (int u = 0; u < 2; u++) {
            cp16(s0 + 0 * KV_T + so + u * 16, Kd + go + u * 8);
            cp16(s0 + 1 * KV_T + so + u * 16, Vd + go + u * 8);
        }
        cp_commit();
    };

    // ---- fill Q tile (128 x 64 fp16)
    {
        const int row = tid >> 1, cb = (tid & 1) * 32;
        const size_t go = (size_t)(b * S + q0 + row) * DM + hc + cb;
        const uint32_t so = (uint32_t)(row * 144 + cb * 2);
#pragma unroll
        for (int u = 0; u < 4; u++)
            *(uint4*)(smem + AT_Q + so + u * 16) = *(const uint4*)(Qd + go + u * 8);
    }
    issueKV(0, 0);
    issueKV(64, 1);
    __syncthreads();   // Q fill visible

    // ---- preload Q fragments
    const uint32_t aOff = (uint32_t)(((lane & 7) + ((lane >> 3) & 1) * 8) * 144
                                     + (lane >> 4) * 16);
    const uint32_t bOff4 = (uint32_t)(((lane & 7) + ((lane >> 4) & 1) * 8) * 144
                                      + ((lane >> 3) & 1) * 16);
    const uint32_t vOff4 = (uint32_t)((lane & 15) * 144 + (lane >> 4) * 16);

    uint32_t qF[4][4];
#pragma unroll
    for (int kd = 0; kd < 4; kd++) {
        const uint32_t ro = (uint32_t)(wid * 16 * 144) + kd * 32 + aOff;
        ldmx4(qF[kd], sb + AT_Q + ro);
    }

    float o[8][4];
#pragma unroll
    for (int nd = 0; nd < 8; nd++)
#pragma unroll
        for (int e = 0; e < 4; e++) o[nd][e] = 0.0f;
    float m0 = -1e30f, m1 = -1e30f, l0 = 0.0f, l1 = 0.0f;

    constexpr int NT = S / 64;   // 32
    for (int t = 0; t < NT; t++) {
        cp_wait<1>();        // tile t complete
        __syncthreads();     // cross-warp visibility + prior-stage consumers done
        if (t + 2 < NT) issueKV((t + 2) * 64, (t + 2) % 3);

        const uint32_t sK = sb + AT_KV0 + (uint32_t)(t % 3) * KV_STAGE;
        const uint32_t sV = sK + KV_T;

        // ---- S = Q K^T  (single-term); scores already in log2 units
        float s[8][4];
#pragma unroll
        for (int nf = 0; nf < 8; nf++)
#pragma unroll
            for (int e = 0; e < 4; e++) s[nf][e] = 0.0f;

#pragma unroll
        for (int kd = 0; kd < 4; kd++) {
#pragma unroll
            for (int g = 0; g < 2; g++) {
                uint32_t kf[4][2];
#pragma unroll
                for (int p = 0; p < 2; p++) {
                    const int nf = g * 4 + p * 2;
                    const uint32_t ro = (uint32_t)(nf * 8 * 144) + kd * 32 + bOff4;
                    ldmx4(&kf[2 * p][0], sK + ro);
                }
#pragma unroll
                for (int j = 0; j < 4; j++) mma16816(s[g * 4 + j], qF[kd], kf[j]);
            }
        }

        // ---- online softmax (base 2)
        float mx0 = -1e30f, mx1 = -1e30f;
#pragma unroll
        for (int nf = 0; nf < 8; nf++) {
            mx0 = fmaxf(mx0, fmaxf(s[nf][0], s[nf][1]));
            mx1 = fmaxf(mx1, fmaxf(s[nf][2], s[nf][3]));
        }
        mx0 = fmaxf(mx0, __shfl_xor_sync(0xffffffffu, mx0, 1));
        mx0 = fmaxf(mx0, __shfl_xor_sync(0xffffffffu, mx0, 2));
        mx1 = fmaxf(mx1, __shfl_xor_sync(0xffffffffu, mx1, 1));
        mx1 = fmaxf(mx1, __shfl_xor_sync(0xffffffffu, mx1, 2));

        const float nm0 = fmaxf(m0, mx0), nm1 = fmaxf(m1, mx1);
        const float a0 = ex2f(m0 - nm0), a1 = ex2f(m1 - nm1);
        m0 = nm0; m1 = nm1;

        float ls0 = 0.0f, ls1 = 0.0f;
#pragma unroll
        for (int nf = 0; nf < 8; nf++) {
            s[nf][0] = ex2f(s[nf][0] - m0);
            s[nf][1] = ex2f(s[nf][1] - m0);
            s[nf][2] = ex2f(s[nf][2] - m1);
            s[nf][3] = ex2f(s[nf][3] - m1);
            ls0 += s[nf][0] + s[nf][1];
            ls1 += s[nf][2] + s[nf][3];
        }
        ls0 += __shfl_xor_sync(0xffffffffu, ls0, 1);
        ls0 += __shfl_xor_sync(0xffffffffu, ls0, 2);
        ls1 += __shfl_xor_sync(0xffffffffu, ls1, 1);
        ls1 += __shfl_xor_sync(0xffffffffu, ls1, 2);
        l0 = l0 * a0 + ls0;
        l1 = l1 * a1 + ls1;
#pragma unroll
        for (int nd = 0; nd < 8; nd++) {
            o[nd][0] *= a0; o[nd][1] *= a0;
            o[nd][2] *= a1; o[nd][3] *= a1;
        }

        // ---- O += P V  (single fp16 P)
#pragma unroll
        for (int kd = 0; kd < 4; kd++) {
            uint32_t pa[4];
#pragma unroll
            for (int half = 0; half < 2; half++) {
                const int nf = 2 * kd + half;
#pragma unroll
                for (int rr = 0; rr < 2; rr++)
                    pa[half * 2 + rr] = pack_h2(s[nf][rr * 2 + 0], s[nf][rr * 2 + 1]);
            }
#pragma unroll
            for (int g = 0; g < 2; g++) {
                uint32_t vf[4][2];
#pragma unroll
                for (int p = 0; p < 2; p++) {
                    const int nd = g * 4 + p * 2;
                    const uint32_t ro = (uint32_t)(kd * 16 * 144) + nd * 16 + vOff4;
                    ldmx4t(&vf[2 * p][0], sV + ro);
                }
#pragma unroll
                for (int j = 0; j < 4; j++) mma16816(o[g * 4 + j], pa, vf[j]);
            }
        }
    }

    // ---- epilogue: normalize, single fp16 store
    const float inv0 = 1.0f / l0, inv1 = 1.0f / l1;
    const int gr0 = b * S + q0 + wid * 16 + (lane >> 2);
#pragma unroll
    for (int nd = 0; nd < 8; nd++) {
        const int cc = hc + nd * 8 + (lane & 3) * 2;
#pragma unroll
        for (int half = 0; half < 2; half++) {
            const int rr = gr0 + half * 8;
            const float inv = half ? inv1 : inv0;
            *(uint32_t*)(Oh + (size_t)rr * DM + cc) =
                pack_h2(o[nd][half * 2 + 0] * inv, o[nd][half * 2 + 1] * inv);
        }
    }
}

// ===========================================================================
// Launch
// ===========================================================================
extern "C" void kernel_launch(void* const* d_in, const int* in_sizes, int n_in,
                              void* d_out, int out_size)
{
    const float* x  = (const float*)d_in[0];
    const float* wq = (const float*)d_in[1];
    const float* bq = (const float*)d_in[2];
    const float* wk = (const float*)d_in[3];
    const float* bk = (const float*)d_in[4];
    const float* wv = (const float*)d_in[5];
    const float* bv = (const float*)d_in[6];
    const float* wo = (const float*)d_in[7];
    const float* bo = (const float*)d_in[8];
    float* out = (float*)d_out;

    __half *xh, *qh, *kh, *vh, *ah, *wt;
    cudaGetSymbolAddress((void**)&xh, g_xh);
    cudaGetSymbolAddress((void**)&qh, g_qh);
    cudaGetSymbolAddress((void**)&kh, g_kh);
    cudaGetSymbolAddress((void**)&vh, g_vh);
    cudaGetSymbolAddress((void**)&ah, g_ah);
    cudaGetSymbolAddress((void**)&wt, g_wt);

    cudaFuncSetAttribute(gemm_mma<true>,  cudaFuncAttributeMaxDynamicSharedMemorySize, SMG_TOTAL);
    cudaFuncSetAttribute(gemm_mma<false>, cudaFuncAttributeMaxDynamicSharedMemorySize, SMG_TOTAL);
    cudaFuncSetAttribute(attn_mma, cudaFuncAttributeMaxDynamicSharedMemorySize, SMA_TOTAL);

    const size_t WSZ = (size_t)DM * DM;

    // 1) operand prep
    convert_kernel<<<(MR * DM / 4 + 255) / 256, 256>>>(x, xh, MR * DM / 4);
    dim3 gT(DM / 32, DM / 32, 4);
    tsplit_kernel<<<gT, dim3(32, 8)>>>(wq, wk, wv, wo, wt);

    // 2) fused QKV projections (all single fp16; Q pre-scaled)
    dim3 gQKV(DM / 128, MR / 128, 3);
    gemm_mma<true><<<gQKV, 256, SMG_TOTAL>>>(
        xh, wt, bq, bk, bv,
        nullptr, qh, kh, vh);

    // 3) attention (fp16 tensor cores, base-2 softmax) -> single fp16
    dim3 gAttn(S / 128, H, B);   // (16, 16, 2)
    attn_mma<<<gAttn, 256, SMA_TOTAL>>>(qh, kh, vh, ah);

    // 4) output projection -> fp32 out
    dim3 gO(DM / 128, MR / 128, 1);
    gemm_mma<false><<<gO, 256, SMG_TOTAL>>>(
        ah, wt + 3 * WSZ, bo, bo, bo,
        out, nullptr, nullptr, nullptr);
}